// round 1
// baseline (speedup 1.0000x reference)
#include <cuda_runtime.h>
#include <math.h>

#define S_LEN   2048
#define D_MODEL 2048
#define HID     5632
#define NH      32
#define NKV     8
#define HD      64
#define KVD     (NKV*HD)   // 512
#define KT      32         // attention key tile

// ---------------- scratch (static device globals; no allocation) -------------
__device__ float g_h  [S_LEN * D_MODEL];
__device__ float g_q  [S_LEN * D_MODEL];
__device__ float g_k  [S_LEN * KVD];
__device__ float g_v  [S_LEN * KVD];
__device__ float g_ctx[S_LEN * D_MODEL];
__device__ float g_x1 [S_LEN * D_MODEL];
__device__ float g_g1 [S_LEN * HID];
__device__ float g_g3 [S_LEN * HID];

// ---------------- LayerNorm: one block per row -------------------------------
__global__ void ln_kernel(const float* __restrict__ x, const float* __restrict__ w,
                          const float* __restrict__ b, float* __restrict__ out) {
    int row = blockIdx.x;
    const float* xr = x + (size_t)row * D_MODEL;
    float s = 0.f, s2 = 0.f;
    for (int i = threadIdx.x; i < D_MODEL; i += blockDim.x) {
        float v = xr[i]; s += v; s2 += v * v;
    }
    __shared__ float r0[256], r1[256];
    r0[threadIdx.x] = s; r1[threadIdx.x] = s2;
    __syncthreads();
    for (int o = 128; o > 0; o >>= 1) {
        if (threadIdx.x < o) { r0[threadIdx.x] += r0[threadIdx.x + o];
                               r1[threadIdx.x] += r1[threadIdx.x + o]; }
        __syncthreads();
    }
    float mean = r0[0] * (1.0f / D_MODEL);
    float var  = r1[0] * (1.0f / D_MODEL) - mean * mean;
    float inv  = rsqrtf(var + 1e-5f);
    float* orow = out + (size_t)row * D_MODEL;
    for (int i = threadIdx.x; i < D_MODEL; i += blockDim.x)
        orow[i] = (xr[i] - mean) * inv * w[i] + b[i];
}

// ---------------- SGEMM: C[M,N] = A[M,K] @ B[K,N] (+ residual) ---------------
// BM=BN=64, BK=16, 256 threads, 4x4 per thread. M,N,K multiples of 64/64/16.
__global__ void gemm_kernel(const float* __restrict__ A, const float* __restrict__ B,
                            const float* __restrict__ R, float* __restrict__ C,
                            int M, int N, int K) {
    __shared__ __align__(16) float As[16][64];
    __shared__ __align__(16) float Bs[16][64];
    int tid = threadIdx.x;
    int tx = tid & 15, ty = tid >> 4;
    int m0 = blockIdx.y * 64, n0 = blockIdx.x * 64;

    int arow = tid >> 2;           // 0..63
    int akq  = (tid & 3) * 4;      // 0,4,8,12
    int bkr  = tid >> 4;           // 0..15
    int bnq  = (tid & 15) * 4;     // 0..60

    float acc[4][4];
#pragma unroll
    for (int i = 0; i < 4; i++)
#pragma unroll
        for (int j = 0; j < 4; j++) acc[i][j] = 0.f;

    for (int k0 = 0; k0 < K; k0 += 16) {
        float4 av = *(const float4*)&A[(size_t)(m0 + arow) * K + k0 + akq];
        As[akq + 0][arow] = av.x; As[akq + 1][arow] = av.y;
        As[akq + 2][arow] = av.z; As[akq + 3][arow] = av.w;
        float4 bv = *(const float4*)&B[(size_t)(k0 + bkr) * N + n0 + bnq];
        *(float4*)&Bs[bkr][bnq] = bv;
        __syncthreads();
#pragma unroll
        for (int kk = 0; kk < 16; kk++) {
            float4 a = *(const float4*)&As[kk][ty * 4];
            float4 b = *(const float4*)&Bs[kk][tx * 4];
            float ar[4] = {a.x, a.y, a.z, a.w};
            float br[4] = {b.x, b.y, b.z, b.w};
#pragma unroll
            for (int i = 0; i < 4; i++)
#pragma unroll
                for (int j = 0; j < 4; j++)
                    acc[i][j] = fmaf(ar[i], br[j], acc[i][j]);
        }
        __syncthreads();
    }
#pragma unroll
    for (int i = 0; i < 4; i++) {
        int r = m0 + ty * 4 + i;
#pragma unroll
        for (int j = 0; j < 4; j++) {
            int c = n0 + tx * 4 + j;
            float v = acc[i][j];
            if (R) v += R[(size_t)r * N + c];
            C[(size_t)r * N + c] = v;
        }
    }
}

// ---------------- RoPE (in place) on (S, H, 64) fp32 -------------------------
__global__ void rope_kernel(float* __restrict__ x, int H, int total) {
    int idx = blockIdx.x * blockDim.x + threadIdx.x;
    if (idx >= total) return;               // total = S*H*32 pairs
    int i   = idx & 31;
    int t   = idx >> 5;
    int h   = t % H;
    int s   = t / H;
    float freq = 1.0f / powf(10000.0f, (2.0f * (float)i) / 64.0f);
    float ang  = (float)s * freq;
    float sn, cs; sincosf(ang, &sn, &cs);
    float* p = x + ((size_t)s * H + h) * 64 + 2 * i;
    float xr = p[0], xi = p[1];
    p[0] = xr * cs - xi * sn;
    p[1] = xr * sn + xi * cs;
}

// ---------------- Flash attention (GQA), 64-q tile x 32-k tile ---------------
__global__ void attn_kernel(const float* __restrict__ q, const float* __restrict__ k,
                            const float* __restrict__ v, const int* __restrict__ mask,
                            float* __restrict__ ctx_out) {
    __shared__ __align__(16) float Qs[64][65];
    __shared__ __align__(16) float Ks[KT][65];
    __shared__ __align__(16) float Vs[KT][65];
    __shared__ float Ps[64][KT + 1];
    __shared__ int   Ms[KT];

    int h   = blockIdx.y;
    int q0  = blockIdx.x * 64;
    int kvh = h >> 2;                 // N_REP = 4
    int tid = threadIdx.x;
    int tx = tid & 15, ty = tid >> 4;

    for (int t = tid; t < 64 * 16; t += 256) {
        int r = t >> 4; int cq = (t & 15) * 4;
        float4 qv = *(const float4*)&q[(size_t)(q0 + r) * D_MODEL + h * 64 + cq];
        Qs[r][cq] = qv.x; Qs[r][cq + 1] = qv.y; Qs[r][cq + 2] = qv.z; Qs[r][cq + 3] = qv.w;
    }
    float m[4], l[4], ctx[4][4];
#pragma unroll
    for (int i = 0; i < 4; i++) {
        m[i] = -INFINITY; l[i] = 0.f;
#pragma unroll
        for (int j = 0; j < 4; j++) ctx[i][j] = 0.f;
    }
    __syncthreads();

    for (int k0 = 0; k0 < S_LEN; k0 += KT) {
        for (int t = tid; t < KT * 16; t += 256) {
            int r = t >> 4; int cq = (t & 15) * 4;
            float4 kv = *(const float4*)&k[(size_t)(k0 + r) * KVD + kvh * 64 + cq];
            Ks[r][cq] = kv.x; Ks[r][cq + 1] = kv.y; Ks[r][cq + 2] = kv.z; Ks[r][cq + 3] = kv.w;
            float4 vv = *(const float4*)&v[(size_t)(k0 + r) * KVD + kvh * 64 + cq];
            Vs[r][cq] = vv.x; Vs[r][cq + 1] = vv.y; Vs[r][cq + 2] = vv.z; Vs[r][cq + 3] = vv.w;
        }
        if (tid < KT) Ms[tid] = mask[k0 + tid];
        __syncthreads();

        // scores: thread owns rows 4ty..+3, key cols 2tx..+1
        float s[4][2];
#pragma unroll
        for (int i = 0; i < 4; i++) { s[i][0] = 0.f; s[i][1] = 0.f; }
#pragma unroll 8
        for (int d = 0; d < 64; d++) {
            float k0r = Ks[2 * tx + 0][d];
            float k1r = Ks[2 * tx + 1][d];
#pragma unroll
            for (int i = 0; i < 4; i++) {
                float qv = Qs[4 * ty + i][d];
                s[i][0] = fmaf(qv, k0r, s[i][0]);
                s[i][1] = fmaf(qv, k1r, s[i][1]);
            }
        }
        const float scale = 0.125f;   // 1/sqrt(64)
#pragma unroll
        for (int i = 0; i < 4; i++) {
            float mx = -INFINITY;
#pragma unroll
            for (int j = 0; j < 2; j++) {
                s[i][j] = Ms[2 * tx + j] ? s[i][j] * scale : -INFINITY;
                mx = fmaxf(mx, s[i][j]);
            }
            for (int o = 1; o < 16; o <<= 1)
                mx = fmaxf(mx, __shfl_xor_sync(0xffffffffu, mx, o));
            float mnew = fmaxf(m[i], mx);
            float rs = 0.f;
#pragma unroll
            for (int j = 0; j < 2; j++) {
                float pv = (s[i][j] == -INFINITY) ? 0.f : expf(s[i][j] - mnew);
                rs += pv;
                Ps[4 * ty + i][2 * tx + j] = pv;
            }
            for (int o = 1; o < 16; o <<= 1)
                rs += __shfl_xor_sync(0xffffffffu, rs, o);
            float alpha = (mnew == -INFINITY) ? 1.f : expf(m[i] - mnew);
            l[i] = l[i] * alpha + rs;
            m[i] = mnew;
#pragma unroll
            for (int j = 0; j < 4; j++) ctx[i][j] *= alpha;
        }
        __syncthreads();

        // ctx += P @ V  (thread owns rows 4ty..+3, d cols 4tx..+3)
#pragma unroll 8
        for (int j0 = 0; j0 < KT; j0++) {
            float vr0 = Vs[j0][4 * tx + 0];
            float vr1 = Vs[j0][4 * tx + 1];
            float vr2 = Vs[j0][4 * tx + 2];
            float vr3 = Vs[j0][4 * tx + 3];
#pragma unroll
            for (int i = 0; i < 4; i++) {
                float pv = Ps[4 * ty + i][j0];
                ctx[i][0] = fmaf(pv, vr0, ctx[i][0]);
                ctx[i][1] = fmaf(pv, vr1, ctx[i][1]);
                ctx[i][2] = fmaf(pv, vr2, ctx[i][2]);
                ctx[i][3] = fmaf(pv, vr3, ctx[i][3]);
            }
        }
        __syncthreads();
    }
#pragma unroll
    for (int i = 0; i < 4; i++) {
        int r = q0 + 4 * ty + i;
        float inv = (l[i] > 0.f) ? (1.f / l[i]) : 0.f;
#pragma unroll
        for (int j = 0; j < 4; j++)
            ctx_out[(size_t)r * D_MODEL + h * 64 + 4 * tx + j] = ctx[i][j] * inv;
    }
}

// ---------------- silu(g1) * g3 -> g1 ----------------------------------------
__global__ void silumul_kernel(float* __restrict__ g1, const float* __restrict__ g3, int n) {
    int idx = blockIdx.x * blockDim.x + threadIdx.x;
    if (idx >= n) return;
    float a = g1[idx];
    float sig = 1.0f / (1.0f + expf(-a));
    g1[idx] = a * sig * g3[idx];
}

// ---------------- launch -----------------------------------------------------
extern "C" void kernel_launch(void* const* d_in, const int* in_sizes, int n_in,
                              void* d_out, int out_size) {
    const float* x    = (const float*)d_in[0];
    const int*   mask = (const int*)  d_in[1];
    const float* wq   = (const float*)d_in[2];
    const float* wk   = (const float*)d_in[3];
    const float* wv   = (const float*)d_in[4];
    const float* wo   = (const float*)d_in[5];
    const float* w1   = (const float*)d_in[6];
    const float* w2   = (const float*)d_in[7];
    const float* w3   = (const float*)d_in[8];
    const float* ln1w = (const float*)d_in[9];
    const float* ln1b = (const float*)d_in[10];
    const float* ln2w = (const float*)d_in[11];
    const float* ln2b = (const float*)d_in[12];
    float* out = (float*)d_out;

    float *h, *q, *k, *v, *ctx, *x1, *g1, *g3;
    cudaGetSymbolAddress((void**)&h,   g_h);
    cudaGetSymbolAddress((void**)&q,   g_q);
    cudaGetSymbolAddress((void**)&k,   g_k);
    cudaGetSymbolAddress((void**)&v,   g_v);
    cudaGetSymbolAddress((void**)&ctx, g_ctx);
    cudaGetSymbolAddress((void**)&x1,  g_x1);
    cudaGetSymbolAddress((void**)&g1,  g_g1);
    cudaGetSymbolAddress((void**)&g3,  g_g3);

    // h = LN1(x)
    ln_kernel<<<S_LEN, 256>>>(x, ln1w, ln1b, h);
    // q/k/v projections
    gemm_kernel<<<dim3(D_MODEL / 64, S_LEN / 64), 256>>>(h, wq, nullptr, q, S_LEN, D_MODEL, D_MODEL);
    gemm_kernel<<<dim3(KVD / 64,     S_LEN / 64), 256>>>(h, wk, nullptr, k, S_LEN, KVD,     D_MODEL);
    gemm_kernel<<<dim3(KVD / 64,     S_LEN / 64), 256>>>(h, wv, nullptr, v, S_LEN, KVD,     D_MODEL);
    // RoPE
    {
        int tq = S_LEN * NH  * 32;
        int tk = S_LEN * NKV * 32;
        rope_kernel<<<(tq + 255) / 256, 256>>>(q, NH,  tq);
        rope_kernel<<<(tk + 255) / 256, 256>>>(k, NKV, tk);
    }
    // attention -> ctx (already in (s, h*d) layout)
    attn_kernel<<<dim3(S_LEN / 64, NH), 256>>>(q, k, v, mask, ctx);
    // x1 = x + ctx @ wo
    gemm_kernel<<<dim3(D_MODEL / 64, S_LEN / 64), 256>>>(ctx, wo, x, x1, S_LEN, D_MODEL, D_MODEL);
    // h = LN2(x1)
    ln_kernel<<<S_LEN, 256>>>(x1, ln2w, ln2b, h);
    // FFN
    gemm_kernel<<<dim3(HID / 64, S_LEN / 64), 256>>>(h, w1, nullptr, g1, S_LEN, HID, D_MODEL);
    gemm_kernel<<<dim3(HID / 64, S_LEN / 64), 256>>>(h, w3, nullptr, g3, S_LEN, HID, D_MODEL);
    {
        int n = S_LEN * HID;
        silumul_kernel<<<(n + 255) / 256, 256>>>(g1, g3, n);
    }
    // out = x1 + g1 @ w2
    gemm_kernel<<<dim3(D_MODEL / 64, S_LEN / 64), 256>>>(g1, w2, x1, out, S_LEN, D_MODEL, HID);
}

// round 5
// speedup vs baseline: 2.4965x; 2.4965x over previous
#include <cuda_runtime.h>
#include <cuda_bf16.h>
#include <cstdint>
#include <math.h>

#define S_LEN   2048
#define D_MODEL 2048
#define HID     5632
#define NH      32
#define NKV     8
#define HD      64
#define QKV_N   3072        // 2048 q | 512 k | 512 v
#define W13_N   11264       // 5632 g1 | 5632 g3
#define KT_ATT  32

// ---------------- fp32 scratch ------------------------------------------------
__device__ __align__(1024) float g_h  [S_LEN * D_MODEL];
__device__ __align__(1024) float g_qkv[S_LEN * QKV_N];
__device__ __align__(1024) float g_ctx[S_LEN * D_MODEL];
__device__ __align__(1024) float g_x1 [S_LEN * D_MODEL];
__device__ __align__(1024) float g_g13[S_LEN * W13_N];
__device__ __align__(1024) float g_gb [S_LEN * HID];

// ---------------- bf16 tiled (SW128 pre-swizzled) scratch ---------------------
// Tiles: [K/64][M/128] x (128 rows x 64 cols bf16), row r / colgroup g at
// byte offset r*128 + ((g ^ (r&7))<<4)  -> canonical ldmatrix swizzle.
__device__ __align__(1024) __nv_bfloat16 t_h_hi  [S_LEN * D_MODEL];
__device__ __align__(1024) __nv_bfloat16 t_h_lo  [S_LEN * D_MODEL];
__device__ __align__(1024) __nv_bfloat16 t_ctx_hi[S_LEN * D_MODEL];
__device__ __align__(1024) __nv_bfloat16 t_ctx_lo[S_LEN * D_MODEL];
__device__ __align__(1024) __nv_bfloat16 t_g_hi  [S_LEN * HID];
__device__ __align__(1024) __nv_bfloat16 t_g_lo  [S_LEN * HID];
__device__ __align__(1024) __nv_bfloat16 t_wqkv_hi[QKV_N * D_MODEL];
__device__ __align__(1024) __nv_bfloat16 t_wqkv_lo[QKV_N * D_MODEL];
__device__ __align__(1024) __nv_bfloat16 t_wo_hi [D_MODEL * D_MODEL];
__device__ __align__(1024) __nv_bfloat16 t_wo_lo [D_MODEL * D_MODEL];
__device__ __align__(1024) __nv_bfloat16 t_w13_hi[W13_N * D_MODEL];
__device__ __align__(1024) __nv_bfloat16 t_w13_lo[W13_N * D_MODEL];
__device__ __align__(1024) __nv_bfloat16 t_w2_hi [D_MODEL * HID];
__device__ __align__(1024) __nv_bfloat16 t_w2_lo [D_MODEL * HID];

// ---------------- PTX helpers (baseline PTX only; no sm_103a-accel) ----------
__device__ __forceinline__ uint32_t smem_u32(const void* p) {
    uint32_t a;
    asm("{ .reg .u64 t; cvta.to.shared.u64 t, %1; cvt.u32.u64 %0, t; }" : "=r"(a) : "l"(p));
    return a;
}
#define MBAR_INIT(a, c) asm volatile("mbarrier.init.shared.b64 [%0], %1;" :: "r"(a), "r"(c) : "memory")
#define MBAR_EXPECT(a, b) asm volatile("mbarrier.arrive.expect_tx.shared.b64 _, [%0], %1;" :: "r"(a), "r"(b) : "memory")
#define MBAR_INVAL(a) asm volatile("mbarrier.inval.shared.b64 [%0];" :: "r"(a) : "memory")
__device__ __forceinline__ void mbar_wait(uint32_t mbar, uint32_t parity) {
    asm volatile(
        "{\n\t.reg .pred P1;\n\t"
        "W_%=:\n\t"
        "mbarrier.try_wait.parity.acquire.cta.shared::cta.b64 P1, [%0], %1, 0x989680;\n\t"
        "@P1 bra.uni D_%=;\n\t"
        "bra.uni W_%=;\n\t"
        "D_%=:\n\t}"
        :: "r"(mbar), "r"(parity) : "memory");
}
__device__ __forceinline__ void bulk_g2s(uint32_t dst, const void* src, uint32_t bytes, uint32_t mbar) {
    asm volatile("cp.async.bulk.shared::cta.global.mbarrier::complete_tx::bytes [%0], [%1], %2, [%3];"
        :: "r"(dst), "l"(src), "r"(bytes), "r"(mbar) : "memory");
}
#define LDSM4(r, a) \
    asm volatile("ldmatrix.sync.aligned.m8n8.x4.shared.b16 {%0,%1,%2,%3}, [%4];" \
        : "=r"((r)[0]), "=r"((r)[1]), "=r"((r)[2]), "=r"((r)[3]) : "r"(a))
#define MMA_BF16(d, a, b) \
    asm volatile("mma.sync.aligned.m16n8k16.row.col.f32.bf16.bf16.f32 " \
        "{%0,%1,%2,%3}, {%4,%5,%6,%7}, {%8,%9}, {%0,%1,%2,%3};" \
        : "+f"((d)[0]), "+f"((d)[1]), "+f"((d)[2]), "+f"((d)[3]) \
        : "r"((a)[0]), "r"((a)[1]), "r"((a)[2]), "r"((a)[3]), "r"((b)[0]), "r"((b)[1]))

// ---------------- mma.sync GEMM: C[M,N] = A[M,K] @ B^T (+R) ------------------
// A,B given as hi/lo pre-swizzled 128x64 tiles. 3-pass compensation:
// C = Ah*Bh + Ah*Bl + Al*Bh  (fp32 accumulate in registers).
#define TILE_B 16384
__global__ void __launch_bounds__(256, 1) mma_gemm(
    const __nv_bfloat16* __restrict__ Ahi, const __nv_bfloat16* __restrict__ Alo,
    const __nv_bfloat16* __restrict__ Bhi, const __nv_bfloat16* __restrict__ Blo,
    const float* __restrict__ R, float* __restrict__ C, int M, int N, int K)
{
    extern __shared__ char smem[];
    uint32_t sb = smem_u32(smem);
    int tid = threadIdx.x, wid = tid >> 5, l = tid & 31;
    int wm = wid >> 2, wn = wid & 3;          // 2 x 4 warp grid
    int mt = blockIdx.y, nt = blockIdx.x;
    int MT = M >> 7, NT = N >> 7, KTt = K >> 6;
    uint32_t mb0 = sb + 2 * 4 * TILE_B;       // two mbarriers after tiles

    if (tid == 0) { MBAR_INIT(mb0, 1); MBAR_INIT(mb0 + 8, 1); }
    __syncthreads();

    auto issue = [&](int s, int kt) {
        uint32_t mb = mb0 + s * 8;
        uint32_t dst = sb + s * (4 * TILE_B);
        size_t aoff = ((size_t)kt * MT + mt) * (size_t)(128 * 64);
        size_t boff = ((size_t)kt * NT + nt) * (size_t)(128 * 64);
        MBAR_EXPECT(mb, 4 * TILE_B);
        bulk_g2s(dst,              Ahi + aoff, TILE_B, mb);
        bulk_g2s(dst + TILE_B,     Alo + aoff, TILE_B, mb);
        bulk_g2s(dst + 2 * TILE_B, Bhi + boff, TILE_B, mb);
        bulk_g2s(dst + 3 * TILE_B, Blo + boff, TILE_B, mb);
    };
    if (tid == 0) { issue(0, 0); if (KTt > 1) issue(1, 1); }

    float acc[4][4][4];
#pragma unroll
    for (int i = 0; i < 4; i++)
#pragma unroll
        for (int j = 0; j < 4; j++)
#pragma unroll
            for (int r = 0; r < 4; r++) acc[i][j][r] = 0.f;

    // per-thread ldmatrix address components
    int arow0 = wm * 64 + (l & 7) + ((l & 8) ? 8 : 0);   // + fm*16
    int acgs  = (l >> 4) & 1;                            // col-group select
    int brow0 = wn * 32 + (l & 7) + ((l & 16) ? 8 : 0);  // + pair*16
    int bcgs  = (l >> 3) & 1;

    for (int kt = 0; kt < KTt; kt++) {
        int s = kt & 1, ph = (kt >> 1) & 1;
        mbar_wait(mb0 + s * 8, ph);
        uint32_t st = sb + s * (4 * TILE_B);
        uint32_t Ah = st, Al = st + TILE_B, Bh = st + 2 * TILE_B, Bl = st + 3 * TILE_B;
#pragma unroll
        for (int ks = 0; ks < 4; ks++) {
            int acg = ks * 2 + acgs;
            int bcg = ks * 2 + bcgs;
            uint32_t ahr[16], alr[16], bhr[8], blr[8];
#pragma unroll
            for (int fm = 0; fm < 4; fm++) {
                int row = arow0 + fm * 16;
                uint32_t off = (uint32_t)(row * 128) + (uint32_t)((acg ^ (row & 7)) << 4);
                LDSM4(ahr + fm * 4, Ah + off);
                LDSM4(alr + fm * 4, Al + off);
            }
#pragma unroll
            for (int pr = 0; pr < 2; pr++) {
                int row = brow0 + pr * 16;
                uint32_t off = (uint32_t)(row * 128) + (uint32_t)((bcg ^ (row & 7)) << 4);
                LDSM4(bhr + pr * 4, Bh + off);
                LDSM4(blr + pr * 4, Bl + off);
            }
#pragma unroll
            for (int fm = 0; fm < 4; fm++)
#pragma unroll
                for (int fn = 0; fn < 4; fn++) {
                    MMA_BF16(acc[fm][fn], ahr + fm * 4, bhr + fn * 2);
                    MMA_BF16(acc[fm][fn], ahr + fm * 4, blr + fn * 2);
                    MMA_BF16(acc[fm][fn], alr + fm * 4, bhr + fn * 2);
                }
        }
        __syncthreads();
        if (tid == 0 && kt + 2 < KTt) issue(s, kt + 2);
    }

    // epilogue: direct register -> gmem (float2), optional residual
    int qr = l >> 2, qc = l & 3;
#pragma unroll
    for (int fm = 0; fm < 4; fm++) {
        int row0 = mt * 128 + wm * 64 + fm * 16 + qr;
#pragma unroll
        for (int fn = 0; fn < 4; fn++) {
            int col = nt * 128 + wn * 32 + fn * 8 + 2 * qc;
            size_t i0 = (size_t)row0 * N + col;
            size_t i1 = (size_t)(row0 + 8) * N + col;
            float2 v0 = make_float2(acc[fm][fn][0], acc[fm][fn][1]);
            float2 v1 = make_float2(acc[fm][fn][2], acc[fm][fn][3]);
            if (R) {
                float2 r0 = *(const float2*)&R[i0];
                float2 r1 = *(const float2*)&R[i1];
                v0.x += r0.x; v0.y += r0.y; v1.x += r1.x; v1.y += r1.y;
            }
            *(float2*)&C[i0] = v0;
            *(float2*)&C[i1] = v1;
        }
    }
}
#define GEMM_SMEM (2 * 4 * TILE_B + 64)

// ---------------- LayerNorm ---------------------------------------------------
__global__ void ln_kernel(const float* __restrict__ x, const float* __restrict__ w,
                          const float* __restrict__ b, float* __restrict__ out) {
    int row = blockIdx.x;
    const float* xr = x + (size_t)row * D_MODEL;
    float s = 0.f, s2 = 0.f;
    for (int i = threadIdx.x; i < D_MODEL; i += blockDim.x) {
        float v = xr[i]; s += v; s2 += v * v;
    }
    __shared__ float r0[256], r1[256];
    r0[threadIdx.x] = s; r1[threadIdx.x] = s2;
    __syncthreads();
    for (int o = 128; o > 0; o >>= 1) {
        if (threadIdx.x < o) { r0[threadIdx.x] += r0[threadIdx.x + o]; r1[threadIdx.x] += r1[threadIdx.x + o]; }
        __syncthreads();
    }
    float mean = r0[0] * (1.0f / D_MODEL);
    float var  = r1[0] * (1.0f / D_MODEL) - mean * mean;
    float inv  = rsqrtf(var + 1e-5f);
    float* orow = out + (size_t)row * D_MODEL;
    for (int i = threadIdx.x; i < D_MODEL; i += blockDim.x)
        orow[i] = (xr[i] - mean) * inv * w[i] + b[i];
}

// ---------------- fp32 row-major -> tiled swizzled bf16 hi/lo ----------------
__global__ void conv_act(const float* __restrict__ X, __nv_bfloat16* __restrict__ Hi,
                         __nv_bfloat16* __restrict__ Lo, int M, int K) {
    size_t idx = (size_t)blockIdx.x * blockDim.x + threadIdx.x;
    size_t total = (size_t)M * K / 8;
    if (idx >= total) return;
    int cpr = K >> 3;                         // 8-elem chunks per row
    int m  = (int)(idx / cpr), ck = (int)(idx % cpr);
    int kt = ck >> 3, c8 = ck & 7;
    int mt = m >> 7, r = m & 127;
    int MT = M >> 7;
    size_t tile = ((size_t)kt * MT + mt) * TILE_B;
    uint32_t off = (uint32_t)(r * 128) + (uint32_t)((c8 ^ (r & 7)) << 4);
    const float* src = X + (size_t)m * K + (size_t)kt * 64 + c8 * 8;
    float4 v0 = *(const float4*)src;
    float4 v1 = *(const float4*)(src + 4);
    float xin[8] = {v0.x, v0.y, v0.z, v0.w, v1.x, v1.y, v1.z, v1.w};
    __nv_bfloat16 h8[8], l8[8];
#pragma unroll
    for (int u = 0; u < 8; u++) {
        __nv_bfloat16 h = __float2bfloat16(xin[u]);
        h8[u] = h;
        l8[u] = __float2bfloat16(xin[u] - __bfloat162float(h));
    }
    *(uint4*)((char*)Hi + tile + off) = *(uint4*)h8;
    *(uint4*)((char*)Lo + tile + off) = *(uint4*)l8;
}

// ---------------- fp32 weight [K,N] -> tiled transposed swizzled bf16 --------
__global__ void conv_w(const float* __restrict__ W, __nv_bfloat16* __restrict__ Hi,
                       __nv_bfloat16* __restrict__ Lo, int K, int Nsrc,
                       int nt_off, int NT_total) {
    __shared__ float s[128][65];
    int kt = blockIdx.x, nt = blockIdx.y;
    int tid = threadIdx.x;
    for (int t = tid; t < 64 * 32; t += 256) {
        int i = t >> 5, j4 = (t & 31) * 4;
        float4 v = *(const float4*)&W[((size_t)kt * 64 + i) * Nsrc + (size_t)nt * 128 + j4];
        s[j4 + 0][i] = v.x; s[j4 + 1][i] = v.y; s[j4 + 2][i] = v.z; s[j4 + 3][i] = v.w;
    }
    __syncthreads();
    size_t tile = ((size_t)kt * NT_total + (nt_off + nt)) * TILE_B;
    for (int t = tid; t < 1024; t += 256) {
        int r = t >> 3, c8 = t & 7;
        __nv_bfloat16 h8[8], l8[8];
#pragma unroll
        for (int u = 0; u < 8; u++) {
            float x = s[r][c8 * 8 + u];
            __nv_bfloat16 h = __float2bfloat16(x);
            h8[u] = h;
            l8[u] = __float2bfloat16(x - __bfloat162float(h));
        }
        uint32_t off = (uint32_t)(r * 128) + (uint32_t)((c8 ^ (r & 7)) << 4);
        *(uint4*)((char*)Hi + tile + off) = *(uint4*)h8;
        *(uint4*)((char*)Lo + tile + off) = *(uint4*)l8;
    }
}

// ---------------- RoPE on qkv buffer -----------------------------------------
__global__ void rope_kernel(float* __restrict__ x, int H, int colbase, int total) {
    int idx = blockIdx.x * blockDim.x + threadIdx.x;
    if (idx >= total) return;               // total = S*H*32
    int i = idx & 31;
    int t = idx >> 5;
    int h = t % H;
    int s = t / H;
    float freq = 1.0f / powf(10000.0f, (2.0f * (float)i) / 64.0f);
    float ang = (float)s * freq;
    float sn, cs; sincosf(ang, &sn, &cs);
    float* p = x + (size_t)s * QKV_N + colbase + h * 64 + 2 * i;
    float xr = p[0], xi = p[1];
    p[0] = xr * cs - xi * sn;
    p[1] = xr * sn + xi * cs;
}

// ---------------- Flash attention (fp32, GQA) --------------------------------
__global__ void attn_kernel(const float* __restrict__ qkv, const int* __restrict__ mask,
                            float* __restrict__ ctx_out) {
    __shared__ __align__(16) float Qs[64][65];
    __shared__ __align__(16) float Ks[KT_ATT][65];
    __shared__ __align__(16) float Vs[KT_ATT][65];
    __shared__ float Ps[64][KT_ATT + 1];
    __shared__ int   Ms[KT_ATT];

    int h = blockIdx.y;
    int q0 = blockIdx.x * 64;
    int kvh = h >> 2;
    int tid = threadIdx.x;
    int tx = tid & 15, ty = tid >> 4;

    for (int t = tid; t < 64 * 16; t += 256) {
        int r = t >> 4; int cq = (t & 15) * 4;
        float4 qv = *(const float4*)&qkv[(size_t)(q0 + r) * QKV_N + h * 64 + cq];
        Qs[r][cq] = qv.x; Qs[r][cq + 1] = qv.y; Qs[r][cq + 2] = qv.z; Qs[r][cq + 3] = qv.w;
    }
    float m[4], l[4], ctx[4][4];
#pragma unroll
    for (int i = 0; i < 4; i++) {
        m[i] = -INFINITY; l[i] = 0.f;
#pragma unroll
        for (int j = 0; j < 4; j++) ctx[i][j] = 0.f;
    }
    __syncthreads();

    for (int k0 = 0; k0 < S_LEN; k0 += KT_ATT) {
        for (int t = tid; t < KT_ATT * 16; t += 256) {
            int r = t >> 4; int cq = (t & 15) * 4;
            float4 kv = *(const float4*)&qkv[(size_t)(k0 + r) * QKV_N + 2048 + kvh * 64 + cq];
            Ks[r][cq] = kv.x; Ks[r][cq + 1] = kv.y; Ks[r][cq + 2] = kv.z; Ks[r][cq + 3] = kv.w;
            float4 vv = *(const float4*)&qkv[(size_t)(k0 + r) * QKV_N + 2560 + kvh * 64 + cq];
            Vs[r][cq] = vv.x; Vs[r][cq + 1] = vv.y; Vs[r][cq + 2] = vv.z; Vs[r][cq + 3] = vv.w;
        }
        if (tid < KT_ATT) Ms[tid] = mask[k0 + tid];
        __syncthreads();

        float s[4][2];
#pragma unroll
        for (int i = 0; i < 4; i++) { s[i][0] = 0.f; s[i][1] = 0.f; }
#pragma unroll 8
        for (int d = 0; d < 64; d++) {
            float k0r = Ks[2 * tx + 0][d];
            float k1r = Ks[2 * tx + 1][d];
#pragma unroll
            for (int i = 0; i < 4; i++) {
                float qv = Qs[4 * ty + i][d];
                s[i][0] = fmaf(qv, k0r, s[i][0]);
                s[i][1] = fmaf(qv, k1r, s[i][1]);
            }
        }
        const float scale = 0.125f;
#pragma unroll
        for (int i = 0; i < 4; i++) {
            float mx = -INFINITY;
#pragma unroll
            for (int j = 0; j < 2; j++) {
                s[i][j] = Ms[2 * tx + j] ? s[i][j] * scale : -INFINITY;
                mx = fmaxf(mx, s[i][j]);
            }
            for (int o = 1; o < 16; o <<= 1)
                mx = fmaxf(mx, __shfl_xor_sync(0xffffffffu, mx, o));
            float mnew = fmaxf(m[i], mx);
            float rs = 0.f;
#pragma unroll
            for (int j = 0; j < 2; j++) {
                float pv = (s[i][j] == -INFINITY) ? 0.f : expf(s[i][j] - mnew);
                rs += pv;
                Ps[4 * ty + i][2 * tx + j] = pv;
            }
            for (int o = 1; o < 16; o <<= 1)
                rs += __shfl_xor_sync(0xffffffffu, rs, o);
            float alpha = (mnew == -INFINITY) ? 1.f : expf(m[i] - mnew);
            l[i] = l[i] * alpha + rs;
            m[i] = mnew;
#pragma unroll
            for (int j = 0; j < 4; j++) ctx[i][j] *= alpha;
        }
        __syncthreads();

#pragma unroll 8
        for (int j0 = 0; j0 < KT_ATT; j0++) {
            float vr0 = Vs[j0][4 * tx + 0];
            float vr1 = Vs[j0][4 * tx + 1];
            float vr2 = Vs[j0][4 * tx + 2];
            float vr3 = Vs[j0][4 * tx + 3];
#pragma unroll
            for (int i = 0; i < 4; i++) {
                float pv = Ps[4 * ty + i][j0];
                ctx[i][0] = fmaf(pv, vr0, ctx[i][0]);
                ctx[i][1] = fmaf(pv, vr1, ctx[i][1]);
                ctx[i][2] = fmaf(pv, vr2, ctx[i][2]);
                ctx[i][3] = fmaf(pv, vr3, ctx[i][3]);
            }
        }
        __syncthreads();
    }
#pragma unroll
    for (int i = 0; i < 4; i++) {
        int r = q0 + 4 * ty + i;
        float inv = (l[i] > 0.f) ? (1.f / l[i]) : 0.f;
#pragma unroll
        for (int j = 0; j < 4; j++)
            ctx_out[(size_t)r * D_MODEL + h * 64 + 4 * tx + j] = ctx[i][j] * inv;
    }
}

// ---------------- silu(g1)*g3 from fused g13 ---------------------------------
__global__ void silumul_kernel(const float* __restrict__ g13, float* __restrict__ gb, int n) {
    int idx = blockIdx.x * blockDim.x + threadIdx.x;
    if (idx >= n) return;
    int s = idx / HID, j = idx % HID;
    float a = g13[(size_t)s * W13_N + j];
    float c = g13[(size_t)s * W13_N + HID + j];
    float sig = 1.0f / (1.0f + expf(-a));
    gb[idx] = a * sig * c;
}

// ---------------- launch -----------------------------------------------------
extern "C" void kernel_launch(void* const* d_in, const int* in_sizes, int n_in,
                              void* d_out, int out_size) {
    const float* x    = (const float*)d_in[0];
    const int*   mask = (const int*)  d_in[1];
    const float* wq   = (const float*)d_in[2];
    const float* wk   = (const float*)d_in[3];
    const float* wv   = (const float*)d_in[4];
    const float* wo   = (const float*)d_in[5];
    const float* w1   = (const float*)d_in[6];
    const float* w2   = (const float*)d_in[7];
    const float* w3   = (const float*)d_in[8];
    const float* ln1w = (const float*)d_in[9];
    const float* ln1b = (const float*)d_in[10];
    const float* ln2w = (const float*)d_in[11];
    const float* ln2b = (const float*)d_in[12];
    float* out = (float*)d_out;

    float *h, *qkv, *ctx, *x1, *g13, *gb;
    cudaGetSymbolAddress((void**)&h,   g_h);
    cudaGetSymbolAddress((void**)&qkv, g_qkv);
    cudaGetSymbolAddress((void**)&ctx, g_ctx);
    cudaGetSymbolAddress((void**)&x1,  g_x1);
    cudaGetSymbolAddress((void**)&g13, g_g13);
    cudaGetSymbolAddress((void**)&gb,  g_gb);

    __nv_bfloat16 *hhi, *hlo, *chi, *clo, *ghi, *glo;
    __nv_bfloat16 *wqkvh, *wqkvl, *woh, *wol, *w13h, *w13l, *w2h, *w2l;
    cudaGetSymbolAddress((void**)&hhi, t_h_hi);   cudaGetSymbolAddress((void**)&hlo, t_h_lo);
    cudaGetSymbolAddress((void**)&chi, t_ctx_hi); cudaGetSymbolAddress((void**)&clo, t_ctx_lo);
    cudaGetSymbolAddress((void**)&ghi, t_g_hi);   cudaGetSymbolAddress((void**)&glo, t_g_lo);
    cudaGetSymbolAddress((void**)&wqkvh, t_wqkv_hi); cudaGetSymbolAddress((void**)&wqkvl, t_wqkv_lo);
    cudaGetSymbolAddress((void**)&woh, t_wo_hi);  cudaGetSymbolAddress((void**)&wol, t_wo_lo);
    cudaGetSymbolAddress((void**)&w13h, t_w13_hi); cudaGetSymbolAddress((void**)&w13l, t_w13_lo);
    cudaGetSymbolAddress((void**)&w2h, t_w2_hi);  cudaGetSymbolAddress((void**)&w2l, t_w2_lo);

    cudaFuncSetAttribute(mma_gemm, cudaFuncAttributeMaxDynamicSharedMemorySize, GEMM_SMEM);

    // weights -> tiled bf16 hi/lo (transposed to [N,K] K-major)
    conv_w<<<dim3(D_MODEL / 64, 16), 256>>>(wq, wqkvh, wqkvl, D_MODEL, D_MODEL, 0,  24);
    conv_w<<<dim3(D_MODEL / 64, 4),  256>>>(wk, wqkvh, wqkvl, D_MODEL, 512,     16, 24);
    conv_w<<<dim3(D_MODEL / 64, 4),  256>>>(wv, wqkvh, wqkvl, D_MODEL, 512,     20, 24);
    conv_w<<<dim3(D_MODEL / 64, 16), 256>>>(wo, woh,   wol,   D_MODEL, D_MODEL, 0,  16);
    conv_w<<<dim3(D_MODEL / 64, 44), 256>>>(w1, w13h,  w13l,  D_MODEL, HID,     0,  88);
    conv_w<<<dim3(D_MODEL / 64, 44), 256>>>(w3, w13h,  w13l,  D_MODEL, HID,     44, 88);
    conv_w<<<dim3(HID / 64,     16), 256>>>(w2, w2h,   w2l,   HID,     D_MODEL, 0,  16);

    // h = LN1(x); tiled
    ln_kernel<<<S_LEN, 256>>>(x, ln1w, ln1b, h);
    conv_act<<<(S_LEN * D_MODEL / 8 + 255) / 256, 256>>>(h, hhi, hlo, S_LEN, D_MODEL);

    // qkv = h @ [wq|wk|wv]
    mma_gemm<<<dim3(QKV_N / 128, S_LEN / 128), 256, GEMM_SMEM>>>(hhi, hlo, wqkvh, wqkvl,
        nullptr, qkv, S_LEN, QKV_N, D_MODEL);

    rope_kernel<<<(S_LEN * NH  * 32 + 255) / 256, 256>>>(qkv, NH,  0,    S_LEN * NH  * 32);
    rope_kernel<<<(S_LEN * NKV * 32 + 255) / 256, 256>>>(qkv, NKV, 2048, S_LEN * NKV * 32);

    attn_kernel<<<dim3(S_LEN / 64, NH), 256>>>(qkv, mask, ctx);
    conv_act<<<(S_LEN * D_MODEL / 8 + 255) / 256, 256>>>(ctx, chi, clo, S_LEN, D_MODEL);

    // x1 = x + ctx @ wo
    mma_gemm<<<dim3(D_MODEL / 128, S_LEN / 128), 256, GEMM_SMEM>>>(chi, clo, woh, wol,
        x, x1, S_LEN, D_MODEL, D_MODEL);

    // h = LN2(x1); tiled
    ln_kernel<<<S_LEN, 256>>>(x1, ln2w, ln2b, h);
    conv_act<<<(S_LEN * D_MODEL / 8 + 255) / 256, 256>>>(h, hhi, hlo, S_LEN, D_MODEL);

    // g13 = h @ [w1|w3]
    mma_gemm<<<dim3(W13_N / 128, S_LEN / 128), 256, GEMM_SMEM>>>(hhi, hlo, w13h, w13l,
        nullptr, g13, S_LEN, W13_N, D_MODEL);

    silumul_kernel<<<(S_LEN * HID + 255) / 256, 256>>>(g13, gb, S_LEN * HID);
    conv_act<<<(S_LEN * HID / 8 + 255) / 256, 256>>>(gb, ghi, glo, S_LEN, HID);

    // out = x1 + gb @ w2
    mma_gemm<<<dim3(D_MODEL / 128, S_LEN / 128), 256, GEMM_SMEM>>>(ghi, glo, w2h, w2l,
        x1, out, S_LEN, D_MODEL, HID);
}

// round 8
// speedup vs baseline: 3.8755x; 1.5524x over previous
#include <cuda_runtime.h>
#include <cuda_bf16.h>
#include <cstdint>
#include <math.h>

#define S_LEN   2048
#define D_MODEL 2048
#define HID     5632
#define NH      32
#define NKV     8
#define HD      64
#define QKV_N   3072        // 2048 q | 512 k | 512 v
#define W13_N   11264       // 5632 g1 | 5632 g3

// ---------------- fp32 scratch ------------------------------------------------
__device__ __align__(1024) float g_h  [S_LEN * D_MODEL];
__device__ __align__(1024) float g_qkv[S_LEN * QKV_N];
__device__ __align__(1024) float g_ctx[S_LEN * D_MODEL];
__device__ __align__(1024) float g_x1 [S_LEN * D_MODEL];
__device__ __align__(1024) float g_g13[S_LEN * W13_N];
__device__ __align__(1024) float g_gb [S_LEN * HID];

// ---------------- bf16 tiled (pre-swizzled) scratch ---------------------------
__device__ __align__(1024) __nv_bfloat16 t_h_hi  [S_LEN * D_MODEL];
__device__ __align__(1024) __nv_bfloat16 t_h_lo  [S_LEN * D_MODEL];
__device__ __align__(1024) __nv_bfloat16 t_ctx_hi[S_LEN * D_MODEL];
__device__ __align__(1024) __nv_bfloat16 t_ctx_lo[S_LEN * D_MODEL];
__device__ __align__(1024) __nv_bfloat16 t_g_hi  [S_LEN * HID];
__device__ __align__(1024) __nv_bfloat16 t_g_lo  [S_LEN * HID];
__device__ __align__(1024) __nv_bfloat16 t_wqkv_hi[QKV_N * D_MODEL];
__device__ __align__(1024) __nv_bfloat16 t_wqkv_lo[QKV_N * D_MODEL];
__device__ __align__(1024) __nv_bfloat16 t_wo_hi [D_MODEL * D_MODEL];
__device__ __align__(1024) __nv_bfloat16 t_wo_lo [D_MODEL * D_MODEL];
__device__ __align__(1024) __nv_bfloat16 t_w13_hi[W13_N * D_MODEL];
__device__ __align__(1024) __nv_bfloat16 t_w13_lo[W13_N * D_MODEL];
__device__ __align__(1024) __nv_bfloat16 t_w2_hi [D_MODEL * HID];
__device__ __align__(1024) __nv_bfloat16 t_w2_lo [D_MODEL * HID];
// attention tiles: Q per head [NH][16][128x64]; K per kv-head [NKV][16][128x64];
// V transposed per kv-head [NKV][16][2 sub][64 d-rows x 64 key-cols]
__device__ __align__(1024) __nv_bfloat16 t_qat_hi[NH  * 16 * 8192];
__device__ __align__(1024) __nv_bfloat16 t_qat_lo[NH  * 16 * 8192];
__device__ __align__(1024) __nv_bfloat16 t_kat_hi[NKV * 16 * 8192];
__device__ __align__(1024) __nv_bfloat16 t_kat_lo[NKV * 16 * 8192];
__device__ __align__(1024) __nv_bfloat16 t_vat_hi[NKV * 16 * 8192];
__device__ __align__(1024) __nv_bfloat16 t_vat_lo[NKV * 16 * 8192];

// ---------------- PTX helpers (baseline PTX only) -----------------------------
__device__ __forceinline__ uint32_t smem_u32(const void* p) {
    uint32_t a;
    asm("{ .reg .u64 t; cvta.to.shared.u64 t, %1; cvt.u32.u64 %0, t; }" : "=r"(a) : "l"(p));
    return a;
}
#define MBAR_INIT(a, c) asm volatile("mbarrier.init.shared.b64 [%0], %1;" :: "r"(a), "r"(c) : "memory")
#define MBAR_EXPECT(a, b) asm volatile("mbarrier.arrive.expect_tx.shared.b64 _, [%0], %1;" :: "r"(a), "r"(b) : "memory")
__device__ __forceinline__ void mbar_wait(uint32_t mbar, uint32_t parity) {
    asm volatile(
        "{\n\t.reg .pred P1;\n\t"
        "W_%=:\n\t"
        "mbarrier.try_wait.parity.acquire.cta.shared::cta.b64 P1, [%0], %1, 0x989680;\n\t"
        "@P1 bra.uni D_%=;\n\t"
        "bra.uni W_%=;\n\t"
        "D_%=:\n\t}"
        :: "r"(mbar), "r"(parity) : "memory");
}
__device__ __forceinline__ void bulk_g2s(uint32_t dst, const void* src, uint32_t bytes, uint32_t mbar) {
    asm volatile("cp.async.bulk.shared::cta.global.mbarrier::complete_tx::bytes [%0], [%1], %2, [%3];"
        :: "r"(dst), "l"(src), "r"(bytes), "r"(mbar) : "memory");
}
#define LDSM4(r, a) \
    asm volatile("ldmatrix.sync.aligned.m8n8.x4.shared.b16 {%0,%1,%2,%3}, [%4];" \
        : "=r"((r)[0]), "=r"((r)[1]), "=r"((r)[2]), "=r"((r)[3]) : "r"(a))
#define MMA_BF16(d, a, b) \
    asm volatile("mma.sync.aligned.m16n8k16.row.col.f32.bf16.bf16.f32 " \
        "{%0,%1,%2,%3}, {%4,%5,%6,%7}, {%8,%9}, {%0,%1,%2,%3};" \
        : "+f"((d)[0]), "+f"((d)[1]), "+f"((d)[2]), "+f"((d)[3]) \
        : "r"((a)[0]), "r"((a)[1]), "r"((a)[2]), "r"((a)[3]), "r"((b)[0]), "r"((b)[1]))

__device__ __forceinline__ uint32_t pack_bf2(float a, float b) {
    __nv_bfloat162 t = __floats2bfloat162_rn(a, b);
    return *(uint32_t*)&t;
}

// ---------------- mma.sync GEMM: C[M,N] = A[M,K] @ B^T (+R) ------------------
#define TILE_B 16384
__global__ void __launch_bounds__(256, 1) mma_gemm(
    const __nv_bfloat16* __restrict__ Ahi, const __nv_bfloat16* __restrict__ Alo,
    const __nv_bfloat16* __restrict__ Bhi, const __nv_bfloat16* __restrict__ Blo,
    const float* __restrict__ R, float* __restrict__ C, int M, int N, int K)
{
    extern __shared__ char smem[];
    uint32_t sb = smem_u32(smem);
    int tid = threadIdx.x, wid = tid >> 5, ln = tid & 31;
    int wm = wid >> 2, wn = wid & 3;
    int mt = blockIdx.y, nt = blockIdx.x;
    int MT = M >> 7, NT = N >> 7, KTt = K >> 6;
    uint32_t mb0 = sb + 2 * 4 * TILE_B;

    if (tid == 0) { MBAR_INIT(mb0, 1); MBAR_INIT(mb0 + 8, 1); }
    __syncthreads();

    auto issue = [&](int s, int kt) {
        uint32_t mb = mb0 + s * 8;
        uint32_t dst = sb + s * (4 * TILE_B);
        size_t aoff = ((size_t)kt * MT + mt) * (size_t)(128 * 64);
        size_t boff = ((size_t)kt * NT + nt) * (size_t)(128 * 64);
        MBAR_EXPECT(mb, 4 * TILE_B);
        bulk_g2s(dst,              Ahi + aoff, TILE_B, mb);
        bulk_g2s(dst + TILE_B,     Alo + aoff, TILE_B, mb);
        bulk_g2s(dst + 2 * TILE_B, Bhi + boff, TILE_B, mb);
        bulk_g2s(dst + 3 * TILE_B, Blo + boff, TILE_B, mb);
    };
    if (tid == 0) { issue(0, 0); if (KTt > 1) issue(1, 1); }

    float acc[4][4][4];
#pragma unroll
    for (int i = 0; i < 4; i++)
#pragma unroll
        for (int j = 0; j < 4; j++)
#pragma unroll
            for (int r = 0; r < 4; r++) acc[i][j][r] = 0.f;

    int arow0 = wm * 64 + (ln & 7) + ((ln & 8) ? 8 : 0);
    int acgs  = (ln >> 4) & 1;
    int brow0 = wn * 32 + (ln & 7) + ((ln & 16) ? 8 : 0);
    int bcgs  = (ln >> 3) & 1;

    for (int kt = 0; kt < KTt; kt++) {
        int s = kt & 1, ph = (kt >> 1) & 1;
        mbar_wait(mb0 + s * 8, ph);
        uint32_t st = sb + s * (4 * TILE_B);
        uint32_t Ah = st, Al = st + TILE_B, Bh = st + 2 * TILE_B, Bl = st + 3 * TILE_B;
#pragma unroll
        for (int ks = 0; ks < 4; ks++) {
            int acg = ks * 2 + acgs;
            int bcg = ks * 2 + bcgs;
            uint32_t ahr[16], alr[16], bhr[8], blr[8];
#pragma unroll
            for (int fm = 0; fm < 4; fm++) {
                int row = arow0 + fm * 16;
                uint32_t off = (uint32_t)(row * 128) + (uint32_t)((acg ^ (row & 7)) << 4);
                LDSM4(ahr + fm * 4, Ah + off);
                LDSM4(alr + fm * 4, Al + off);
            }
#pragma unroll
            for (int pr = 0; pr < 2; pr++) {
                int row = brow0 + pr * 16;
                uint32_t off = (uint32_t)(row * 128) + (uint32_t)((bcg ^ (row & 7)) << 4);
                LDSM4(bhr + pr * 4, Bh + off);
                LDSM4(blr + pr * 4, Bl + off);
            }
#pragma unroll
            for (int fm = 0; fm < 4; fm++)
#pragma unroll
                for (int fn = 0; fn < 4; fn++) {
                    MMA_BF16(acc[fm][fn], ahr + fm * 4, bhr + fn * 2);
                    MMA_BF16(acc[fm][fn], ahr + fm * 4, blr + fn * 2);
                    MMA_BF16(acc[fm][fn], alr + fm * 4, bhr + fn * 2);
                }
        }
        __syncthreads();
        if (tid == 0 && kt + 2 < KTt) issue(s, kt + 2);
    }

    int qr = ln >> 2, qc = ln & 3;
#pragma unroll
    for (int fm = 0; fm < 4; fm++) {
        int row0 = mt * 128 + wm * 64 + fm * 16 + qr;
#pragma unroll
        for (int fn = 0; fn < 4; fn++) {
            int col = nt * 128 + wn * 32 + fn * 8 + 2 * qc;
            size_t i0 = (size_t)row0 * N + col;
            size_t i1 = (size_t)(row0 + 8) * N + col;
            float2 v0 = make_float2(acc[fm][fn][0], acc[fm][fn][1]);
            float2 v1 = make_float2(acc[fm][fn][2], acc[fm][fn][3]);
            if (R) {
                float2 r0 = *(const float2*)&R[i0];
                float2 r1 = *(const float2*)&R[i1];
                v0.x += r0.x; v0.y += r0.y; v1.x += r1.x; v1.y += r1.y;
            }
            *(float2*)&C[i0] = v0;
            *(float2*)&C[i1] = v1;
        }
    }
}
#define GEMM_SMEM (2 * 4 * TILE_B + 64)

// ---------------- tensorized flash attention ---------------------------------
// CTA = (q-block 128, head). Q frags resident; K/V 2-stage bulk pipeline.
#define ATT_SQ    0u
#define ATT_SMSK  32768u
#define ATT_SST   40960u
#define ATT_MB    (40960u + 131072u)
#define ATT_SMEM  (40960 + 131072 + 64)
__global__ void __launch_bounds__(256, 1) attn_mma(
    const __nv_bfloat16* __restrict__ Qhi, const __nv_bfloat16* __restrict__ Qlo,
    const __nv_bfloat16* __restrict__ Khi, const __nv_bfloat16* __restrict__ Klo,
    const __nv_bfloat16* __restrict__ Vhi, const __nv_bfloat16* __restrict__ Vlo,
    const int* __restrict__ mask, float* __restrict__ ctx_out)
{
    extern __shared__ char smem[];
    uint32_t sb = smem_u32(smem);
    int tid = threadIdx.x, wid = tid >> 5, ln = tid & 31;
    int qb = blockIdx.x, h = blockIdx.y;
    int kvh = h >> 2;
    int q2 = (ln & 3) * 2;

    // mask -> smem
    int* msk = (int*)(smem + ATT_SMSK);
    for (int i = tid; i < S_LEN; i += 256) msk[i] = mask[i];
    // Q tiles -> smem (already swizzled; linear copy)
    {
        const uint4* qs0 = (const uint4*)(Qhi + ((size_t)h * 16 + qb) * 8192);
        const uint4* qs1 = (const uint4*)(Qlo + ((size_t)h * 16 + qb) * 8192);
        uint4* qd0 = (uint4*)(smem + ATT_SQ);
        uint4* qd1 = (uint4*)(smem + ATT_SQ + 16384);
        for (int i = tid; i < 1024; i += 256) { qd0[i] = qs0[i]; qd1[i] = qs1[i]; }
    }
    uint32_t mb0 = sb + ATT_MB;
    if (tid == 0) { MBAR_INIT(mb0, 1); MBAR_INIT(mb0 + 8, 1); }
    __syncthreads();

    auto issue = [&](int s, int kb) {
        uint32_t mb = mb0 + s * 8;
        uint32_t dst = sb + ATT_SST + s * 65536;
        size_t ko = ((size_t)kvh * 16 + kb) * 8192;
        MBAR_EXPECT(mb, 65536);
        bulk_g2s(dst,         Khi + ko, 16384, mb);
        bulk_g2s(dst + 16384, Klo + ko, 16384, mb);
        bulk_g2s(dst + 32768, Vhi + ko, 16384, mb);
        bulk_g2s(dst + 49152, Vlo + ko, 16384, mb);
    };
    if (tid == 0) { issue(0, 0); issue(1, 1); }

    // Q fragments (warp rows 16*wid .. +15)
    uint32_t qh[4][4], qlr[4][4];
    {
        int arow0 = wid * 16 + (ln & 7) + ((ln & 8) ? 8 : 0);
        int acgs = (ln >> 4) & 1;
#pragma unroll
        for (int ks = 0; ks < 4; ks++) {
            int cg = ks * 2 + acgs;
            uint32_t off = (uint32_t)(arow0 * 128) + (uint32_t)((cg ^ (arow0 & 7)) << 4);
            LDSM4(qh[ks],  sb + ATT_SQ + off);
            LDSM4(qlr[ks], sb + ATT_SQ + 16384 + off);
        }
    }

    float mrow0 = -INFINITY, mrow1 = -INFINITY, lrow0 = 0.f, lrow1 = 0.f;
    float cacc[8][4];
#pragma unroll
    for (int j = 0; j < 8; j++)
#pragma unroll
        for (int r = 0; r < 4; r++) cacc[j][r] = 0.f;

    int brow_b = (ln & 7) + ((ln & 16) ? 8 : 0);
    int bcgs = (ln >> 3) & 1;

    for (int kb = 0; kb < 16; kb++) {
        int s = kb & 1, ph = (kb >> 1) & 1;
        mbar_wait(mb0 + s * 8, ph);
        uint32_t st = sb + ATT_SST + s * 65536;
        uint32_t Kh = st, Kl = st + 16384, Vh = st + 32768, Vl = st + 49152;

        // ---- S = Q @ K^T (3-pass) -> sacc[16][4] (128 keys) ----
        float sacc[16][4];
#pragma unroll
        for (int j = 0; j < 16; j++)
#pragma unroll
            for (int r = 0; r < 4; r++) sacc[j][r] = 0.f;
#pragma unroll
        for (int nj = 0; nj < 4; nj++) {
#pragma unroll
            for (int ks = 0; ks < 4; ks++) {
                uint32_t bh[8], bl[8];
                int cg = ks * 2 + bcgs;
#pragma unroll
                for (int pr = 0; pr < 2; pr++) {
                    int row = nj * 32 + pr * 16 + brow_b;
                    uint32_t off = (uint32_t)(row * 128) + (uint32_t)((cg ^ (row & 7)) << 4);
                    LDSM4(bh + pr * 4, Kh + off);
                    LDSM4(bl + pr * 4, Kl + off);
                }
#pragma unroll
                for (int nt = 0; nt < 4; nt++) {
                    float* d = sacc[nj * 4 + nt];
                    uint32_t* rh = bh + (nt >> 1) * 4 + (nt & 1) * 2;
                    uint32_t* rl = bl + (nt >> 1) * 4 + (nt & 1) * 2;
                    MMA_BF16(d, qh[ks], rh);
                    MMA_BF16(d, qh[ks], rl);
                    MMA_BF16(d, qlr[ks], rh);
                }
            }
        }
        // ---- online softmax ----
        float tmax0 = -INFINITY, tmax1 = -INFINITY;
#pragma unroll
        for (int j = 0; j < 16; j++) {
            int c = kb * 128 + 8 * j + q2;
            float m0v = msk[c] ? 0.125f : 0.f;
            float m1v = msk[c + 1] ? 0.125f : 0.f;
            sacc[j][0] = msk[c]     ? sacc[j][0] * 0.125f : -1e30f;
            sacc[j][1] = msk[c + 1] ? sacc[j][1] * 0.125f : -1e30f;
            sacc[j][2] = msk[c]     ? sacc[j][2] * 0.125f : -1e30f;
            sacc[j][3] = msk[c + 1] ? sacc[j][3] * 0.125f : -1e30f;
            (void)m0v; (void)m1v;
            tmax0 = fmaxf(tmax0, fmaxf(sacc[j][0], sacc[j][1]));
            tmax1 = fmaxf(tmax1, fmaxf(sacc[j][2], sacc[j][3]));
        }
        tmax0 = fmaxf(tmax0, __shfl_xor_sync(0xffffffffu, tmax0, 1));
        tmax0 = fmaxf(tmax0, __shfl_xor_sync(0xffffffffu, tmax0, 2));
        tmax1 = fmaxf(tmax1, __shfl_xor_sync(0xffffffffu, tmax1, 1));
        tmax1 = fmaxf(tmax1, __shfl_xor_sync(0xffffffffu, tmax1, 2));
        float mnew0 = fmaxf(mrow0, tmax0);
        float mnew1 = fmaxf(mrow1, tmax1);
        float alpha0 = (mrow0 == -INFINITY) ? 0.f : __expf(mrow0 - mnew0);
        float alpha1 = (mrow1 == -INFINITY) ? 0.f : __expf(mrow1 - mnew1);
        float rs0 = 0.f, rs1 = 0.f;
#pragma unroll
        for (int j = 0; j < 16; j++) {
            float p0 = __expf(sacc[j][0] - mnew0);
            float p1 = __expf(sacc[j][1] - mnew0);
            float p2 = __expf(sacc[j][2] - mnew1);
            float p3 = __expf(sacc[j][3] - mnew1);
            rs0 += p0 + p1; rs1 += p2 + p3;
            sacc[j][0] = p0; sacc[j][1] = p1; sacc[j][2] = p2; sacc[j][3] = p3;
        }
        rs0 += __shfl_xor_sync(0xffffffffu, rs0, 1);
        rs0 += __shfl_xor_sync(0xffffffffu, rs0, 2);
        rs1 += __shfl_xor_sync(0xffffffffu, rs1, 1);
        rs1 += __shfl_xor_sync(0xffffffffu, rs1, 2);
        lrow0 = lrow0 * alpha0 + rs0;
        lrow1 = lrow1 * alpha1 + rs1;
        mrow0 = mnew0; mrow1 = mnew1;
#pragma unroll
        for (int j = 0; j < 8; j++) {
            cacc[j][0] *= alpha0; cacc[j][1] *= alpha0;
            cacc[j][2] *= alpha1; cacc[j][3] *= alpha1;
        }
        // ---- ctx += P @ V (3-pass) ----
#pragma unroll
        for (int t = 0; t < 8; t++) {
            uint32_t pah[4], pal[4];
            {
                float* s0 = sacc[2 * t]; float* s1 = sacc[2 * t + 1];
                float v00 = s0[0], v01 = s0[1], v02 = s0[2], v03 = s0[3];
                float v10 = s1[0], v11 = s1[1], v12 = s1[2], v13 = s1[3];
                __nv_bfloat16 h00 = __float2bfloat16(v00), h01 = __float2bfloat16(v01);
                __nv_bfloat16 h02 = __float2bfloat16(v02), h03 = __float2bfloat16(v03);
                __nv_bfloat16 h10 = __float2bfloat16(v10), h11 = __float2bfloat16(v11);
                __nv_bfloat16 h12 = __float2bfloat16(v12), h13 = __float2bfloat16(v13);
                pah[0] = pack_bf2(v00, v01); pah[1] = pack_bf2(v02, v03);
                pah[2] = pack_bf2(v10, v11); pah[3] = pack_bf2(v12, v13);
                pal[0] = pack_bf2(v00 - __bfloat162float(h00), v01 - __bfloat162float(h01));
                pal[1] = pack_bf2(v02 - __bfloat162float(h02), v03 - __bfloat162float(h03));
                pal[2] = pack_bf2(v10 - __bfloat162float(h10), v11 - __bfloat162float(h11));
                pal[3] = pack_bf2(v12 - __bfloat162float(h12), v13 - __bfloat162float(h13));
            }
            uint32_t vbh[16], vbl[16];
            int sub = t >> 2;
            int cgv = (t & 3) * 2 + bcgs;
#pragma unroll
            for (int prd = 0; prd < 4; prd++) {
                int row = prd * 16 + brow_b;
                uint32_t off = (uint32_t)(sub * 8192) + (uint32_t)(row * 128) +
                               (uint32_t)((cgv ^ (row & 7)) << 4);
                LDSM4(vbh + prd * 4, Vh + off);
                LDSM4(vbl + prd * 4, Vl + off);
            }
#pragma unroll
            for (int jd = 0; jd < 8; jd++) {
                uint32_t* rh = vbh + (jd >> 1) * 4 + (jd & 1) * 2;
                uint32_t* rl = vbl + (jd >> 1) * 4 + (jd & 1) * 2;
                MMA_BF16(cacc[jd], pah, rh);
                MMA_BF16(cacc[jd], pal, rh);
                MMA_BF16(cacc[jd], pah, rl);
            }
        }
        __syncthreads();
        if (tid == 0 && kb + 2 < 16) issue(s, kb + 2);
    }
    // epilogue
    float inv0 = (lrow0 > 0.f) ? (1.f / lrow0) : 0.f;
    float inv1 = (lrow1 > 0.f) ? (1.f / lrow1) : 0.f;
    int r0 = qb * 128 + wid * 16 + (ln >> 2);
    int r1 = r0 + 8;
#pragma unroll
    for (int jd = 0; jd < 8; jd++) {
        int col = h * 64 + 8 * jd + q2;
        *(float2*)&ctx_out[(size_t)r0 * D_MODEL + col] =
            make_float2(cacc[jd][0] * inv0, cacc[jd][1] * inv0);
        *(float2*)&ctx_out[(size_t)r1 * D_MODEL + col] =
            make_float2(cacc[jd][2] * inv1, cacc[jd][3] * inv1);
    }
}

// ---------------- LayerNorm ---------------------------------------------------
__global__ void ln_kernel(const float* __restrict__ x, const float* __restrict__ w,
                          const float* __restrict__ b, float* __restrict__ out) {
    int row = blockIdx.x;
    const float* xr = x + (size_t)row * D_MODEL;
    float s = 0.f, s2 = 0.f;
    for (int i = threadIdx.x; i < D_MODEL; i += blockDim.x) {
        float v = xr[i]; s += v; s2 += v * v;
    }
    __shared__ float r0[256], r1[256];
    r0[threadIdx.x] = s; r1[threadIdx.x] = s2;
    __syncthreads();
    for (int o = 128; o > 0; o >>= 1) {
        if (threadIdx.x < o) { r0[threadIdx.x] += r0[threadIdx.x + o]; r1[threadIdx.x] += r1[threadIdx.x + o]; }
        __syncthreads();
    }
    float mean = r0[0] * (1.0f / D_MODEL);
    float var  = r1[0] * (1.0f / D_MODEL) - mean * mean;
    float inv  = rsqrtf(var + 1e-5f);
    float* orow = out + (size_t)row * D_MODEL;
    for (int i = threadIdx.x; i < D_MODEL; i += blockDim.x)
        orow[i] = (xr[i] - mean) * inv * w[i] + b[i];
}

// ---------------- fp32 row-major -> tiled swizzled bf16 hi/lo ----------------
__global__ void conv_act(const float* __restrict__ X, __nv_bfloat16* __restrict__ Hi,
                         __nv_bfloat16* __restrict__ Lo, int M, int K) {
    size_t idx = (size_t)blockIdx.x * blockDim.x + threadIdx.x;
    size_t total = (size_t)M * K / 8;
    if (idx >= total) return;
    int cpr = K >> 3;
    int m  = (int)(idx / cpr), ck = (int)(idx % cpr);
    int kt = ck >> 3, c8 = ck & 7;
    int mt = m >> 7, r = m & 127;
    int MT = M >> 7;
    size_t tile = ((size_t)kt * MT + mt) * TILE_B;
    uint32_t off = (uint32_t)(r * 128) + (uint32_t)((c8 ^ (r & 7)) << 4);
    const float* src = X + (size_t)m * K + (size_t)kt * 64 + c8 * 8;
    float4 v0 = *(const float4*)src;
    float4 v1 = *(const float4*)(src + 4);
    float xin[8] = {v0.x, v0.y, v0.z, v0.w, v1.x, v1.y, v1.z, v1.w};
    __nv_bfloat16 h8[8], l8[8];
#pragma unroll
    for (int u = 0; u < 8; u++) {
        __nv_bfloat16 hh = __float2bfloat16(xin[u]);
        h8[u] = hh;
        l8[u] = __float2bfloat16(xin[u] - __bfloat162float(hh));
    }
    *(uint4*)((char*)Hi + tile + off) = *(uint4*)h8;
    *(uint4*)((char*)Lo + tile + off) = *(uint4*)l8;
}

// ---------------- qkv fp32 -> per-head attention tiles (Q or K) --------------
__global__ void conv_att(const float* __restrict__ src, __nv_bfloat16* __restrict__ Hi,
                         __nv_bfloat16* __restrict__ Lo, int colbase, int H) {
    int idx = blockIdx.x * blockDim.x + threadIdx.x;
    int total = S_LEN * H * 8;
    if (idx >= total) return;
    int cpr = H * 8;
    int m = idx / cpr, rem = idx % cpr;
    int hh = rem >> 3, c8 = rem & 7;
    int sbk = m >> 7, r = m & 127;
    size_t tile = ((size_t)hh * 16 + sbk) * (size_t)TILE_B;
    uint32_t off = (uint32_t)(r * 128) + (uint32_t)((c8 ^ (r & 7)) << 4);
    const float* p = src + (size_t)m * QKV_N + colbase + hh * 64 + c8 * 8;
    float4 v0 = *(const float4*)p;
    float4 v1 = *(const float4*)(p + 4);
    float xin[8] = {v0.x, v0.y, v0.z, v0.w, v1.x, v1.y, v1.z, v1.w};
    __nv_bfloat16 h8[8], l8[8];
#pragma unroll
    for (int u = 0; u < 8; u++) {
        __nv_bfloat16 hv = __float2bfloat16(xin[u]);
        h8[u] = hv;
        l8[u] = __float2bfloat16(xin[u] - __bfloat162float(hv));
    }
    *(uint4*)((char*)Hi + tile + off) = *(uint4*)h8;
    *(uint4*)((char*)Lo + tile + off) = *(uint4*)l8;
}

// ---------------- V fp32 -> transposed tiles [64 d][128 keys] ----------------
__global__ void conv_vt(const float* __restrict__ src, __nv_bfloat16* __restrict__ Hi,
                        __nv_bfloat16* __restrict__ Lo) {
    __shared__ float s[128][65];
    int sbk = blockIdx.x, kvh = blockIdx.y;
    int tid = threadIdx.x;
    for (int t = tid; t < 128 * 16; t += 256) {
        int r = t >> 4, c4 = (t & 15) * 4;
        float4 v = *(const float4*)&src[(size_t)(sbk * 128 + r) * QKV_N + 2560 + kvh * 64 + c4];
        s[r][c4] = v.x; s[r][c4 + 1] = v.y; s[r][c4 + 2] = v.z; s[r][c4 + 3] = v.w;
    }
    __syncthreads();
    size_t tile = ((size_t)kvh * 16 + sbk) * (size_t)TILE_B;   // bytes
    for (int t = tid; t < 1024; t += 256) {
        int d = t >> 4, kc8 = t & 15;
        int sub = kc8 >> 3, c8 = kc8 & 7;
        __nv_bfloat16 h8[8], l8[8];
#pragma unroll
        for (int u = 0; u < 8; u++) {
            float x = s[(kc8 & 7) * 8 + sub * 64 + u][d];
            __nv_bfloat16 hv = __float2bfloat16(x);
            h8[u] = hv;
            l8[u] = __float2bfloat16(x - __bfloat162float(hv));
        }
        uint32_t off = (uint32_t)(sub * 8192) + (uint32_t)(d * 128) +
                       (uint32_t)((c8 ^ (d & 7)) << 4);
        *(uint4*)((char*)Hi + tile + off) = *(uint4*)h8;
        *(uint4*)((char*)Lo + tile + off) = *(uint4*)l8;
    }
}

// ---------------- fp32 weight [K,N] -> tiled transposed swizzled bf16 --------
__global__ void conv_w(const float* __restrict__ W, __nv_bfloat16* __restrict__ Hi,
                       __nv_bfloat16* __restrict__ Lo, int K, int Nsrc,
                       int nt_off, int NT_total) {
    __shared__ float s[128][65];
    int kt = blockIdx.x, nt = blockIdx.y;
    int tid = threadIdx.x;
    for (int t = tid; t < 64 * 32; t += 256) {
        int i = t >> 5, j4 = (t & 31) * 4;
        float4 v = *(const float4*)&W[((size_t)kt * 64 + i) * Nsrc + (size_t)nt * 128 + j4];
        s[j4 + 0][i] = v.x; s[j4 + 1][i] = v.y; s[j4 + 2][i] = v.z; s[j4 + 3][i] = v.w;
    }
    __syncthreads();
    size_t tile = ((size_t)kt * NT_total + (nt_off + nt)) * TILE_B;
    for (int t = tid; t < 1024; t += 256) {
        int r = t >> 3, c8 = t & 7;
        __nv_bfloat16 h8[8], l8[8];
#pragma unroll
        for (int u = 0; u < 8; u++) {
            float x = s[r][c8 * 8 + u];
            __nv_bfloat16 hv = __float2bfloat16(x);
            h8[u] = hv;
            l8[u] = __float2bfloat16(x - __bfloat162float(hv));
        }
        uint32_t off = (uint32_t)(r * 128) + (uint32_t)((c8 ^ (r & 7)) << 4);
        *(uint4*)((char*)Hi + tile + off) = *(uint4*)h8;
        *(uint4*)((char*)Lo + tile + off) = *(uint4*)l8;
    }
}

// ---------------- RoPE on qkv buffer -----------------------------------------
__global__ void rope_kernel(float* __restrict__ x, int H, int colbase, int total) {
    int idx = blockIdx.x * blockDim.x + threadIdx.x;
    if (idx >= total) return;
    int i = idx & 31;
    int t = idx >> 5;
    int h = t % H;
    int s = t / H;
    float freq = 1.0f / powf(10000.0f, (2.0f * (float)i) / 64.0f);
    float ang = (float)s * freq;
    float sn, cs; sincosf(ang, &sn, &cs);
    float* p = x + (size_t)s * QKV_N + colbase + h * 64 + 2 * i;
    float xr = p[0], xi = p[1];
    p[0] = xr * cs - xi * sn;
    p[1] = xr * sn + xi * cs;
}

// ---------------- silu(g1)*g3 from fused g13 ---------------------------------
__global__ void silumul_kernel(const float* __restrict__ g13, float* __restrict__ gb, int n) {
    int idx = blockIdx.x * blockDim.x + threadIdx.x;
    if (idx >= n) return;
    int s = idx / HID, j = idx % HID;
    float a = g13[(size_t)s * W13_N + j];
    float c = g13[(size_t)s * W13_N + HID + j];
    float sig = 1.0f / (1.0f + expf(-a));
    gb[idx] = a * sig * c;
}

// ---------------- launch -----------------------------------------------------
extern "C" void kernel_launch(void* const* d_in, const int* in_sizes, int n_in,
                              void* d_out, int out_size) {
    const float* x    = (const float*)d_in[0];
    const int*   mask = (const int*)  d_in[1];
    const float* wq   = (const float*)d_in[2];
    const float* wk   = (const float*)d_in[3];
    const float* wv   = (const float*)d_in[4];
    const float* wo   = (const float*)d_in[5];
    const float* w1   = (const float*)d_in[6];
    const float* w2   = (const float*)d_in[7];
    const float* w3   = (const float*)d_in[8];
    const float* ln1w = (const float*)d_in[9];
    const float* ln1b = (const float*)d_in[10];
    const float* ln2w = (const float*)d_in[11];
    const float* ln2b = (const float*)d_in[12];
    float* out = (float*)d_out;

    float *h, *qkv, *ctx, *x1, *g13, *gb;
    cudaGetSymbolAddress((void**)&h,   g_h);
    cudaGetSymbolAddress((void**)&qkv, g_qkv);
    cudaGetSymbolAddress((void**)&ctx, g_ctx);
    cudaGetSymbolAddress((void**)&x1,  g_x1);
    cudaGetSymbolAddress((void**)&g13, g_g13);
    cudaGetSymbolAddress((void**)&gb,  g_gb);

    __nv_bfloat16 *hhi, *hlo, *chi, *clo, *ghi, *glo;
    __nv_bfloat16 *wqkvh, *wqkvl, *woh, *wol, *w13h, *w13l, *w2h, *w2l;
    __nv_bfloat16 *qah, *qal, *kah, *kal, *vah, *val_;
    cudaGetSymbolAddress((void**)&hhi, t_h_hi);   cudaGetSymbolAddress((void**)&hlo, t_h_lo);
    cudaGetSymbolAddress((void**)&chi, t_ctx_hi); cudaGetSymbolAddress((void**)&clo, t_ctx_lo);
    cudaGetSymbolAddress((void**)&ghi, t_g_hi);   cudaGetSymbolAddress((void**)&glo, t_g_lo);
    cudaGetSymbolAddress((void**)&wqkvh, t_wqkv_hi); cudaGetSymbolAddress((void**)&wqkvl, t_wqkv_lo);
    cudaGetSymbolAddress((void**)&woh, t_wo_hi);  cudaGetSymbolAddress((void**)&wol, t_wo_lo);
    cudaGetSymbolAddress((void**)&w13h, t_w13_hi); cudaGetSymbolAddress((void**)&w13l, t_w13_lo);
    cudaGetSymbolAddress((void**)&w2h, t_w2_hi);  cudaGetSymbolAddress((void**)&w2l, t_w2_lo);
    cudaGetSymbolAddress((void**)&qah, t_qat_hi); cudaGetSymbolAddress((void**)&qal, t_qat_lo);
    cudaGetSymbolAddress((void**)&kah, t_kat_hi); cudaGetSymbolAddress((void**)&kal, t_kat_lo);
    cudaGetSymbolAddress((void**)&vah, t_vat_hi); cudaGetSymbolAddress((void**)&val_, t_vat_lo);

    cudaFuncSetAttribute(mma_gemm, cudaFuncAttributeMaxDynamicSharedMemorySize, GEMM_SMEM);
    cudaFuncSetAttribute(attn_mma, cudaFuncAttributeMaxDynamicSharedMemorySize, ATT_SMEM);

    // weights -> tiled bf16 hi/lo
    conv_w<<<dim3(D_MODEL / 64, 16), 256>>>(wq, wqkvh, wqkvl, D_MODEL, D_MODEL, 0,  24);
    conv_w<<<dim3(D_MODEL / 64, 4),  256>>>(wk, wqkvh, wqkvl, D_MODEL, 512,     16, 24);
    conv_w<<<dim3(D_MODEL / 64, 4),  256>>>(wv, wqkvh, wqkvl, D_MODEL, 512,     20, 24);
    conv_w<<<dim3(D_MODEL / 64, 16), 256>>>(wo, woh,   wol,   D_MODEL, D_MODEL, 0,  16);
    conv_w<<<dim3(D_MODEL / 64, 44), 256>>>(w1, w13h,  w13l,  D_MODEL, HID,     0,  88);
    conv_w<<<dim3(D_MODEL / 64, 44), 256>>>(w3, w13h,  w13l,  D_MODEL, HID,     44, 88);
    conv_w<<<dim3(HID / 64,     16), 256>>>(w2, w2h,   w2l,   HID,     D_MODEL, 0,  16);

    // h = LN1(x); tiled
    ln_kernel<<<S_LEN, 256>>>(x, ln1w, ln1b, h);
    conv_act<<<(S_LEN * D_MODEL / 8 + 255) / 256, 256>>>(h, hhi, hlo, S_LEN, D_MODEL);

    // qkv = h @ [wq|wk|wv]
    mma_gemm<<<dim3(QKV_N / 128, S_LEN / 128), 256, GEMM_SMEM>>>(hhi, hlo, wqkvh, wqkvl,
        nullptr, qkv, S_LEN, QKV_N, D_MODEL);

    rope_kernel<<<(S_LEN * NH  * 32 + 255) / 256, 256>>>(qkv, NH,  0,    S_LEN * NH  * 32);
    rope_kernel<<<(S_LEN * NKV * 32 + 255) / 256, 256>>>(qkv, NKV, 2048, S_LEN * NKV * 32);

    // attention operand tiles
    conv_att<<<(S_LEN * NH  * 8 + 255) / 256, 256>>>(qkv, qah, qal, 0,    NH);
    conv_att<<<(S_LEN * NKV * 8 + 255) / 256, 256>>>(qkv, kah, kal, 2048, NKV);
    conv_vt<<<dim3(16, NKV), 256>>>(qkv, vah, val_);

    // attention
    attn_mma<<<dim3(S_LEN / 128, NH), 256, ATT_SMEM>>>(qah, qal, kah, kal, vah, val_,
        mask, ctx);
    conv_act<<<(S_LEN * D_MODEL / 8 + 255) / 256, 256>>>(ctx, chi, clo, S_LEN, D_MODEL);

    // x1 = x + ctx @ wo
    mma_gemm<<<dim3(D_MODEL / 128, S_LEN / 128), 256, GEMM_SMEM>>>(chi, clo, woh, wol,
        x, x1, S_LEN, D_MODEL, D_MODEL);

    // h = LN2(x1); tiled
    ln_kernel<<<S_LEN, 256>>>(x1, ln2w, ln2b, h);
    conv_act<<<(S_LEN * D_MODEL / 8 + 255) / 256, 256>>>(h, hhi, hlo, S_LEN, D_MODEL);

    // g13 = h @ [w1|w3]
    mma_gemm<<<dim3(W13_N / 128, S_LEN / 128), 256, GEMM_SMEM>>>(hhi, hlo, w13h, w13l,
        nullptr, g13, S_LEN, W13_N, D_MODEL);

    silumul_kernel<<<(S_LEN * HID + 255) / 256, 256>>>(g13, gb, S_LEN * HID);
    conv_act<<<(S_LEN * HID / 8 + 255) / 256, 256>>>(gb, ghi, glo, S_LEN, HID);

    // out = x1 + gb @ w2
    mma_gemm<<<dim3(D_MODEL / 128, S_LEN / 128), 256, GEMM_SMEM>>>(ghi, glo, w2h, w2l,
        x1, out, S_LEN, D_MODEL, HID);
}

// round 9
// speedup vs baseline: 3.9223x; 1.0121x over previous
#include <cuda_runtime.h>
#include <cuda_bf16.h>
#include <cstdint>
#include <math.h>

#define S_LEN   2048
#define D_MODEL 2048
#define HID     5632
#define NH      32
#define NKV     8
#define HD      64
#define QKV_N   3072        // 2048 q | 512 k | 512 v
#define W13_N   11264       // 5632 g1 | 5632 g3
#define TILE_B  16384

// ---------------- fp32 scratch ------------------------------------------------
__device__ __align__(1024) float g_qkv[S_LEN * QKV_N];   // only V cols written/read
__device__ __align__(1024) float g_x1 [S_LEN * D_MODEL];

// ---------------- bf16 scratch ------------------------------------------------
__device__ __align__(1024) __nv_bfloat16 t_h_hi  [S_LEN * D_MODEL];
__device__ __align__(1024) __nv_bfloat16 t_h_lo  [S_LEN * D_MODEL];
__device__ __align__(1024) __nv_bfloat16 t_ctx_hi[S_LEN * D_MODEL];
__device__ __align__(1024) __nv_bfloat16 t_ctx_lo[S_LEN * D_MODEL];
__device__ __align__(1024) __nv_bfloat16 t_g_hi  [S_LEN * HID];
__device__ __align__(1024) __nv_bfloat16 t_g_lo  [S_LEN * HID];
__device__ __align__(1024) __nv_bfloat16 t_g13_hi[S_LEN * W13_N];   // row-major
__device__ __align__(1024) __nv_bfloat16 t_g13_lo[S_LEN * W13_N];   // row-major
__device__ __align__(1024) __nv_bfloat16 t_wqkv_hi[QKV_N * D_MODEL];
__device__ __align__(1024) __nv_bfloat16 t_wqkv_lo[QKV_N * D_MODEL];
__device__ __align__(1024) __nv_bfloat16 t_wo_hi [D_MODEL * D_MODEL];
__device__ __align__(1024) __nv_bfloat16 t_wo_lo [D_MODEL * D_MODEL];
__device__ __align__(1024) __nv_bfloat16 t_w13_hi[W13_N * D_MODEL];
__device__ __align__(1024) __nv_bfloat16 t_w13_lo[W13_N * D_MODEL];
__device__ __align__(1024) __nv_bfloat16 t_w2_hi [D_MODEL * HID];
__device__ __align__(1024) __nv_bfloat16 t_w2_lo [D_MODEL * HID];
__device__ __align__(1024) __nv_bfloat16 t_qat_hi[NH  * 16 * 8192];
__device__ __align__(1024) __nv_bfloat16 t_qat_lo[NH  * 16 * 8192];
__device__ __align__(1024) __nv_bfloat16 t_kat_hi[NKV * 16 * 8192];
__device__ __align__(1024) __nv_bfloat16 t_kat_lo[NKV * 16 * 8192];
__device__ __align__(1024) __nv_bfloat16 t_vat_hi[NKV * 16 * 8192];
__device__ __align__(1024) __nv_bfloat16 t_vat_lo[NKV * 16 * 8192];

// ---------------- PTX helpers (baseline PTX only) -----------------------------
__device__ __forceinline__ uint32_t smem_u32(const void* p) {
    uint32_t a;
    asm("{ .reg .u64 t; cvta.to.shared.u64 t, %1; cvt.u32.u64 %0, t; }" : "=r"(a) : "l"(p));
    return a;
}
#define MBAR_INIT(a, c) asm volatile("mbarrier.init.shared.b64 [%0], %1;" :: "r"(a), "r"(c) : "memory")
#define MBAR_EXPECT(a, b) asm volatile("mbarrier.arrive.expect_tx.shared.b64 _, [%0], %1;" :: "r"(a), "r"(b) : "memory")
__device__ __forceinline__ void mbar_wait(uint32_t mbar, uint32_t parity) {
    asm volatile(
        "{\n\t.reg .pred P1;\n\t"
        "W_%=:\n\t"
        "mbarrier.try_wait.parity.acquire.cta.shared::cta.b64 P1, [%0], %1, 0x989680;\n\t"
        "@P1 bra.uni D_%=;\n\t"
        "bra.uni W_%=;\n\t"
        "D_%=:\n\t}"
        :: "r"(mbar), "r"(parity) : "memory");
}
__device__ __forceinline__ void bulk_g2s(uint32_t dst, const void* src, uint32_t bytes, uint32_t mbar) {
    asm volatile("cp.async.bulk.shared::cta.global.mbarrier::complete_tx::bytes [%0], [%1], %2, [%3];"
        :: "r"(dst), "l"(src), "r"(bytes), "r"(mbar) : "memory");
}
#define LDSM4(r, a) \
    asm volatile("ldmatrix.sync.aligned.m8n8.x4.shared.b16 {%0,%1,%2,%3}, [%4];" \
        : "=r"((r)[0]), "=r"((r)[1]), "=r"((r)[2]), "=r"((r)[3]) : "r"(a))
#define MMA_BF16(d, a, b) \
    asm volatile("mma.sync.aligned.m16n8k16.row.col.f32.bf16.bf16.f32 " \
        "{%0,%1,%2,%3}, {%4,%5,%6,%7}, {%8,%9}, {%0,%1,%2,%3};" \
        : "+f"((d)[0]), "+f"((d)[1]), "+f"((d)[2]), "+f"((d)[3]) \
        : "r"((a)[0]), "r"((a)[1]), "r"((a)[2]), "r"((a)[3]), "r"((b)[0]), "r"((b)[1]))

__device__ __forceinline__ uint32_t pack_bf2(float a, float b) {
    __nv_bfloat162 t = __floats2bfloat162_rn(a, b);
    return *(uint32_t*)&t;
}
// split pair into hi/lo packed bf16x2
__device__ __forceinline__ void split_pair(float v0, float v1, uint32_t& hi, uint32_t& lo) {
    __nv_bfloat16 h0 = __float2bfloat16(v0);
    __nv_bfloat16 h1 = __float2bfloat16(v1);
    hi = pack_bf2(v0, v1);
    lo = pack_bf2(v0 - __bfloat162float(h0), v1 - __bfloat162float(h1));
}

// ---------------- mma.sync GEMM (3-stage pipeline, fused epilogues) ----------
// mode 0: C fp32 (+R)
// mode 1: qkv — rope Q/K into attention tiles (P0/P1=Q hi/lo, P2/P3=K hi/lo),
//         V columns (>=2560) -> C fp32
// mode 2: row-major bf16 hi/lo into P0/P1
__global__ void __launch_bounds__(256, 1) mma_gemm(
    const __nv_bfloat16* __restrict__ Ahi, const __nv_bfloat16* __restrict__ Alo,
    const __nv_bfloat16* __restrict__ Bhi, const __nv_bfloat16* __restrict__ Blo,
    const float* __restrict__ R, float* __restrict__ C, int M, int N, int K, int mode,
    __nv_bfloat16* __restrict__ P0, __nv_bfloat16* __restrict__ P1,
    __nv_bfloat16* __restrict__ P2, __nv_bfloat16* __restrict__ P3)
{
    extern __shared__ char smem[];
    uint32_t sb = smem_u32(smem);
    int tid = threadIdx.x, wid = tid >> 5, ln = tid & 31;
    int wm = wid >> 2, wn = wid & 3;
    int mt = blockIdx.y, nt = blockIdx.x;
    int MT = M >> 7, NT = N >> 7, KTt = K >> 6;
    uint32_t mb0 = sb + 3 * 4 * TILE_B;

    if (tid == 0) { MBAR_INIT(mb0, 1); MBAR_INIT(mb0 + 8, 1); MBAR_INIT(mb0 + 16, 1); }
    __syncthreads();

    auto issue = [&](int s, int kt) {
        uint32_t mb = mb0 + s * 8;
        uint32_t dst = sb + s * (4 * TILE_B);
        size_t aoff = ((size_t)kt * MT + mt) * (size_t)(128 * 64);
        size_t boff = ((size_t)kt * NT + nt) * (size_t)(128 * 64);
        MBAR_EXPECT(mb, 4 * TILE_B);
        bulk_g2s(dst,              Ahi + aoff, TILE_B, mb);
        bulk_g2s(dst + TILE_B,     Alo + aoff, TILE_B, mb);
        bulk_g2s(dst + 2 * TILE_B, Bhi + boff, TILE_B, mb);
        bulk_g2s(dst + 3 * TILE_B, Blo + boff, TILE_B, mb);
    };
    if (tid == 0) { issue(0, 0); issue(1, 1); issue(2, 2); }

    float acc[4][4][4];
#pragma unroll
    for (int i = 0; i < 4; i++)
#pragma unroll
        for (int j = 0; j < 4; j++)
#pragma unroll
            for (int r = 0; r < 4; r++) acc[i][j][r] = 0.f;

    int arow0 = wm * 64 + (ln & 7) + ((ln & 8) ? 8 : 0);
    int acgs  = (ln >> 4) & 1;
    int brow0 = wn * 32 + (ln & 7) + ((ln & 16) ? 8 : 0);
    int bcgs  = (ln >> 3) & 1;

    for (int kt = 0; kt < KTt; kt++) {
        int s = kt % 3, ph = (kt / 3) & 1;
        mbar_wait(mb0 + s * 8, ph);
        uint32_t st = sb + s * (4 * TILE_B);
        uint32_t Ah = st, Al = st + TILE_B, Bh = st + 2 * TILE_B, Bl = st + 3 * TILE_B;
#pragma unroll
        for (int ks = 0; ks < 4; ks++) {
            int acg = ks * 2 + acgs;
            int bcg = ks * 2 + bcgs;
            uint32_t ahr[16], alr[16], bhr[8], blr[8];
#pragma unroll
            for (int fm = 0; fm < 4; fm++) {
                int row = arow0 + fm * 16;
                uint32_t off = (uint32_t)(row * 128) + (uint32_t)((acg ^ (row & 7)) << 4);
                LDSM4(ahr + fm * 4, Ah + off);
                LDSM4(alr + fm * 4, Al + off);
            }
#pragma unroll
            for (int pr = 0; pr < 2; pr++) {
                int row = brow0 + pr * 16;
                uint32_t off = (uint32_t)(row * 128) + (uint32_t)((bcg ^ (row & 7)) << 4);
                LDSM4(bhr + pr * 4, Bh + off);
                LDSM4(blr + pr * 4, Bl + off);
            }
#pragma unroll
            for (int fm = 0; fm < 4; fm++)
#pragma unroll
                for (int fn = 0; fn < 4; fn++) {
                    MMA_BF16(acc[fm][fn], ahr + fm * 4, bhr + fn * 2);
                    MMA_BF16(acc[fm][fn], ahr + fm * 4, blr + fn * 2);
                    MMA_BF16(acc[fm][fn], alr + fm * 4, bhr + fn * 2);
                }
        }
        __syncthreads();
        if (tid == 0 && kt + 3 < KTt) issue(s, kt + 3);
    }

    int qr = ln >> 2, qc = ln & 3;
#pragma unroll
    for (int fm = 0; fm < 4; fm++) {
        int row0 = mt * 128 + wm * 64 + fm * 16 + qr;
#pragma unroll
        for (int fn = 0; fn < 4; fn++) {
            int col = nt * 128 + wn * 32 + fn * 8 + 2 * qc;
            if (mode == 0) {
                size_t i0 = (size_t)row0 * N + col;
                size_t i1 = (size_t)(row0 + 8) * N + col;
                float2 v0 = make_float2(acc[fm][fn][0], acc[fm][fn][1]);
                float2 v1 = make_float2(acc[fm][fn][2], acc[fm][fn][3]);
                if (R) {
                    float2 r0 = *(const float2*)&R[i0];
                    float2 r1 = *(const float2*)&R[i1];
                    v0.x += r0.x; v0.y += r0.y; v1.x += r1.x; v1.y += r1.y;
                }
                *(float2*)&C[i0] = v0;
                *(float2*)&C[i1] = v1;
            } else if (mode == 2) {
                uint32_t h0, l0, h1, l1;
                split_pair(acc[fm][fn][0], acc[fm][fn][1], h0, l0);
                split_pair(acc[fm][fn][2], acc[fm][fn][3], h1, l1);
                size_t i0 = ((size_t)row0 * N + col) >> 1;
                size_t i1 = ((size_t)(row0 + 8) * N + col) >> 1;
                ((uint32_t*)P0)[i0] = h0; ((uint32_t*)P1)[i0] = l0;
                ((uint32_t*)P0)[i1] = h1; ((uint32_t*)P1)[i1] = l1;
            } else {   // mode 1: qkv
                if (col >= 2560) {
                    size_t i0 = (size_t)row0 * N + col;
                    size_t i1 = (size_t)(row0 + 8) * N + col;
                    *(float2*)&C[i0] = make_float2(acc[fm][fn][0], acc[fm][fn][1]);
                    *(float2*)&C[i1] = make_float2(acc[fm][fn][2], acc[fm][fn][3]);
                } else {
                    int i = (col & 63) >> 1;
                    float freq = 1.0f / powf(10000.0f, (2.0f * (float)i) / 64.0f);
                    __nv_bfloat16* Hp; __nv_bfloat16* Lp; int head;
                    if (col < 2048) { head = col >> 6; Hp = P0; Lp = P1; }
                    else            { head = (col - 2048) >> 6; Hp = P2; Lp = P3; }
                    int c8 = (col & 63) >> 3;
                    uint32_t inoff = (uint32_t)((col & 7) * 2);
#pragma unroll
                    for (int rr = 0; rr < 2; rr++) {
                        int row = row0 + rr * 8;
                        float v0 = acc[fm][fn][rr * 2], v1 = acc[fm][fn][rr * 2 + 1];
                        float sn, cs; sincosf((float)row * freq, &sn, &cs);
                        float orr = v0 * cs - v1 * sn;
                        float oii = v0 * sn + v1 * cs;
                        uint32_t hi, lo;
                        split_pair(orr, oii, hi, lo);
                        int r = row & 127;
                        size_t tile = ((size_t)head * 16 + (row >> 7)) * (size_t)TILE_B;
                        uint32_t off = (uint32_t)(r * 128) + (uint32_t)((c8 ^ (r & 7)) << 4) + inoff;
                        *(uint32_t*)((char*)Hp + tile + off) = hi;
                        *(uint32_t*)((char*)Lp + tile + off) = lo;
                    }
                }
            }
        }
    }
}
#define GEMM_SMEM (3 * 4 * TILE_B + 64)

// ---------------- tensorized flash attention ---------------------------------
#define ATT_SQ    0u
#define ATT_SMSK  32768u
#define ATT_SST   40960u
#define ATT_MB    (40960u + 131072u)
#define ATT_SMEM  (40960 + 131072 + 64)
__global__ void __launch_bounds__(256, 1) attn_mma(
    const __nv_bfloat16* __restrict__ Qhi, const __nv_bfloat16* __restrict__ Qlo,
    const __nv_bfloat16* __restrict__ Khi, const __nv_bfloat16* __restrict__ Klo,
    const __nv_bfloat16* __restrict__ Vhi, const __nv_bfloat16* __restrict__ Vlo,
    const int* __restrict__ mask,
    __nv_bfloat16* __restrict__ Chi, __nv_bfloat16* __restrict__ Clo)
{
    extern __shared__ char smem[];
    uint32_t sb = smem_u32(smem);
    int tid = threadIdx.x, wid = tid >> 5, ln = tid & 31;
    int qb = blockIdx.x, h = blockIdx.y;
    int kvh = h >> 2;
    int q2 = (ln & 3) * 2;

    int* msk = (int*)(smem + ATT_SMSK);
    for (int i = tid; i < S_LEN; i += 256) msk[i] = mask[i];
    {
        const uint4* qs0 = (const uint4*)(Qhi + ((size_t)h * 16 + qb) * 8192);
        const uint4* qs1 = (const uint4*)(Qlo + ((size_t)h * 16 + qb) * 8192);
        uint4* qd0 = (uint4*)(smem + ATT_SQ);
        uint4* qd1 = (uint4*)(smem + ATT_SQ + 16384);
        for (int i = tid; i < 1024; i += 256) { qd0[i] = qs0[i]; qd1[i] = qs1[i]; }
    }
    uint32_t mb0 = sb + ATT_MB;
    if (tid == 0) { MBAR_INIT(mb0, 1); MBAR_INIT(mb0 + 8, 1); }
    __syncthreads();

    auto issue = [&](int s, int kb) {
        uint32_t mb = mb0 + s * 8;
        uint32_t dst = sb + ATT_SST + s * 65536;
        size_t ko = ((size_t)kvh * 16 + kb) * 8192;
        MBAR_EXPECT(mb, 65536);
        bulk_g2s(dst,         Khi + ko, 16384, mb);
        bulk_g2s(dst + 16384, Klo + ko, 16384, mb);
        bulk_g2s(dst + 32768, Vhi + ko, 16384, mb);
        bulk_g2s(dst + 49152, Vlo + ko, 16384, mb);
    };
    if (tid == 0) { issue(0, 0); issue(1, 1); }

    uint32_t qh[4][4], qlr[4][4];
    {
        int arow0 = wid * 16 + (ln & 7) + ((ln & 8) ? 8 : 0);
        int acgs = (ln >> 4) & 1;
#pragma unroll
        for (int ks = 0; ks < 4; ks++) {
            int cg = ks * 2 + acgs;
            uint32_t off = (uint32_t)(arow0 * 128) + (uint32_t)((cg ^ (arow0 & 7)) << 4);
            LDSM4(qh[ks],  sb + ATT_SQ + off);
            LDSM4(qlr[ks], sb + ATT_SQ + 16384 + off);
        }
    }

    float mrow0 = -INFINITY, mrow1 = -INFINITY, lrow0 = 0.f, lrow1 = 0.f;
    float cacc[8][4];
#pragma unroll
    for (int j = 0; j < 8; j++)
#pragma unroll
        for (int r = 0; r < 4; r++) cacc[j][r] = 0.f;

    int brow_b = (ln & 7) + ((ln & 16) ? 8 : 0);
    int bcgs = (ln >> 3) & 1;

    for (int kb = 0; kb < 16; kb++) {
        int s = kb & 1, ph = (kb >> 1) & 1;
        mbar_wait(mb0 + s * 8, ph);
        uint32_t st = sb + ATT_SST + s * 65536;
        uint32_t Kh = st, Kl = st + 16384, Vh = st + 32768, Vl = st + 49152;

        float sacc[16][4];
#pragma unroll
        for (int j = 0; j < 16; j++)
#pragma unroll
            for (int r = 0; r < 4; r++) sacc[j][r] = 0.f;
#pragma unroll
        for (int nj = 0; nj < 4; nj++) {
#pragma unroll
            for (int ks = 0; ks < 4; ks++) {
                uint32_t bh[8], bl[8];
                int cg = ks * 2 + bcgs;
#pragma unroll
                for (int pr = 0; pr < 2; pr++) {
                    int row = nj * 32 + pr * 16 + brow_b;
                    uint32_t off = (uint32_t)(row * 128) + (uint32_t)((cg ^ (row & 7)) << 4);
                    LDSM4(bh + pr * 4, Kh + off);
                    LDSM4(bl + pr * 4, Kl + off);
                }
#pragma unroll
                for (int nt = 0; nt < 4; nt++) {
                    float* d = sacc[nj * 4 + nt];
                    uint32_t* rh = bh + (nt >> 1) * 4 + (nt & 1) * 2;
                    uint32_t* rl = bl + (nt >> 1) * 4 + (nt & 1) * 2;
                    MMA_BF16(d, qh[ks], rh);
                    MMA_BF16(d, qh[ks], rl);
                    MMA_BF16(d, qlr[ks], rh);
                }
            }
        }
        float tmax0 = -INFINITY, tmax1 = -INFINITY;
#pragma unroll
        for (int j = 0; j < 16; j++) {
            int c = kb * 128 + 8 * j + q2;
            sacc[j][0] = msk[c]     ? sacc[j][0] * 0.125f : -1e30f;
            sacc[j][1] = msk[c + 1] ? sacc[j][1] * 0.125f : -1e30f;
            sacc[j][2] = msk[c]     ? sacc[j][2] * 0.125f : -1e30f;
            sacc[j][3] = msk[c + 1] ? sacc[j][3] * 0.125f : -1e30f;
            tmax0 = fmaxf(tmax0, fmaxf(sacc[j][0], sacc[j][1]));
            tmax1 = fmaxf(tmax1, fmaxf(sacc[j][2], sacc[j][3]));
        }
        tmax0 = fmaxf(tmax0, __shfl_xor_sync(0xffffffffu, tmax0, 1));
        tmax0 = fmaxf(tmax0, __shfl_xor_sync(0xffffffffu, tmax0, 2));
        tmax1 = fmaxf(tmax1, __shfl_xor_sync(0xffffffffu, tmax1, 1));
        tmax1 = fmaxf(tmax1, __shfl_xor_sync(0xffffffffu, tmax1, 2));
        float mnew0 = fmaxf(mrow0, tmax0);
        float mnew1 = fmaxf(mrow1, tmax1);
        float alpha0 = (mrow0 == -INFINITY) ? 0.f : __expf(mrow0 - mnew0);
        float alpha1 = (mrow1 == -INFINITY) ? 0.f : __expf(mrow1 - mnew1);
        float rs0 = 0.f, rs1 = 0.f;
#pragma unroll
        for (int j = 0; j < 16; j++) {
            float p0 = __expf(sacc[j][0] - mnew0);
            float p1 = __expf(sacc[j][1] - mnew0);
            float p2 = __expf(sacc[j][2] - mnew1);
            float p3 = __expf(sacc[j][3] - mnew1);
            rs0 += p0 + p1; rs1 += p2 + p3;
            sacc[j][0] = p0; sacc[j][1] = p1; sacc[j][2] = p2; sacc[j][3] = p3;
        }
        rs0 += __shfl_xor_sync(0xffffffffu, rs0, 1);
        rs0 += __shfl_xor_sync(0xffffffffu, rs0, 2);
        rs1 += __shfl_xor_sync(0xffffffffu, rs1, 1);
        rs1 += __shfl_xor_sync(0xffffffffu, rs1, 2);
        lrow0 = lrow0 * alpha0 + rs0;
        lrow1 = lrow1 * alpha1 + rs1;
        mrow0 = mnew0; mrow1 = mnew1;
#pragma unroll
        for (int j = 0; j < 8; j++) {
            cacc[j][0] *= alpha0; cacc[j][1] *= alpha0;
            cacc[j][2] *= alpha1; cacc[j][3] *= alpha1;
        }
#pragma unroll
        for (int t = 0; t < 8; t++) {
            uint32_t pah[4], pal[4];
            {
                float* s0 = sacc[2 * t]; float* s1 = sacc[2 * t + 1];
                float v00 = s0[0], v01 = s0[1], v02 = s0[2], v03 = s0[3];
                float v10 = s1[0], v11 = s1[1], v12 = s1[2], v13 = s1[3];
                __nv_bfloat16 h00 = __float2bfloat16(v00), h01 = __float2bfloat16(v01);
                __nv_bfloat16 h02 = __float2bfloat16(v02), h03 = __float2bfloat16(v03);
                __nv_bfloat16 h10 = __float2bfloat16(v10), h11 = __float2bfloat16(v11);
                __nv_bfloat16 h12 = __float2bfloat16(v12), h13 = __float2bfloat16(v13);
                pah[0] = pack_bf2(v00, v01); pah[1] = pack_bf2(v02, v03);
                pah[2] = pack_bf2(v10, v11); pah[3] = pack_bf2(v12, v13);
                pal[0] = pack_bf2(v00 - __bfloat162float(h00), v01 - __bfloat162float(h01));
                pal[1] = pack_bf2(v02 - __bfloat162float(h02), v03 - __bfloat162float(h03));
                pal[2] = pack_bf2(v10 - __bfloat162float(h10), v11 - __bfloat162float(h11));
                pal[3] = pack_bf2(v12 - __bfloat162float(h12), v13 - __bfloat162float(h13));
            }
            uint32_t vbh[16], vbl[16];
            int sub = t >> 2;
            int cgv = (t & 3) * 2 + bcgs;
#pragma unroll
            for (int prd = 0; prd < 4; prd++) {
                int row = prd * 16 + brow_b;
                uint32_t off = (uint32_t)(sub * 8192) + (uint32_t)(row * 128) +
                               (uint32_t)((cgv ^ (row & 7)) << 4);
                LDSM4(vbh + prd * 4, Vh + off);
                LDSM4(vbl + prd * 4, Vl + off);
            }
#pragma unroll
            for (int jd = 0; jd < 8; jd++) {
                uint32_t* rh = vbh + (jd >> 1) * 4 + (jd & 1) * 2;
                uint32_t* rl = vbl + (jd >> 1) * 4 + (jd & 1) * 2;
                MMA_BF16(cacc[jd], pah, rh);
                MMA_BF16(cacc[jd], pal, rh);
                MMA_BF16(cacc[jd], pah, rl);
            }
        }
        __syncthreads();
        if (tid == 0 && kb + 2 < 16) issue(s, kb + 2);
    }
    // epilogue -> ctx tiles (hi/lo) directly; A-layout for wo GEMM: kt = head
    float inv0 = (lrow0 > 0.f) ? (1.f / lrow0) : 0.f;
    float inv1 = (lrow1 > 0.f) ? (1.f / lrow1) : 0.f;
    int r0 = wid * 16 + (ln >> 2);    // row within 128-block
    size_t tile = ((size_t)h * 16 + qb) * (size_t)TILE_B;
#pragma unroll
    for (int jd = 0; jd < 8; jd++) {
        uint32_t inoff = (uint32_t)(q2 * 2);
#pragma unroll
        for (int rr = 0; rr < 2; rr++) {
            int r = r0 + rr * 8;
            float v0 = cacc[jd][rr * 2] * (rr ? inv1 : inv0);
            float v1 = cacc[jd][rr * 2 + 1] * (rr ? inv1 : inv0);
            uint32_t hi, lo;
            split_pair(v0, v1, hi, lo);
            uint32_t off = (uint32_t)(r * 128) + (uint32_t)((jd ^ (r & 7)) << 4) + inoff;
            *(uint32_t*)((char*)Chi + tile + off) = hi;
            *(uint32_t*)((char*)Clo + tile + off) = lo;
        }
    }
}

// ---------------- LayerNorm -> tiled bf16 hi/lo directly ----------------------
__global__ void ln_tile(const float* __restrict__ x, const float* __restrict__ w,
                        const float* __restrict__ b,
                        __nv_bfloat16* __restrict__ Hi, __nv_bfloat16* __restrict__ Lo) {
    int row = blockIdx.x;
    int tid = threadIdx.x;
    const float* xr = x + (size_t)row * D_MODEL;
    float4 v0 = *(const float4*)&xr[tid * 8];
    float4 v1 = *(const float4*)&xr[tid * 8 + 4];
    float xin[8] = {v0.x, v0.y, v0.z, v0.w, v1.x, v1.y, v1.z, v1.w};
    float s = 0.f, s2 = 0.f;
#pragma unroll
    for (int u = 0; u < 8; u++) { s += xin[u]; s2 += xin[u] * xin[u]; }
    __shared__ float r0s[256], r1s[256];
    r0s[tid] = s; r1s[tid] = s2;
    __syncthreads();
    for (int o = 128; o > 0; o >>= 1) {
        if (tid < o) { r0s[tid] += r0s[tid + o]; r1s[tid] += r1s[tid + o]; }
        __syncthreads();
    }
    float mean = r0s[0] * (1.0f / D_MODEL);
    float var  = r1s[0] * (1.0f / D_MODEL) - mean * mean;
    float inv  = rsqrtf(var + 1e-5f);
    int kt = tid >> 3, c8 = tid & 7;
    int mt = row >> 7, r = row & 127;
    size_t tile = ((size_t)kt * 16 + mt) * (size_t)TILE_B;
    uint32_t off = (uint32_t)(r * 128) + (uint32_t)((c8 ^ (r & 7)) << 4);
    __nv_bfloat16 h8[8], l8[8];
#pragma unroll
    for (int u = 0; u < 8; u++) {
        float vv = (xin[u] - mean) * inv * w[tid * 8 + u] + b[tid * 8 + u];
        __nv_bfloat16 hh = __float2bfloat16(vv);
        h8[u] = hh;
        l8[u] = __float2bfloat16(vv - __bfloat162float(hh));
    }
    *(uint4*)((char*)Hi + tile + off) = *(uint4*)h8;
    *(uint4*)((char*)Lo + tile + off) = *(uint4*)l8;
}

// ---------------- V fp32 -> transposed tiles [64 d][128 keys] ----------------
__global__ void conv_vt(const float* __restrict__ src, __nv_bfloat16* __restrict__ Hi,
                        __nv_bfloat16* __restrict__ Lo) {
    __shared__ float s[128][65];
    int sbk = blockIdx.x, kvh = blockIdx.y;
    int tid = threadIdx.x;
    for (int t = tid; t < 128 * 16; t += 256) {
        int r = t >> 4, c4 = (t & 15) * 4;
        float4 v = *(const float4*)&src[(size_t)(sbk * 128 + r) * QKV_N + 2560 + kvh * 64 + c4];
        s[r][c4] = v.x; s[r][c4 + 1] = v.y; s[r][c4 + 2] = v.z; s[r][c4 + 3] = v.w;
    }
    __syncthreads();
    size_t tile = ((size_t)kvh * 16 + sbk) * (size_t)TILE_B;
    for (int t = tid; t < 1024; t += 256) {
        int d = t >> 4, kc8 = t & 15;
        int sub = kc8 >> 3, c8 = kc8 & 7;
        __nv_bfloat16 h8[8], l8[8];
#pragma unroll
        for (int u = 0; u < 8; u++) {
            float x = s[(kc8 & 7) * 8 + sub * 64 + u][d];
            __nv_bfloat16 hv = __float2bfloat16(x);
            h8[u] = hv;
            l8[u] = __float2bfloat16(x - __bfloat162float(hv));
        }
        uint32_t off = (uint32_t)(sub * 8192) + (uint32_t)(d * 128) +
                       (uint32_t)((c8 ^ (d & 7)) << 4);
        *(uint4*)((char*)Hi + tile + off) = *(uint4*)h8;
        *(uint4*)((char*)Lo + tile + off) = *(uint4*)l8;
    }
}

// ---------------- fp32 weight [K,N] -> tiled transposed swizzled bf16 --------
__global__ void conv_w(const float* __restrict__ W, __nv_bfloat16* __restrict__ Hi,
                       __nv_bfloat16* __restrict__ Lo, int K, int Nsrc,
                       int nt_off, int NT_total) {
    __shared__ float s[128][65];
    int kt = blockIdx.x, nt = blockIdx.y;
    int tid = threadIdx.x;
    for (int t = tid; t < 64 * 32; t += 256) {
        int i = t >> 5, j4 = (t & 31) * 4;
        float4 v = *(const float4*)&W[((size_t)kt * 64 + i) * Nsrc + (size_t)nt * 128 + j4];
        s[j4 + 0][i] = v.x; s[j4 + 1][i] = v.y; s[j4 + 2][i] = v.z; s[j4 + 3][i] = v.w;
    }
    __syncthreads();
    size_t tile = ((size_t)kt * NT_total + (nt_off + nt)) * TILE_B;
    for (int t = tid; t < 1024; t += 256) {
        int r = t >> 3, c8 = t & 7;
        __nv_bfloat16 h8[8], l8[8];
#pragma unroll
        for (int u = 0; u < 8; u++) {
            float x = s[r][c8 * 8 + u];
            __nv_bfloat16 hv = __float2bfloat16(x);
            h8[u] = hv;
            l8[u] = __float2bfloat16(x - __bfloat162float(hv));
        }
        uint32_t off = (uint32_t)(r * 128) + (uint32_t)((c8 ^ (r & 7)) << 4);
        *(uint4*)((char*)Hi + tile + off) = *(uint4*)h8;
        *(uint4*)((char*)Lo + tile + off) = *(uint4*)l8;
    }
}

// ---------------- silu(g1)*g3 from bf16 hi/lo -> gb tiles --------------------
__global__ void silu_conv(const __nv_bfloat16* __restrict__ Gh, const __nv_bfloat16* __restrict__ Gl,
                          __nv_bfloat16* __restrict__ Hi, __nv_bfloat16* __restrict__ Lo) {
    int idx = blockIdx.x * blockDim.x + threadIdx.x;   // chunk of 8
    int cpr = HID / 8;                                 // 704
    int m = idx / cpr, ck = idx % cpr;
    size_t base1 = (size_t)m * W13_N + ck * 8;
    size_t base3 = base1 + HID;
    uint4 g1h4 = *(const uint4*)&Gh[base1];
    uint4 g1l4 = *(const uint4*)&Gl[base1];
    uint4 g3h4 = *(const uint4*)&Gh[base3];
    uint4 g3l4 = *(const uint4*)&Gl[base3];
    const __nv_bfloat16* g1h = (const __nv_bfloat16*)&g1h4;
    const __nv_bfloat16* g1l = (const __nv_bfloat16*)&g1l4;
    const __nv_bfloat16* g3h = (const __nv_bfloat16*)&g3h4;
    const __nv_bfloat16* g3l = (const __nv_bfloat16*)&g3l4;
    __nv_bfloat16 h8[8], l8[8];
#pragma unroll
    for (int u = 0; u < 8; u++) {
        float a = __bfloat162float(g1h[u]) + __bfloat162float(g1l[u]);
        float c = __bfloat162float(g3h[u]) + __bfloat162float(g3l[u]);
        float sig = 1.0f / (1.0f + expf(-a));
        float vv = a * sig * c;
        __nv_bfloat16 hh = __float2bfloat16(vv);
        h8[u] = hh;
        l8[u] = __float2bfloat16(vv - __bfloat162float(hh));
    }
    int kt = ck >> 3, c8 = ck & 7;
    int mt = m >> 7, r = m & 127;
    size_t tile = ((size_t)kt * 16 + mt) * (size_t)TILE_B;
    uint32_t off = (uint32_t)(r * 128) + (uint32_t)((c8 ^ (r & 7)) << 4);
    *(uint4*)((char*)Hi + tile + off) = *(uint4*)h8;
    *(uint4*)((char*)Lo + tile + off) = *(uint4*)l8;
}

// ---------------- launch -----------------------------------------------------
extern "C" void kernel_launch(void* const* d_in, const int* in_sizes, int n_in,
                              void* d_out, int out_size) {
    const float* x    = (const float*)d_in[0];
    const int*   mask = (const int*)  d_in[1];
    const float* wq   = (const float*)d_in[2];
    const float* wk   = (const float*)d_in[3];
    const float* wv   = (const float*)d_in[4];
    const float* wo   = (const float*)d_in[5];
    const float* w1   = (const float*)d_in[6];
    const float* w2   = (const float*)d_in[7];
    const float* w3   = (const float*)d_in[8];
    const float* ln1w = (const float*)d_in[9];
    const float* ln1b = (const float*)d_in[10];
    const float* ln2w = (const float*)d_in[11];
    const float* ln2b = (const float*)d_in[12];
    float* out = (float*)d_out;

    float *qkv, *x1;
    cudaGetSymbolAddress((void**)&qkv, g_qkv);
    cudaGetSymbolAddress((void**)&x1,  g_x1);

    __nv_bfloat16 *hhi, *hlo, *chi, *clo, *ghi, *glo, *g13h, *g13l;
    __nv_bfloat16 *wqkvh, *wqkvl, *woh, *wol, *w13h, *w13l, *w2h, *w2l;
    __nv_bfloat16 *qah, *qal, *kah, *kal, *vah, *val_;
    cudaGetSymbolAddress((void**)&hhi, t_h_hi);   cudaGetSymbolAddress((void**)&hlo, t_h_lo);
    cudaGetSymbolAddress((void**)&chi, t_ctx_hi); cudaGetSymbolAddress((void**)&clo, t_ctx_lo);
    cudaGetSymbolAddress((void**)&ghi, t_g_hi);   cudaGetSymbolAddress((void**)&glo, t_g_lo);
    cudaGetSymbolAddress((void**)&g13h, t_g13_hi); cudaGetSymbolAddress((void**)&g13l, t_g13_lo);
    cudaGetSymbolAddress((void**)&wqkvh, t_wqkv_hi); cudaGetSymbolAddress((void**)&wqkvl, t_wqkv_lo);
    cudaGetSymbolAddress((void**)&woh, t_wo_hi);  cudaGetSymbolAddress((void**)&wol, t_wo_lo);
    cudaGetSymbolAddress((void**)&w13h, t_w13_hi); cudaGetSymbolAddress((void**)&w13l, t_w13_lo);
    cudaGetSymbolAddress((void**)&w2h, t_w2_hi);  cudaGetSymbolAddress((void**)&w2l, t_w2_lo);
    cudaGetSymbolAddress((void**)&qah, t_qat_hi); cudaGetSymbolAddress((void**)&qal, t_qat_lo);
    cudaGetSymbolAddress((void**)&kah, t_kat_hi); cudaGetSymbolAddress((void**)&kal, t_kat_lo);
    cudaGetSymbolAddress((void**)&vah, t_vat_hi); cudaGetSymbolAddress((void**)&val_, t_vat_lo);

    cudaFuncSetAttribute(mma_gemm, cudaFuncAttributeMaxDynamicSharedMemorySize, GEMM_SMEM);
    cudaFuncSetAttribute(attn_mma, cudaFuncAttributeMaxDynamicSharedMemorySize, ATT_SMEM);

    // weights -> tiled bf16 hi/lo
    conv_w<<<dim3(D_MODEL / 64, 16), 256>>>(wq, wqkvh, wqkvl, D_MODEL, D_MODEL, 0,  24);
    conv_w<<<dim3(D_MODEL / 64, 4),  256>>>(wk, wqkvh, wqkvl, D_MODEL, 512,     16, 24);
    conv_w<<<dim3(D_MODEL / 64, 4),  256>>>(wv, wqkvh, wqkvl, D_MODEL, 512,     20, 24);
    conv_w<<<dim3(D_MODEL / 64, 16), 256>>>(wo, woh,   wol,   D_MODEL, D_MODEL, 0,  16);
    conv_w<<<dim3(D_MODEL / 64, 44), 256>>>(w1, w13h,  w13l,  D_MODEL, HID,     0,  88);
    conv_w<<<dim3(D_MODEL / 64, 44), 256>>>(w3, w13h,  w13l,  D_MODEL, HID,     44, 88);
    conv_w<<<dim3(HID / 64,     16), 256>>>(w2, w2h,   w2l,   HID,     D_MODEL, 0,  16);

    // h tiles = LN1(x)
    ln_tile<<<S_LEN, 256>>>(x, ln1w, ln1b, hhi, hlo);

    // qkv GEMM: rope Q/K -> attention tiles; V -> fp32
    mma_gemm<<<dim3(QKV_N / 128, S_LEN / 128), 256, GEMM_SMEM>>>(hhi, hlo, wqkvh, wqkvl,
        nullptr, qkv, S_LEN, QKV_N, D_MODEL, 1, qah, qal, kah, kal);

    conv_vt<<<dim3(16, NKV), 256>>>(qkv, vah, val_);

    // attention -> ctx tiles
    attn_mma<<<dim3(S_LEN / 128, NH), 256, ATT_SMEM>>>(qah, qal, kah, kal, vah, val_,
        mask, chi, clo);

    // x1 = x + ctx @ wo (fp32)
    mma_gemm<<<dim3(D_MODEL / 128, S_LEN / 128), 256, GEMM_SMEM>>>(chi, clo, woh, wol,
        x, x1, S_LEN, D_MODEL, D_MODEL, 0, nullptr, nullptr, nullptr, nullptr);

    // h tiles = LN2(x1)
    ln_tile<<<S_LEN, 256>>>(x1, ln2w, ln2b, hhi, hlo);

    // g13 = h @ [w1|w3] -> bf16 hi/lo row-major
    mma_gemm<<<dim3(W13_N / 128, S_LEN / 128), 256, GEMM_SMEM>>>(hhi, hlo, w13h, w13l,
        nullptr, nullptr, S_LEN, W13_N, D_MODEL, 2, g13h, g13l, nullptr, nullptr);

    // gb tiles = silu(g1) * g3
    silu_conv<<<(S_LEN * HID / 8) / 256, 256>>>(g13h, g13l, ghi, glo);

    // out = x1 + gb @ w2
    mma_gemm<<<dim3(D_MODEL / 128, S_LEN / 128), 256, GEMM_SMEM>>>(ghi, glo, w2h, w2l,
        x1, out, S_LEN, D_MODEL, HID, 0, nullptr, nullptr, nullptr, nullptr);
}

// round 10
// speedup vs baseline: 5.2196x; 1.3307x over previous
#include <cuda_runtime.h>
#include <cuda_fp16.h>
#include <cstdint>
#include <math.h>

#define S_LEN   2048
#define D_MODEL 2048
#define HID     5632
#define NH      32
#define NKV     8
#define HD      64
#define QKV_N   3072        // 2048 q | 512 k | 512 v
#define W13_N   11264       // 5632 g1 | 5632 g3
#define TILE_B  16384

// ---------------- fp32 scratch ------------------------------------------------
__device__ __align__(1024) float g_qkv[S_LEN * QKV_N];   // only V cols written/read
__device__ __align__(1024) float g_x1 [S_LEN * D_MODEL];

// ---------------- fp16 scratch ------------------------------------------------
// Activations: hi/lo pairs (corrected operand). Weights / K / V: hi only.
__device__ __align__(1024) __half t_h_hi  [S_LEN * D_MODEL];
__device__ __align__(1024) __half t_h_lo  [S_LEN * D_MODEL];
__device__ __align__(1024) __half t_ctx_hi[S_LEN * D_MODEL];
__device__ __align__(1024) __half t_ctx_lo[S_LEN * D_MODEL];
__device__ __align__(1024) __half t_g_hi  [S_LEN * HID];
__device__ __align__(1024) __half t_g_lo  [S_LEN * HID];
__device__ __align__(1024) __half t_g13_hi[S_LEN * W13_N];   // row-major
__device__ __align__(1024) __half t_g13_lo[S_LEN * W13_N];   // row-major
__device__ __align__(1024) __half t_wqkv_hi[QKV_N * D_MODEL];
__device__ __align__(1024) __half t_wo_hi [D_MODEL * D_MODEL];
__device__ __align__(1024) __half t_w13_hi[W13_N * D_MODEL];
__device__ __align__(1024) __half t_w2_hi [D_MODEL * HID];
__device__ __align__(1024) __half t_qat_hi[NH  * 16 * 8192];
__device__ __align__(1024) __half t_qat_lo[NH  * 16 * 8192];
__device__ __align__(1024) __half t_kat_hi[NKV * 16 * 8192];
__device__ __align__(1024) __half t_vat_hi[NKV * 16 * 8192];

// ---------------- PTX helpers (baseline PTX only) -----------------------------
__device__ __forceinline__ uint32_t smem_u32(const void* p) {
    uint32_t a;
    asm("{ .reg .u64 t; cvta.to.shared.u64 t, %1; cvt.u32.u64 %0, t; }" : "=r"(a) : "l"(p));
    return a;
}
#define MBAR_INIT(a, c) asm volatile("mbarrier.init.shared.b64 [%0], %1;" :: "r"(a), "r"(c) : "memory")
#define MBAR_EXPECT(a, b) asm volatile("mbarrier.arrive.expect_tx.shared.b64 _, [%0], %1;" :: "r"(a), "r"(b) : "memory")
__device__ __forceinline__ void mbar_wait(uint32_t mbar, uint32_t parity) {
    asm volatile(
        "{\n\t.reg .pred P1;\n\t"
        "W_%=:\n\t"
        "mbarrier.try_wait.parity.acquire.cta.shared::cta.b64 P1, [%0], %1, 0x989680;\n\t"
        "@P1 bra.uni D_%=;\n\t"
        "bra.uni W_%=;\n\t"
        "D_%=:\n\t}"
        :: "r"(mbar), "r"(parity) : "memory");
}
__device__ __forceinline__ void bulk_g2s(uint32_t dst, const void* src, uint32_t bytes, uint32_t mbar) {
    asm volatile("cp.async.bulk.shared::cta.global.mbarrier::complete_tx::bytes [%0], [%1], %2, [%3];"
        :: "r"(dst), "l"(src), "r"(bytes), "r"(mbar) : "memory");
}
#define LDSM4(r, a) \
    asm volatile("ldmatrix.sync.aligned.m8n8.x4.shared.b16 {%0,%1,%2,%3}, [%4];" \
        : "=r"((r)[0]), "=r"((r)[1]), "=r"((r)[2]), "=r"((r)[3]) : "r"(a))
#define MMA_F16(d, a, b) \
    asm volatile("mma.sync.aligned.m16n8k16.row.col.f32.f16.f16.f32 " \
        "{%0,%1,%2,%3}, {%4,%5,%6,%7}, {%8,%9}, {%0,%1,%2,%3};" \
        : "+f"((d)[0]), "+f"((d)[1]), "+f"((d)[2]), "+f"((d)[3]) \
        : "r"((a)[0]), "r"((a)[1]), "r"((a)[2]), "r"((a)[3]), "r"((b)[0]), "r"((b)[1]))

__device__ __forceinline__ uint32_t pack_h2(float a, float b) {
    __half2 t = __floats2half2_rn(a, b);
    return *(uint32_t*)&t;
}
__device__ __forceinline__ void split_pair(float v0, float v1, uint32_t& hi, uint32_t& lo) {
    __half h0 = __float2half_rn(v0);
    __half h1 = __float2half_rn(v1);
    hi = pack_h2(v0, v1);
    lo = pack_h2(v0 - __half2float(h0), v1 - __half2float(h1));
}

// ---------------- mma.sync GEMM (4-stage pipeline, 2-pass fp16) --------------
// Tiles per stage: Ah, Al, Bh (3 x 16KB). C = Ah*Bh + Al*Bh.
// mode 0: C fp32 (+R)
// mode 1: qkv — rope Q (hi/lo -> P0/P1), K (hi -> P2); V cols >= 2560 -> C fp32
// mode 2: row-major fp16 hi/lo into P0/P1
__global__ void __launch_bounds__(256, 1) mma_gemm(
    const __half* __restrict__ Ahi, const __half* __restrict__ Alo,
    const __half* __restrict__ Bhi,
    const float* __restrict__ R, float* __restrict__ C, int M, int N, int K, int mode,
    __half* __restrict__ P0, __half* __restrict__ P1, __half* __restrict__ P2)
{
    extern __shared__ char smem[];
    uint32_t sb = smem_u32(smem);
    int tid = threadIdx.x, wid = tid >> 5, ln = tid & 31;
    int wm = wid >> 2, wn = wid & 3;
    int mt = blockIdx.y, nt = blockIdx.x;
    int MT = M >> 7, NT = N >> 7, KTt = K >> 6;
    uint32_t mb0 = sb + 4 * 3 * TILE_B;

    if (tid == 0) {
        MBAR_INIT(mb0, 1); MBAR_INIT(mb0 + 8, 1);
        MBAR_INIT(mb0 + 16, 1); MBAR_INIT(mb0 + 24, 1);
    }
    __syncthreads();

    auto issue = [&](int s, int kt) {
        uint32_t mb = mb0 + s * 8;
        uint32_t dst = sb + s * (3 * TILE_B);
        size_t aoff = ((size_t)kt * MT + mt) * (size_t)(128 * 64);
        size_t boff = ((size_t)kt * NT + nt) * (size_t)(128 * 64);
        MBAR_EXPECT(mb, 3 * TILE_B);
        bulk_g2s(dst,              Ahi + aoff, TILE_B, mb);
        bulk_g2s(dst + TILE_B,     Alo + aoff, TILE_B, mb);
        bulk_g2s(dst + 2 * TILE_B, Bhi + boff, TILE_B, mb);
    };
    if (tid == 0) {
        issue(0, 0);
        if (KTt > 1) issue(1, 1);
        if (KTt > 2) issue(2, 2);
        if (KTt > 3) issue(3, 3);
    }

    float acc[4][4][4];
#pragma unroll
    for (int i = 0; i < 4; i++)
#pragma unroll
        for (int j = 0; j < 4; j++)
#pragma unroll
            for (int r = 0; r < 4; r++) acc[i][j][r] = 0.f;

    int arow0 = wm * 64 + (ln & 7) + ((ln & 8) ? 8 : 0);
    int acgs  = (ln >> 4) & 1;
    int brow0 = wn * 32 + (ln & 7) + ((ln & 16) ? 8 : 0);
    int bcgs  = (ln >> 3) & 1;

    for (int kt = 0; kt < KTt; kt++) {
        int s = kt & 3, ph = (kt >> 2) & 1;
        mbar_wait(mb0 + s * 8, ph);
        uint32_t st = sb + s * (3 * TILE_B);
        uint32_t Ah = st, Al = st + TILE_B, Bh = st + 2 * TILE_B;
#pragma unroll
        for (int ks = 0; ks < 4; ks++) {
            int acg = ks * 2 + acgs;
            int bcg = ks * 2 + bcgs;
            uint32_t ahr[16], alr[16], bhr[8];
#pragma unroll
            for (int fm = 0; fm < 4; fm++) {
                int row = arow0 + fm * 16;
                uint32_t off = (uint32_t)(row * 128) + (uint32_t)((acg ^ (row & 7)) << 4);
                LDSM4(ahr + fm * 4, Ah + off);
                LDSM4(alr + fm * 4, Al + off);
            }
#pragma unroll
            for (int pr = 0; pr < 2; pr++) {
                int row = brow0 + pr * 16;
                uint32_t off = (uint32_t)(row * 128) + (uint32_t)((bcg ^ (row & 7)) << 4);
                LDSM4(bhr + pr * 4, Bh + off);
            }
#pragma unroll
            for (int fm = 0; fm < 4; fm++)
#pragma unroll
                for (int fn = 0; fn < 4; fn++) {
                    MMA_F16(acc[fm][fn], ahr + fm * 4, bhr + fn * 2);
                    MMA_F16(acc[fm][fn], alr + fm * 4, bhr + fn * 2);
                }
        }
        __syncthreads();
        if (tid == 0 && kt + 4 < KTt) issue(s, kt + 4);
    }

    int qr = ln >> 2, qc = ln & 3;
#pragma unroll
    for (int fm = 0; fm < 4; fm++) {
        int row0 = mt * 128 + wm * 64 + fm * 16 + qr;
#pragma unroll
        for (int fn = 0; fn < 4; fn++) {
            int col = nt * 128 + wn * 32 + fn * 8 + 2 * qc;
            if (mode == 0) {
                size_t i0 = (size_t)row0 * N + col;
                size_t i1 = (size_t)(row0 + 8) * N + col;
                float2 v0 = make_float2(acc[fm][fn][0], acc[fm][fn][1]);
                float2 v1 = make_float2(acc[fm][fn][2], acc[fm][fn][3]);
                if (R) {
                    float2 r0 = *(const float2*)&R[i0];
                    float2 r1 = *(const float2*)&R[i1];
                    v0.x += r0.x; v0.y += r0.y; v1.x += r1.x; v1.y += r1.y;
                }
                *(float2*)&C[i0] = v0;
                *(float2*)&C[i1] = v1;
            } else if (mode == 2) {
                uint32_t h0, l0, h1, l1;
                split_pair(acc[fm][fn][0], acc[fm][fn][1], h0, l0);
                split_pair(acc[fm][fn][2], acc[fm][fn][3], h1, l1);
                size_t i0 = ((size_t)row0 * N + col) >> 1;
                size_t i1 = ((size_t)(row0 + 8) * N + col) >> 1;
                ((uint32_t*)P0)[i0] = h0; ((uint32_t*)P1)[i0] = l0;
                ((uint32_t*)P0)[i1] = h1; ((uint32_t*)P1)[i1] = l1;
            } else {   // mode 1: qkv
                if (col >= 2560) {
                    size_t i0 = (size_t)row0 * N + col;
                    size_t i1 = (size_t)(row0 + 8) * N + col;
                    *(float2*)&C[i0] = make_float2(acc[fm][fn][0], acc[fm][fn][1]);
                    *(float2*)&C[i1] = make_float2(acc[fm][fn][2], acc[fm][fn][3]);
                } else {
                    int i = (col & 63) >> 1;
                    float freq = 1.0f / powf(10000.0f, (2.0f * (float)i) / 64.0f);
                    int isq = (col < 2048);
                    int head = isq ? (col >> 6) : ((col - 2048) >> 6);
                    __half* Hp = isq ? P0 : P2;
                    __half* Lp = P1;
                    int c8 = (col & 63) >> 3;
                    uint32_t inoff = (uint32_t)((col & 7) * 2);
#pragma unroll
                    for (int rr = 0; rr < 2; rr++) {
                        int row = row0 + rr * 8;
                        float v0 = acc[fm][fn][rr * 2], v1 = acc[fm][fn][rr * 2 + 1];
                        float sn, cs; sincosf((float)row * freq, &sn, &cs);
                        float orr = v0 * cs - v1 * sn;
                        float oii = v0 * sn + v1 * cs;
                        uint32_t hi, lo;
                        split_pair(orr, oii, hi, lo);
                        int r = row & 127;
                        size_t tile = ((size_t)head * 16 + (row >> 7)) * (size_t)TILE_B;
                        uint32_t off = (uint32_t)(r * 128) + (uint32_t)((c8 ^ (r & 7)) << 4) + inoff;
                        *(uint32_t*)((char*)Hp + tile + off) = hi;
                        if (isq) *(uint32_t*)((char*)Lp + tile + off) = lo;
                    }
                }
            }
        }
    }
}
#define GEMM_SMEM (4 * 3 * TILE_B + 64)

// ---------------- tensorized flash attention (2-pass fp16) -------------------
// Q hi/lo resident in smem; K/V single fp16, 4-stage pipeline (32KB/stage).
#define ATT_SQ    0u
#define ATT_SMSK  32768u
#define ATT_SST   40960u
#define ATT_MB    (40960u + 131072u)
#define ATT_SMEM  (40960 + 131072 + 64)
__global__ void __launch_bounds__(256, 1) attn_mma(
    const __half* __restrict__ Qhi, const __half* __restrict__ Qlo,
    const __half* __restrict__ Khi, const __half* __restrict__ Vhi,
    const int* __restrict__ mask,
    __half* __restrict__ Chi, __half* __restrict__ Clo)
{
    extern __shared__ char smem[];
    uint32_t sb = smem_u32(smem);
    int tid = threadIdx.x, wid = tid >> 5, ln = tid & 31;
    int qb = blockIdx.x, h = blockIdx.y;
    int kvh = h >> 2;
    int q2 = (ln & 3) * 2;

    int* msk = (int*)(smem + ATT_SMSK);
    for (int i = tid; i < S_LEN; i += 256) msk[i] = mask[i];
    {
        const uint4* qs0 = (const uint4*)(Qhi + ((size_t)h * 16 + qb) * 8192);
        const uint4* qs1 = (const uint4*)(Qlo + ((size_t)h * 16 + qb) * 8192);
        uint4* qd0 = (uint4*)(smem + ATT_SQ);
        uint4* qd1 = (uint4*)(smem + ATT_SQ + 16384);
        for (int i = tid; i < 1024; i += 256) { qd0[i] = qs0[i]; qd1[i] = qs1[i]; }
    }
    uint32_t mb0 = sb + ATT_MB;
    if (tid == 0) {
        MBAR_INIT(mb0, 1); MBAR_INIT(mb0 + 8, 1);
        MBAR_INIT(mb0 + 16, 1); MBAR_INIT(mb0 + 24, 1);
    }
    __syncthreads();

    auto issue = [&](int s, int kb) {
        uint32_t mb = mb0 + s * 8;
        uint32_t dst = sb + ATT_SST + s * 32768;
        size_t ko = ((size_t)kvh * 16 + kb) * 8192;
        MBAR_EXPECT(mb, 32768);
        bulk_g2s(dst,         Khi + ko, 16384, mb);
        bulk_g2s(dst + 16384, Vhi + ko, 16384, mb);
    };
    if (tid == 0) { issue(0, 0); issue(1, 1); issue(2, 2); issue(3, 3); }

    uint32_t qh[4][4], qlr[4][4];
    {
        int arow0 = wid * 16 + (ln & 7) + ((ln & 8) ? 8 : 0);
        int acgs = (ln >> 4) & 1;
#pragma unroll
        for (int ks = 0; ks < 4; ks++) {
            int cg = ks * 2 + acgs;
            uint32_t off = (uint32_t)(arow0 * 128) + (uint32_t)((cg ^ (arow0 & 7)) << 4);
            LDSM4(qh[ks],  sb + ATT_SQ + off);
            LDSM4(qlr[ks], sb + ATT_SQ + 16384 + off);
        }
    }

    float mrow0 = -INFINITY, mrow1 = -INFINITY, lrow0 = 0.f, lrow1 = 0.f;
    float cacc[8][4];
#pragma unroll
    for (int j = 0; j < 8; j++)
#pragma unroll
        for (int r = 0; r < 4; r++) cacc[j][r] = 0.f;

    int brow_b = (ln & 7) + ((ln & 16) ? 8 : 0);
    int bcgs = (ln >> 3) & 1;

    for (int kb = 0; kb < 16; kb++) {
        int s = kb & 3, ph = (kb >> 2) & 1;
        mbar_wait(mb0 + s * 8, ph);
        uint32_t st = sb + ATT_SST + s * 32768;
        uint32_t Kh = st, Vh = st + 16384;

        float sacc[16][4];
#pragma unroll
        for (int j = 0; j < 16; j++)
#pragma unroll
            for (int r = 0; r < 4; r++) sacc[j][r] = 0.f;
#pragma unroll
        for (int nj = 0; nj < 4; nj++) {
#pragma unroll
            for (int ks = 0; ks < 4; ks++) {
                uint32_t bh[8];
                int cg = ks * 2 + bcgs;
#pragma unroll
                for (int pr = 0; pr < 2; pr++) {
                    int row = nj * 32 + pr * 16 + brow_b;
                    uint32_t off = (uint32_t)(row * 128) + (uint32_t)((cg ^ (row & 7)) << 4);
                    LDSM4(bh + pr * 4, Kh + off);
                }
#pragma unroll
                for (int nt = 0; nt < 4; nt++) {
                    float* d = sacc[nj * 4 + nt];
                    uint32_t* rh = bh + (nt >> 1) * 4 + (nt & 1) * 2;
                    MMA_F16(d, qh[ks], rh);
                    MMA_F16(d, qlr[ks], rh);
                }
            }
        }
        float tmax0 = -INFINITY, tmax1 = -INFINITY;
#pragma unroll
        for (int j = 0; j < 16; j++) {
            int c = kb * 128 + 8 * j + q2;
            sacc[j][0] = msk[c]     ? sacc[j][0] * 0.125f : -1e30f;
            sacc[j][1] = msk[c + 1] ? sacc[j][1] * 0.125f : -1e30f;
            sacc[j][2] = msk[c]     ? sacc[j][2] * 0.125f : -1e30f;
            sacc[j][3] = msk[c + 1] ? sacc[j][3] * 0.125f : -1e30f;
            tmax0 = fmaxf(tmax0, fmaxf(sacc[j][0], sacc[j][1]));
            tmax1 = fmaxf(tmax1, fmaxf(sacc[j][2], sacc[j][3]));
        }
        tmax0 = fmaxf(tmax0, __shfl_xor_sync(0xffffffffu, tmax0, 1));
        tmax0 = fmaxf(tmax0, __shfl_xor_sync(0xffffffffu, tmax0, 2));
        tmax1 = fmaxf(tmax1, __shfl_xor_sync(0xffffffffu, tmax1, 1));
        tmax1 = fmaxf(tmax1, __shfl_xor_sync(0xffffffffu, tmax1, 2));
        float mnew0 = fmaxf(mrow0, tmax0);
        float mnew1 = fmaxf(mrow1, tmax1);
        float alpha0 = (mrow0 == -INFINITY) ? 0.f : __expf(mrow0 - mnew0);
        float alpha1 = (mrow1 == -INFINITY) ? 0.f : __expf(mrow1 - mnew1);
        float rs0 = 0.f, rs1 = 0.f;
#pragma unroll
        for (int j = 0; j < 16; j++) {
            float p0 = __expf(sacc[j][0] - mnew0);
            float p1 = __expf(sacc[j][1] - mnew0);
            float p2 = __expf(sacc[j][2] - mnew1);
            float p3 = __expf(sacc[j][3] - mnew1);
            rs0 += p0 + p1; rs1 += p2 + p3;
            sacc[j][0] = p0; sacc[j][1] = p1; sacc[j][2] = p2; sacc[j][3] = p3;
        }
        rs0 += __shfl_xor_sync(0xffffffffu, rs0, 1);
        rs0 += __shfl_xor_sync(0xffffffffu, rs0, 2);
        rs1 += __shfl_xor_sync(0xffffffffu, rs1, 1);
        rs1 += __shfl_xor_sync(0xffffffffu, rs1, 2);
        lrow0 = lrow0 * alpha0 + rs0;
        lrow1 = lrow1 * alpha1 + rs1;
        mrow0 = mnew0; mrow1 = mnew1;
#pragma unroll
        for (int j = 0; j < 8; j++) {
            cacc[j][0] *= alpha0; cacc[j][1] *= alpha0;
            cacc[j][2] *= alpha1; cacc[j][3] *= alpha1;
        }
#pragma unroll
        for (int t = 0; t < 8; t++) {
            uint32_t pah[4], pal[4];
            {
                float* s0 = sacc[2 * t]; float* s1 = sacc[2 * t + 1];
                split_pair(s0[0], s0[1], pah[0], pal[0]);
                split_pair(s0[2], s0[3], pah[1], pal[1]);
                split_pair(s1[0], s1[1], pah[2], pal[2]);
                split_pair(s1[2], s1[3], pah[3], pal[3]);
            }
            uint32_t vbh[16];
            int sub = t >> 2;
            int cgv = (t & 3) * 2 + bcgs;
#pragma unroll
            for (int prd = 0; prd < 4; prd++) {
                int row = prd * 16 + brow_b;
                uint32_t off = (uint32_t)(sub * 8192) + (uint32_t)(row * 128) +
                               (uint32_t)((cgv ^ (row & 7)) << 4);
                LDSM4(vbh + prd * 4, Vh + off);
            }
#pragma unroll
            for (int jd = 0; jd < 8; jd++) {
                uint32_t* rh = vbh + (jd >> 1) * 4 + (jd & 1) * 2;
                MMA_F16(cacc[jd], pah, rh);
                MMA_F16(cacc[jd], pal, rh);
            }
        }
        __syncthreads();
        if (tid == 0 && kb + 4 < 16) issue(s, kb + 4);
    }
    // epilogue -> ctx tiles (hi/lo, A-side of wo GEMM)
    float inv0 = (lrow0 > 0.f) ? (1.f / lrow0) : 0.f;
    float inv1 = (lrow1 > 0.f) ? (1.f / lrow1) : 0.f;
    int r0 = wid * 16 + (ln >> 2);
    size_t tile = ((size_t)h * 16 + qb) * (size_t)TILE_B;
#pragma unroll
    for (int jd = 0; jd < 8; jd++) {
        uint32_t inoff = (uint32_t)(q2 * 2);
#pragma unroll
        for (int rr = 0; rr < 2; rr++) {
            int r = r0 + rr * 8;
            float v0 = cacc[jd][rr * 2] * (rr ? inv1 : inv0);
            float v1 = cacc[jd][rr * 2 + 1] * (rr ? inv1 : inv0);
            uint32_t hi, lo;
            split_pair(v0, v1, hi, lo);
            uint32_t off = (uint32_t)(r * 128) + (uint32_t)((jd ^ (r & 7)) << 4) + inoff;
            *(uint32_t*)((char*)Chi + tile + off) = hi;
            *(uint32_t*)((char*)Clo + tile + off) = lo;
        }
    }
}

// ---------------- LayerNorm -> tiled fp16 hi/lo directly ----------------------
__global__ void ln_tile(const float* __restrict__ x, const float* __restrict__ w,
                        const float* __restrict__ b,
                        __half* __restrict__ Hi, __half* __restrict__ Lo) {
    int row = blockIdx.x;
    int tid = threadIdx.x;
    const float* xr = x + (size_t)row * D_MODEL;
    float4 v0 = *(const float4*)&xr[tid * 8];
    float4 v1 = *(const float4*)&xr[tid * 8 + 4];
    float xin[8] = {v0.x, v0.y, v0.z, v0.w, v1.x, v1.y, v1.z, v1.w};
    float s = 0.f, s2 = 0.f;
#pragma unroll
    for (int u = 0; u < 8; u++) { s += xin[u]; s2 += xin[u] * xin[u]; }
    __shared__ float r0s[256], r1s[256];
    r0s[tid] = s; r1s[tid] = s2;
    __syncthreads();
    for (int o = 128; o > 0; o >>= 1) {
        if (tid < o) { r0s[tid] += r0s[tid + o]; r1s[tid] += r1s[tid + o]; }
        __syncthreads();
    }
    float mean = r0s[0] * (1.0f / D_MODEL);
    float var  = r1s[0] * (1.0f / D_MODEL) - mean * mean;
    float inv  = rsqrtf(var + 1e-5f);
    int kt = tid >> 3, c8 = tid & 7;
    int mt = row >> 7, r = row & 127;
    size_t tile = ((size_t)kt * 16 + mt) * (size_t)TILE_B;
    uint32_t off = (uint32_t)(r * 128) + (uint32_t)((c8 ^ (r & 7)) << 4);
    __half h8[8], l8[8];
#pragma unroll
    for (int u = 0; u < 8; u++) {
        float vv = (xin[u] - mean) * inv * w[tid * 8 + u] + b[tid * 8 + u];
        __half hh = __float2half_rn(vv);
        h8[u] = hh;
        l8[u] = __float2half_rn(vv - __half2float(hh));
    }
    *(uint4*)((char*)Hi + tile + off) = *(uint4*)h8;
    *(uint4*)((char*)Lo + tile + off) = *(uint4*)l8;
}

// ---------------- V fp32 -> transposed fp16 tiles [64 d][128 keys] -----------
__global__ void conv_vt(const float* __restrict__ src, __half* __restrict__ Hi) {
    __shared__ float s[128][65];
    int sbk = blockIdx.x, kvh = blockIdx.y;
    int tid = threadIdx.x;
    for (int t = tid; t < 128 * 16; t += 256) {
        int r = t >> 4, c4 = (t & 15) * 4;
        float4 v = *(const float4*)&src[(size_t)(sbk * 128 + r) * QKV_N + 2560 + kvh * 64 + c4];
        s[r][c4] = v.x; s[r][c4 + 1] = v.y; s[r][c4 + 2] = v.z; s[r][c4 + 3] = v.w;
    }
    __syncthreads();
    size_t tile = ((size_t)kvh * 16 + sbk) * (size_t)TILE_B;
    for (int t = tid; t < 1024; t += 256) {
        int d = t >> 4, kc8 = t & 15;
        int sub = kc8 >> 3, c8 = kc8 & 7;
        __half h8[8];
#pragma unroll
        for (int u = 0; u < 8; u++)
            h8[u] = __float2half_rn(s[(kc8 & 7) * 8 + sub * 64 + u][d]);
        uint32_t off = (uint32_t)(sub * 8192) + (uint32_t)(d * 128) +
                       (uint32_t)((c8 ^ (d & 7)) << 4);
        *(uint4*)((char*)Hi + tile + off) = *(uint4*)h8;
    }
}

// ---------------- fp32 weight [K,N] -> tiled transposed fp16 (hi only) -------
__global__ void conv_w(const float* __restrict__ W, __half* __restrict__ Hi,
                       int K, int Nsrc, int nt_off, int NT_total) {
    __shared__ float s[128][65];
    int kt = blockIdx.x, nt = blockIdx.y;
    int tid = threadIdx.x;
    for (int t = tid; t < 64 * 32; t += 256) {
        int i = t >> 5, j4 = (t & 31) * 4;
        float4 v = *(const float4*)&W[((size_t)kt * 64 + i) * Nsrc + (size_t)nt * 128 + j4];
        s[j4 + 0][i] = v.x; s[j4 + 1][i] = v.y; s[j4 + 2][i] = v.z; s[j4 + 3][i] = v.w;
    }
    __syncthreads();
    size_t tile = ((size_t)kt * NT_total + (nt_off + nt)) * TILE_B;
    for (int t = tid; t < 1024; t += 256) {
        int r = t >> 3, c8 = t & 7;
        __half h8[8];
#pragma unroll
        for (int u = 0; u < 8; u++)
            h8[u] = __float2half_rn(s[r][c8 * 8 + u]);
        uint32_t off = (uint32_t)(r * 128) + (uint32_t)((c8 ^ (r & 7)) << 4);
        *(uint4*)((char*)Hi + tile + off) = *(uint4*)h8;
    }
}

// ---------------- silu(g1)*g3 from fp16 hi/lo -> gb tiles --------------------
__global__ void silu_conv(const __half* __restrict__ Gh, const __half* __restrict__ Gl,
                          __half* __restrict__ Hi, __half* __restrict__ Lo) {
    int idx = blockIdx.x * blockDim.x + threadIdx.x;   // chunk of 8
    int cpr = HID / 8;                                 // 704
    int m = idx / cpr, ck = idx % cpr;
    size_t base1 = (size_t)m * W13_N + ck * 8;
    size_t base3 = base1 + HID;
    uint4 g1h4 = *(const uint4*)&Gh[base1];
    uint4 g1l4 = *(const uint4*)&Gl[base1];
    uint4 g3h4 = *(const uint4*)&Gh[base3];
    uint4 g3l4 = *(const uint4*)&Gl[base3];
    const __half* g1h = (const __half*)&g1h4;
    const __half* g1l = (const __half*)&g1l4;
    const __half* g3h = (const __half*)&g3h4;
    const __half* g3l = (const __half*)&g3l4;
    __half h8[8], l8[8];
#pragma unroll
    for (int u = 0; u < 8; u++) {
        float a = __half2float(g1h[u]) + __half2float(g1l[u]);
        float c = __half2float(g3h[u]) + __half2float(g3l[u]);
        float sig = 1.0f / (1.0f + expf(-a));
        float vv = a * sig * c;
        __half hh = __float2half_rn(vv);
        h8[u] = hh;
        l8[u] = __float2half_rn(vv - __half2float(hh));
    }
    int kt = ck >> 3, c8 = ck & 7;
    int mt = m >> 7, r = m & 127;
    size_t tile = ((size_t)kt * 16 + mt) * (size_t)TILE_B;
    uint32_t off = (uint32_t)(r * 128) + (uint32_t)((c8 ^ (r & 7)) << 4);
    *(uint4*)((char*)Hi + tile + off) = *(uint4*)h8;
    *(uint4*)((char*)Lo + tile + off) = *(uint4*)l8;
}

// ---------------- launch -----------------------------------------------------
extern "C" void kernel_launch(void* const* d_in, const int* in_sizes, int n_in,
                              void* d_out, int out_size) {
    const float* x    = (const float*)d_in[0];
    const int*   mask = (const int*)  d_in[1];
    const float* wq   = (const float*)d_in[2];
    const float* wk   = (const float*)d_in[3];
    const float* wv   = (const float*)d_in[4];
    const float* wo   = (const float*)d_in[5];
    const float* w1   = (const float*)d_in[6];
    const float* w2   = (const float*)d_in[7];
    const float* w3   = (const float*)d_in[8];
    const float* ln1w = (const float*)d_in[9];
    const float* ln1b = (const float*)d_in[10];
    const float* ln2w = (const float*)d_in[11];
    const float* ln2b = (const float*)d_in[12];
    float* out = (float*)d_out;

    float *qkv, *x1;
    cudaGetSymbolAddress((void**)&qkv, g_qkv);
    cudaGetSymbolAddress((void**)&x1,  g_x1);

    __half *hhi, *hlo, *chi, *clo, *ghi, *glo, *g13h, *g13l;
    __half *wqkvh, *woh, *w13h, *w2h;
    __half *qah, *qal, *kah, *vah;
    cudaGetSymbolAddress((void**)&hhi, t_h_hi);   cudaGetSymbolAddress((void**)&hlo, t_h_lo);
    cudaGetSymbolAddress((void**)&chi, t_ctx_hi); cudaGetSymbolAddress((void**)&clo, t_ctx_lo);
    cudaGetSymbolAddress((void**)&ghi, t_g_hi);   cudaGetSymbolAddress((void**)&glo, t_g_lo);
    cudaGetSymbolAddress((void**)&g13h, t_g13_hi); cudaGetSymbolAddress((void**)&g13l, t_g13_lo);
    cudaGetSymbolAddress((void**)&wqkvh, t_wqkv_hi);
    cudaGetSymbolAddress((void**)&woh, t_wo_hi);
    cudaGetSymbolAddress((void**)&w13h, t_w13_hi);
    cudaGetSymbolAddress((void**)&w2h, t_w2_hi);
    cudaGetSymbolAddress((void**)&qah, t_qat_hi); cudaGetSymbolAddress((void**)&qal, t_qat_lo);
    cudaGetSymbolAddress((void**)&kah, t_kat_hi);
    cudaGetSymbolAddress((void**)&vah, t_vat_hi);

    cudaFuncSetAttribute(mma_gemm, cudaFuncAttributeMaxDynamicSharedMemorySize, GEMM_SMEM);
    cudaFuncSetAttribute(attn_mma, cudaFuncAttributeMaxDynamicSharedMemorySize, ATT_SMEM);

    // weights -> tiled fp16 (hi only)
    conv_w<<<dim3(D_MODEL / 64, 16), 256>>>(wq, wqkvh, D_MODEL, D_MODEL, 0,  24);
    conv_w<<<dim3(D_MODEL / 64, 4),  256>>>(wk, wqkvh, D_MODEL, 512,     16, 24);
    conv_w<<<dim3(D_MODEL / 64, 4),  256>>>(wv, wqkvh, D_MODEL, 512,     20, 24);
    conv_w<<<dim3(D_MODEL / 64, 16), 256>>>(wo, woh,   D_MODEL, D_MODEL, 0,  16);
    conv_w<<<dim3(D_MODEL / 64, 44), 256>>>(w1, w13h,  D_MODEL, HID,     0,  88);
    conv_w<<<dim3(D_MODEL / 64, 44), 256>>>(w3, w13h,  D_MODEL, HID,     44, 88);
    conv_w<<<dim3(HID / 64,     16), 256>>>(w2, w2h,   HID,     D_MODEL, 0,  16);

    // h tiles = LN1(x)
    ln_tile<<<S_LEN, 256>>>(x, ln1w, ln1b, hhi, hlo);

    // qkv GEMM: rope Q/K -> attention tiles; V -> fp32
    mma_gemm<<<dim3(QKV_N / 128, S_LEN / 128), 256, GEMM_SMEM>>>(hhi, hlo, wqkvh,
        nullptr, qkv, S_LEN, QKV_N, D_MODEL, 1, qah, qal, kah);

    conv_vt<<<dim3(16, NKV), 256>>>(qkv, vah);

    // attention -> ctx tiles
    attn_mma<<<dim3(S_LEN / 128, NH), 256, ATT_SMEM>>>(qah, qal, kah, vah,
        mask, chi, clo);

    // x1 = x + ctx @ wo (fp32)
    mma_gemm<<<dim3(D_MODEL / 128, S_LEN / 128), 256, GEMM_SMEM>>>(chi, clo, woh,
        x, x1, S_LEN, D_MODEL, D_MODEL, 0, nullptr, nullptr, nullptr);

    // h tiles = LN2(x1)
    ln_tile<<<S_LEN, 256>>>(x1, ln2w, ln2b, hhi, hlo);

    // g13 = h @ [w1|w3] -> fp16 hi/lo row-major
    mma_gemm<<<dim3(W13_N / 128, S_LEN / 128), 256, GEMM_SMEM>>>(hhi, hlo, w13h,
        nullptr, nullptr, S_LEN, W13_N, D_MODEL, 2, g13h, g13l, nullptr);

    // gb tiles = silu(g1) * g3
    silu_conv<<<(S_LEN * HID / 8) / 256, 256>>>(g13h, g13l, ghi, glo);

    // out = x1 + gb @ w2
    mma_gemm<<<dim3(D_MODEL / 128, S_LEN / 128), 256, GEMM_SMEM>>>(ghi, glo, w2h,
        x1, out, S_LEN, D_MODEL, HID, 0, nullptr, nullptr, nullptr);
}

// round 12
// speedup vs baseline: 8.3761x; 1.6047x over previous
#include <cuda_runtime.h>
#include <cuda_fp16.h>
#include <cstdint>
#include <math.h>

#define S_LEN   2048
#define D_MODEL 2048
#define HID     5632
#define NH      32
#define NKV     8
#define HD      64
#define QKV_N   3072        // 2048 q | 512 k | 512 v
#define W13_N   11264       // 5632 g1 | 5632 g3
#define TILE_B  16384

// ---------------- fp32 scratch ------------------------------------------------
__device__ __align__(1024) float g_qkv[S_LEN * QKV_N];   // only V cols written/read
__device__ __align__(1024) float g_x1 [S_LEN * D_MODEL];

// ---------------- fp16 scratch (all single precision-level, hi only) ----------
__device__ __align__(1024) __half t_h_hi  [S_LEN * D_MODEL];
__device__ __align__(1024) __half t_ctx_hi[S_LEN * D_MODEL];
__device__ __align__(1024) __half t_g_hi  [S_LEN * HID];
__device__ __align__(1024) __half t_g13_hi[S_LEN * W13_N];   // row-major
__device__ __align__(1024) __half t_wqkv_hi[QKV_N * D_MODEL];
__device__ __align__(1024) __half t_wo_hi [D_MODEL * D_MODEL];
__device__ __align__(1024) __half t_w13_hi[W13_N * D_MODEL];
__device__ __align__(1024) __half t_w2_hi [D_MODEL * HID];
__device__ __align__(1024) __half t_qat_hi[NH  * 16 * 8192];
__device__ __align__(1024) __half t_kat_hi[NKV * 16 * 8192];
__device__ __align__(1024) __half t_vat_hi[NKV * 16 * 8192];

// ---------------- PTX helpers (baseline PTX only) -----------------------------
__device__ __forceinline__ uint32_t smem_u32(const void* p) {
    uint32_t a;
    asm("{ .reg .u64 t; cvta.to.shared.u64 t, %1; cvt.u32.u64 %0, t; }" : "=r"(a) : "l"(p));
    return a;
}
#define MBAR_INIT(a, c) asm volatile("mbarrier.init.shared.b64 [%0], %1;" :: "r"(a), "r"(c) : "memory")
#define MBAR_EXPECT(a, b) asm volatile("mbarrier.arrive.expect_tx.shared.b64 _, [%0], %1;" :: "r"(a), "r"(b) : "memory")
__device__ __forceinline__ void mbar_wait(uint32_t mbar, uint32_t parity) {
    asm volatile(
        "{\n\t.reg .pred P1;\n\t"
        "W_%=:\n\t"
        "mbarrier.try_wait.parity.acquire.cta.shared::cta.b64 P1, [%0], %1, 0x989680;\n\t"
        "@P1 bra.uni D_%=;\n\t"
        "bra.uni W_%=;\n\t"
        "D_%=:\n\t}"
        :: "r"(mbar), "r"(parity) : "memory");
}
__device__ __forceinline__ void bulk_g2s(uint32_t dst, const void* src, uint32_t bytes, uint32_t mbar) {
    asm volatile("cp.async.bulk.shared::cta.global.mbarrier::complete_tx::bytes [%0], [%1], %2, [%3];"
        :: "r"(dst), "l"(src), "r"(bytes), "r"(mbar) : "memory");
}
#define LDSM4(r, a) \
    asm volatile("ldmatrix.sync.aligned.m8n8.x4.shared.b16 {%0,%1,%2,%3}, [%4];" \
        : "=r"((r)[0]), "=r"((r)[1]), "=r"((r)[2]), "=r"((r)[3]) : "r"(a))
#define MMA_F16(d, a, b) \
    asm volatile("mma.sync.aligned.m16n8k16.row.col.f32.f16.f16.f32 " \
        "{%0,%1,%2,%3}, {%4,%5,%6,%7}, {%8,%9}, {%0,%1,%2,%3};" \
        : "+f"((d)[0]), "+f"((d)[1]), "+f"((d)[2]), "+f"((d)[3]) \
        : "r"((a)[0]), "r"((a)[1]), "r"((a)[2]), "r"((a)[3]), "r"((b)[0]), "r"((b)[1]))

__device__ __forceinline__ uint32_t pack_h2(float a, float b) {
    __half2 t = __floats2half2_rn(a, b);
    return *(uint32_t*)&t;
}

// ---------------- mma.sync GEMM (4-stage pipeline, single-pass fp16) ---------
// Tiles per stage: Ah, Bh (2 x 16KB). C = Ah*Bh.
// mode 0: C fp32 (+R)
// mode 1: qkv — rope Q (-> PQ), K (-> PK); V cols >= 2560 -> C fp32
// mode 2: row-major fp16 into PQ
__global__ void __launch_bounds__(256, 1) mma_gemm(
    const __half* __restrict__ Ahi, const __half* __restrict__ Bhi,
    const float* __restrict__ R, float* __restrict__ C, int M, int N, int K, int mode,
    __half* __restrict__ PQ, __half* __restrict__ PK)
{
    extern __shared__ char smem[];
    uint32_t sb = smem_u32(smem);
    int tid = threadIdx.x, wid = tid >> 5, ln = tid & 31;
    int wm = wid >> 2, wn = wid & 3;
    int mt = blockIdx.y, nt = blockIdx.x;
    int MT = M >> 7, NT = N >> 7, KTt = K >> 6;
    uint32_t mb0 = sb + 4 * 2 * TILE_B;

    if (tid == 0) {
        MBAR_INIT(mb0, 1); MBAR_INIT(mb0 + 8, 1);
        MBAR_INIT(mb0 + 16, 1); MBAR_INIT(mb0 + 24, 1);
    }
    __syncthreads();

    auto issue = [&](int s, int kt) {
        uint32_t mb = mb0 + s * 8;
        uint32_t dst = sb + s * (2 * TILE_B);
        size_t aoff = ((size_t)kt * MT + mt) * (size_t)(128 * 64);
        size_t boff = ((size_t)kt * NT + nt) * (size_t)(128 * 64);
        MBAR_EXPECT(mb, 2 * TILE_B);
        bulk_g2s(dst,          Ahi + aoff, TILE_B, mb);
        bulk_g2s(dst + TILE_B, Bhi + boff, TILE_B, mb);
    };
    if (tid == 0) {
        issue(0, 0);
        if (KTt > 1) issue(1, 1);
        if (KTt > 2) issue(2, 2);
        if (KTt > 3) issue(3, 3);
    }

    float acc[4][4][4];
#pragma unroll
    for (int i = 0; i < 4; i++)
#pragma unroll
        for (int j = 0; j < 4; j++)
#pragma unroll
            for (int r = 0; r < 4; r++) acc[i][j][r] = 0.f;

    int arow0 = wm * 64 + (ln & 7) + ((ln & 8) ? 8 : 0);
    int acgs  = (ln >> 4) & 1;
    int brow0 = wn * 32 + (ln & 7) + ((ln & 16) ? 8 : 0);
    int bcgs  = (ln >> 3) & 1;

    for (int kt = 0; kt < KTt; kt++) {
        int s = kt & 3, ph = (kt >> 2) & 1;
        mbar_wait(mb0 + s * 8, ph);
        uint32_t st = sb + s * (2 * TILE_B);
        uint32_t Ah = st, Bh = st + TILE_B;
#pragma unroll
        for (int ks = 0; ks < 4; ks++) {
            int acg = ks * 2 + acgs;
            int bcg = ks * 2 + bcgs;
            uint32_t ahr[16], bhr[8];
#pragma unroll
            for (int fm = 0; fm < 4; fm++) {
                int row = arow0 + fm * 16;
                uint32_t off = (uint32_t)(row * 128) + (uint32_t)((acg ^ (row & 7)) << 4);
                LDSM4(ahr + fm * 4, Ah + off);
            }
#pragma unroll
            for (int pr = 0; pr < 2; pr++) {
                int row = brow0 + pr * 16;
                uint32_t off = (uint32_t)(row * 128) + (uint32_t)((bcg ^ (row & 7)) << 4);
                LDSM4(bhr + pr * 4, Bh + off);
            }
#pragma unroll
            for (int fm = 0; fm < 4; fm++)
#pragma unroll
                for (int fn = 0; fn < 4; fn++)
                    MMA_F16(acc[fm][fn], ahr + fm * 4, bhr + fn * 2);
        }
        __syncthreads();
        if (tid == 0 && kt + 4 < KTt) issue(s, kt + 4);
    }

    int qr = ln >> 2, qc = ln & 3;
#pragma unroll
    for (int fm = 0; fm < 4; fm++) {
        int row0 = mt * 128 + wm * 64 + fm * 16 + qr;
#pragma unroll
        for (int fn = 0; fn < 4; fn++) {
            int col = nt * 128 + wn * 32 + fn * 8 + 2 * qc;
            if (mode == 0) {
                size_t i0 = (size_t)row0 * N + col;
                size_t i1 = (size_t)(row0 + 8) * N + col;
                float2 v0 = make_float2(acc[fm][fn][0], acc[fm][fn][1]);
                float2 v1 = make_float2(acc[fm][fn][2], acc[fm][fn][3]);
                if (R) {
                    float2 r0 = *(const float2*)&R[i0];
                    float2 r1 = *(const float2*)&R[i1];
                    v0.x += r0.x; v0.y += r0.y; v1.x += r1.x; v1.y += r1.y;
                }
                *(float2*)&C[i0] = v0;
                *(float2*)&C[i1] = v1;
            } else if (mode == 2) {
                size_t i0 = ((size_t)row0 * N + col) >> 1;
                size_t i1 = ((size_t)(row0 + 8) * N + col) >> 1;
                ((uint32_t*)PQ)[i0] = pack_h2(acc[fm][fn][0], acc[fm][fn][1]);
                ((uint32_t*)PQ)[i1] = pack_h2(acc[fm][fn][2], acc[fm][fn][3]);
            } else {   // mode 1: qkv
                if (col >= 2560) {
                    size_t i0 = (size_t)row0 * N + col;
                    size_t i1 = (size_t)(row0 + 8) * N + col;
                    *(float2*)&C[i0] = make_float2(acc[fm][fn][0], acc[fm][fn][1]);
                    *(float2*)&C[i1] = make_float2(acc[fm][fn][2], acc[fm][fn][3]);
                } else {
                    int i = (col & 63) >> 1;
                    float freq = 1.0f / powf(10000.0f, (2.0f * (float)i) / 64.0f);
                    int isq = (col < 2048);
                    int head = isq ? (col >> 6) : ((col - 2048) >> 6);
                    __half* Hp = isq ? PQ : PK;
                    int c8 = (col & 63) >> 3;
                    uint32_t inoff = (uint32_t)((col & 7) * 2);
#pragma unroll
                    for (int rr = 0; rr < 2; rr++) {
                        int row = row0 + rr * 8;
                        float v0 = acc[fm][fn][rr * 2], v1 = acc[fm][fn][rr * 2 + 1];
                        float sn, cs; sincosf((float)row * freq, &sn, &cs);
                        float orr = v0 * cs - v1 * sn;
                        float oii = v0 * sn + v1 * cs;
                        int r = row & 127;
                        size_t tile = ((size_t)head * 16 + (row >> 7)) * (size_t)TILE_B;
                        uint32_t off = (uint32_t)(r * 128) + (uint32_t)((c8 ^ (r & 7)) << 4) + inoff;
                        *(uint32_t*)((char*)Hp + tile + off) = pack_h2(orr, oii);
                    }
                }
            }
        }
    }
}
#define GEMM_SMEM (4 * 2 * TILE_B + 64)

// ---------------- tensorized flash attention (single-pass fp16) --------------
// Q resident in smem (16KB); K/V fp16, 4-stage pipeline (32KB/stage).
#define ATT_SQ    0u
#define ATT_SMSK  16384u
#define ATT_SST   24576u
#define ATT_MB    (24576u + 131072u)
#define ATT_SMEM  (24576 + 131072 + 64)
__global__ void __launch_bounds__(256, 1) attn_mma(
    const __half* __restrict__ Qhi,
    const __half* __restrict__ Khi, const __half* __restrict__ Vhi,
    const int* __restrict__ mask,
    __half* __restrict__ Chi)
{
    extern __shared__ char smem[];
    uint32_t sb = smem_u32(smem);
    int tid = threadIdx.x, wid = tid >> 5, ln = tid & 31;
    int qb = blockIdx.x, h = blockIdx.y;
    int kvh = h >> 2;
    int q2 = (ln & 3) * 2;

    int* msk = (int*)(smem + ATT_SMSK);
    for (int i = tid; i < S_LEN; i += 256) msk[i] = mask[i];
    {
        const uint4* qs0 = (const uint4*)(Qhi + ((size_t)h * 16 + qb) * 8192);
        uint4* qd0 = (uint4*)(smem + ATT_SQ);
        for (int i = tid; i < 1024; i += 256) qd0[i] = qs0[i];
    }
    uint32_t mb0 = sb + ATT_MB;
    if (tid == 0) {
        MBAR_INIT(mb0, 1); MBAR_INIT(mb0 + 8, 1);
        MBAR_INIT(mb0 + 16, 1); MBAR_INIT(mb0 + 24, 1);
    }
    __syncthreads();

    auto issue = [&](int s, int kb) {
        uint32_t mb = mb0 + s * 8;
        uint32_t dst = sb + ATT_SST + s * 32768;
        size_t ko = ((size_t)kvh * 16 + kb) * 8192;
        MBAR_EXPECT(mb, 32768);
        bulk_g2s(dst,         Khi + ko, 16384, mb);
        bulk_g2s(dst + 16384, Vhi + ko, 16384, mb);
    };
    if (tid == 0) { issue(0, 0); issue(1, 1); issue(2, 2); issue(3, 3); }

    uint32_t qh[4][4];
    {
        int arow0 = wid * 16 + (ln & 7) + ((ln & 8) ? 8 : 0);
        int acgs = (ln >> 4) & 1;
#pragma unroll
        for (int ks = 0; ks < 4; ks++) {
            int cg = ks * 2 + acgs;
            uint32_t off = (uint32_t)(arow0 * 128) + (uint32_t)((cg ^ (arow0 & 7)) << 4);
            LDSM4(qh[ks], sb + ATT_SQ + off);
        }
    }

    float mrow0 = -INFINITY, mrow1 = -INFINITY, lrow0 = 0.f, lrow1 = 0.f;
    float cacc[8][4];
#pragma unroll
    for (int j = 0; j < 8; j++)
#pragma unroll
        for (int r = 0; r < 4; r++) cacc[j][r] = 0.f;

    int brow_b = (ln & 7) + ((ln & 16) ? 8 : 0);
    int bcgs = (ln >> 3) & 1;

    for (int kb = 0; kb < 16; kb++) {
        int s = kb & 3, ph = (kb >> 2) & 1;
        mbar_wait(mb0 + s * 8, ph);
        uint32_t st = sb + ATT_SST + s * 32768;
        uint32_t Kh = st, Vh = st + 16384;

        float sacc[16][4];
#pragma unroll
        for (int j = 0; j < 16; j++)
#pragma unroll
            for (int r = 0; r < 4; r++) sacc[j][r] = 0.f;
#pragma unroll
        for (int nj = 0; nj < 4; nj++) {
#pragma unroll
            for (int ks = 0; ks < 4; ks++) {
                uint32_t bh[8];
                int cg = ks * 2 + bcgs;
#pragma unroll
                for (int pr = 0; pr < 2; pr++) {
                    int row = nj * 32 + pr * 16 + brow_b;
                    uint32_t off = (uint32_t)(row * 128) + (uint32_t)((cg ^ (row & 7)) << 4);
                    LDSM4(bh + pr * 4, Kh + off);
                }
#pragma unroll
                for (int nt = 0; nt < 4; nt++) {
                    float* d = sacc[nj * 4 + nt];
                    uint32_t* rh = bh + (nt >> 1) * 4 + (nt & 1) * 2;
                    MMA_F16(d, qh[ks], rh);
                }
            }
        }
        float tmax0 = -INFINITY, tmax1 = -INFINITY;
#pragma unroll
        for (int j = 0; j < 16; j++) {
            int c = kb * 128 + 8 * j + q2;
            sacc[j][0] = msk[c]     ? sacc[j][0] * 0.125f : -1e30f;
            sacc[j][1] = msk[c + 1] ? sacc[j][1] * 0.125f : -1e30f;
            sacc[j][2] = msk[c]     ? sacc[j][2] * 0.125f : -1e30f;
            sacc[j][3] = msk[c + 1] ? sacc[j][3] * 0.125f : -1e30f;
            tmax0 = fmaxf(tmax0, fmaxf(sacc[j][0], sacc[j][1]));
            tmax1 = fmaxf(tmax1, fmaxf(sacc[j][2], sacc[j][3]));
        }
        tmax0 = fmaxf(tmax0, __shfl_xor_sync(0xffffffffu, tmax0, 1));
        tmax0 = fmaxf(tmax0, __shfl_xor_sync(0xffffffffu, tmax0, 2));
        tmax1 = fmaxf(tmax1, __shfl_xor_sync(0xffffffffu, tmax1, 1));
        tmax1 = fmaxf(tmax1, __shfl_xor_sync(0xffffffffu, tmax1, 2));
        float mnew0 = fmaxf(mrow0, tmax0);
        float mnew1 = fmaxf(mrow1, tmax1);
        float alpha0 = (mrow0 == -INFINITY) ? 0.f : __expf(mrow0 - mnew0);
        float alpha1 = (mrow1 == -INFINITY) ? 0.f : __expf(mrow1 - mnew1);
        float rs0 = 0.f, rs1 = 0.f;
#pragma unroll
        for (int j = 0; j < 16; j++) {
            float p0 = __expf(sacc[j][0] - mnew0);
            float p1 = __expf(sacc[j][1] - mnew0);
            float p2 = __expf(sacc[j][2] - mnew1);
            float p3 = __expf(sacc[j][3] - mnew1);
            rs0 += p0 + p1; rs1 += p2 + p3;
            sacc[j][0] = p0; sacc[j][1] = p1; sacc[j][2] = p2; sacc[j][3] = p3;
        }
        rs0 += __shfl_xor_sync(0xffffffffu, rs0, 1);
        rs0 += __shfl_xor_sync(0xffffffffu, rs0, 2);
        rs1 += __shfl_xor_sync(0xffffffffu, rs1, 1);
        rs1 += __shfl_xor_sync(0xffffffffu, rs1, 2);
        lrow0 = lrow0 * alpha0 + rs0;
        lrow1 = lrow1 * alpha1 + rs1;
        mrow0 = mnew0; mrow1 = mnew1;
#pragma unroll
        for (int j = 0; j < 8; j++) {
            cacc[j][0] *= alpha0; cacc[j][1] *= alpha0;
            cacc[j][2] *= alpha1; cacc[j][3] *= alpha1;
        }
#pragma unroll
        for (int t = 0; t < 8; t++) {
            uint32_t pah[4];
            {
                float* s0 = sacc[2 * t]; float* s1 = sacc[2 * t + 1];
                pah[0] = pack_h2(s0[0], s0[1]);
                pah[1] = pack_h2(s0[2], s0[3]);
                pah[2] = pack_h2(s1[0], s1[1]);
                pah[3] = pack_h2(s1[2], s1[3]);
            }
            uint32_t vbh[16];
            int sub = t >> 2;
            int cgv = (t & 3) * 2 + bcgs;
#pragma unroll
            for (int prd = 0; prd < 4; prd++) {
                int row = prd * 16 + brow_b;
                uint32_t off = (uint32_t)(sub * 8192) + (uint32_t)(row * 128) +
                               (uint32_t)((cgv ^ (row & 7)) << 4);
                LDSM4(vbh + prd * 4, Vh + off);
            }
#pragma unroll
            for (int jd = 0; jd < 8; jd++) {
                uint32_t* rh = vbh + (jd >> 1) * 4 + (jd & 1) * 2;
                MMA_F16(cacc[jd], pah, rh);
            }
        }
        __syncthreads();
        if (tid == 0 && kb + 4 < 16) issue(s, kb + 4);
    }
    // epilogue -> ctx tiles (A-side of wo GEMM)
    float inv0 = (lrow0 > 0.f) ? (1.f / lrow0) : 0.f;
    float inv1 = (lrow1 > 0.f) ? (1.f / lrow1) : 0.f;
    int r0 = wid * 16 + (ln >> 2);
    size_t tile = ((size_t)h * 16 + qb) * (size_t)TILE_B;
#pragma unroll
    for (int jd = 0; jd < 8; jd++) {
        uint32_t inoff = (uint32_t)(q2 * 2);
#pragma unroll
        for (int rr = 0; rr < 2; rr++) {
            int r = r0 + rr * 8;
            float v0 = cacc[jd][rr * 2] * (rr ? inv1 : inv0);
            float v1 = cacc[jd][rr * 2 + 1] * (rr ? inv1 : inv0);
            uint32_t off = (uint32_t)(r * 128) + (uint32_t)((jd ^ (r & 7)) << 4) + inoff;
            *(uint32_t*)((char*)Chi + tile + off) = pack_h2(v0, v1);
        }
    }
}

// ---------------- LayerNorm -> tiled fp16 directly ----------------------------
__global__ void ln_tile(const float* __restrict__ x, const float* __restrict__ w,
                        const float* __restrict__ b, __half* __restrict__ Hi) {
    int row = blockIdx.x;
    int tid = threadIdx.x;
    const float* xr = x + (size_t)row * D_MODEL;
    float4 v0 = *(const float4*)&xr[tid * 8];
    float4 v1 = *(const float4*)&xr[tid * 8 + 4];
    float xin[8] = {v0.x, v0.y, v0.z, v0.w, v1.x, v1.y, v1.z, v1.w};
    float s = 0.f, s2 = 0.f;
#pragma unroll
    for (int u = 0; u < 8; u++) { s += xin[u]; s2 += xin[u] * xin[u]; }
    __shared__ float r0s[256], r1s[256];
    r0s[tid] = s; r1s[tid] = s2;
    __syncthreads();
    for (int o = 128; o > 0; o >>= 1) {
        if (tid < o) { r0s[tid] += r0s[tid + o]; r1s[tid] += r1s[tid + o]; }
        __syncthreads();
    }
    float mean = r0s[0] * (1.0f / D_MODEL);
    float var  = r1s[0] * (1.0f / D_MODEL) - mean * mean;
    float inv  = rsqrtf(var + 1e-5f);
    int kt = tid >> 3, c8 = tid & 7;
    int mt = row >> 7, r = row & 127;
    size_t tile = ((size_t)kt * 16 + mt) * (size_t)TILE_B;
    uint32_t off = (uint32_t)(r * 128) + (uint32_t)((c8 ^ (r & 7)) << 4);
    __half h8[8];
#pragma unroll
    for (int u = 0; u < 8; u++)
        h8[u] = __float2half_rn((xin[u] - mean) * inv * w[tid * 8 + u] + b[tid * 8 + u]);
    *(uint4*)((char*)Hi + tile + off) = *(uint4*)h8;
}

// ---------------- V fp32 -> transposed fp16 tiles [64 d][128 keys] -----------
__global__ void conv_vt(const float* __restrict__ src, __half* __restrict__ Hi) {
    __shared__ float s[128][65];
    int sbk = blockIdx.x, kvh = blockIdx.y;
    int tid = threadIdx.x;
    for (int t = tid; t < 128 * 16; t += 256) {
        int r = t >> 4, c4 = (t & 15) * 4;
        float4 v = *(const float4*)&src[(size_t)(sbk * 128 + r) * QKV_N + 2560 + kvh * 64 + c4];
        s[r][c4] = v.x; s[r][c4 + 1] = v.y; s[r][c4 + 2] = v.z; s[r][c4 + 3] = v.w;
    }
    __syncthreads();
    size_t tile = ((size_t)kvh * 16 + sbk) * (size_t)TILE_B;
    for (int t = tid; t < 1024; t += 256) {
        int d = t >> 4, kc8 = t & 15;
        int sub = kc8 >> 3, c8 = kc8 & 7;
        __half h8[8];
#pragma unroll
        for (int u = 0; u < 8; u++)
            h8[u] = __float2half_rn(s[(kc8 & 7) * 8 + sub * 64 + u][d]);
        uint32_t off = (uint32_t)(sub * 8192) + (uint32_t)(d * 128) +
                       (uint32_t)((c8 ^ (d & 7)) << 4);
        *(uint4*)((char*)Hi + tile + off) = *(uint4*)h8;
    }
}

// ---------------- fp32 weight [K,N] -> tiled transposed fp16 -----------------
__global__ void conv_w(const float* __restrict__ W, __half* __restrict__ Hi,
                       int K, int Nsrc, int nt_off, int NT_total) {
    __shared__ float s[128][65];
    int kt = blockIdx.x, nt = blockIdx.y;
    int tid = threadIdx.x;
    for (int t = tid; t < 64 * 32; t += 256) {
        int i = t >> 5, j4 = (t & 31) * 4;
        float4 v = *(const float4*)&W[((size_t)kt * 64 + i) * Nsrc + (size_t)nt * 128 + j4];
        s[j4 + 0][i] = v.x; s[j4 + 1][i] = v.y; s[j4 + 2][i] = v.z; s[j4 + 3][i] = v.w;
    }
    __syncthreads();
    size_t tile = ((size_t)kt * NT_total + (nt_off + nt)) * TILE_B;
    for (int t = tid; t < 1024; t += 256) {
        int r = t >> 3, c8 = t & 7;
        __half h8[8];
#pragma unroll
        for (int u = 0; u < 8; u++)
            h8[u] = __float2half_rn(s[r][c8 * 8 + u]);
        uint32_t off = (uint32_t)(r * 128) + (uint32_t)((c8 ^ (r & 7)) << 4);
        *(uint4*)((char*)Hi + tile + off) = *(uint4*)h8;
    }
}

// ---------------- silu(g1)*g3 -> gb tiles ------------------------------------
__global__ void silu_conv(const __half* __restrict__ Gh, __half* __restrict__ Hi) {
    int idx = blockIdx.x * blockDim.x + threadIdx.x;   // chunk of 8
    int cpr = HID / 8;                                 // 704
    int m = idx / cpr, ck = idx % cpr;
    size_t base1 = (size_t)m * W13_N + ck * 8;
    size_t base3 = base1 + HID;
    uint4 g1h4 = *(const uint4*)&Gh[base1];
    uint4 g3h4 = *(const uint4*)&Gh[base3];
    const __half* g1h = (const __half*)&g1h4;
    const __half* g3h = (const __half*)&g3h4;
    __half h8[8];
#pragma unroll
    for (int u = 0; u < 8; u++) {
        float a = __half2float(g1h[u]);
        float c = __half2float(g3h[u]);
        float sig = 1.0f / (1.0f + expf(-a));
        h8[u] = __float2half_rn(a * sig * c);
    }
    int kt = ck >> 3, c8 = ck & 7;
    int mt = m >> 7, r = m & 127;
    size_t tile = ((size_t)kt * 16 + mt) * (size_t)TILE_B;
    uint32_t off = (uint32_t)(r * 128) + (uint32_t)((c8 ^ (r & 7)) << 4);
    *(uint4*)((char*)Hi + tile + off) = *(uint4*)h8;
}

// ---------------- launch -----------------------------------------------------
extern "C" void kernel_launch(void* const* d_in, const int* in_sizes, int n_in,
                              void* d_out, int out_size) {
    const float* x    = (const float*)d_in[0];
    const int*   mask = (const int*)  d_in[1];
    const float* wq   = (const float*)d_in[2];
    const float* wk   = (const float*)d_in[3];
    const float* wv   = (const float*)d_in[4];
    const float* wo   = (const float*)d_in[5];
    const float* w1   = (const float*)d_in[6];
    const float* w2   = (const float*)d_in[7];
    const float* w3   = (const float*)d_in[8];
    const float* ln1w = (const float*)d_in[9];
    const float* ln1b = (const float*)d_in[10];
    const float* ln2w = (const float*)d_in[11];
    const float* ln2b = (const float*)d_in[12];
    float* out = (float*)d_out;

    float *qkv, *x1;
    cudaGetSymbolAddress((void**)&qkv, g_qkv);
    cudaGetSymbolAddress((void**)&x1,  g_x1);

    __half *hhi, *chi, *ghi, *g13h;
    __half *wqkvh, *woh, *w13h, *w2h;
    __half *qah, *kah, *vah;
    cudaGetSymbolAddress((void**)&hhi, t_h_hi);
    cudaGetSymbolAddress((void**)&chi, t_ctx_hi);
    cudaGetSymbolAddress((void**)&ghi, t_g_hi);
    cudaGetSymbolAddress((void**)&g13h, t_g13_hi);
    cudaGetSymbolAddress((void**)&wqkvh, t_wqkv_hi);
    cudaGetSymbolAddress((void**)&woh, t_wo_hi);
    cudaGetSymbolAddress((void**)&w13h, t_w13_hi);
    cudaGetSymbolAddress((void**)&w2h, t_w2_hi);
    cudaGetSymbolAddress((void**)&qah, t_qat_hi);
    cudaGetSymbolAddress((void**)&kah, t_kat_hi);
    cudaGetSymbolAddress((void**)&vah, t_vat_hi);

    cudaFuncSetAttribute(mma_gemm, cudaFuncAttributeMaxDynamicSharedMemorySize, GEMM_SMEM);
    cudaFuncSetAttribute(attn_mma, cudaFuncAttributeMaxDynamicSharedMemorySize, ATT_SMEM);

    // weights -> tiled fp16
    conv_w<<<dim3(D_MODEL / 64, 16), 256>>>(wq, wqkvh, D_MODEL, D_MODEL, 0,  24);
    conv_w<<<dim3(D_MODEL / 64, 4),  256>>>(wk, wqkvh, D_MODEL, 512,     16, 24);
    conv_w<<<dim3(D_MODEL / 64, 4),  256>>>(wv, wqkvh, D_MODEL, 512,     20, 24);
    conv_w<<<dim3(D_MODEL / 64, 16), 256>>>(wo, woh,   D_MODEL, D_MODEL, 0,  16);
    conv_w<<<dim3(D_MODEL / 64, 44), 256>>>(w1, w13h,  D_MODEL, HID,     0,  88);
    conv_w<<<dim3(D_MODEL / 64, 44), 256>>>(w3, w13h,  D_MODEL, HID,     44, 88);
    conv_w<<<dim3(HID / 64,     16), 256>>>(w2, w2h,   HID,     D_MODEL, 0,  16);

    // h tiles = LN1(x)
    ln_tile<<<S_LEN, 256>>>(x, ln1w, ln1b, hhi);

    // qkv GEMM: rope Q/K -> attention tiles; V -> fp32
    mma_gemm<<<dim3(QKV_N / 128, S_LEN / 128), 256, GEMM_SMEM>>>(hhi, wqkvh,
        nullptr, qkv, S_LEN, QKV_N, D_MODEL, 1, qah, kah);

    conv_vt<<<dim3(16, NKV), 256>>>(qkv, vah);

    // attention -> ctx tiles
    attn_mma<<<dim3(S_LEN / 128, NH), 256, ATT_SMEM>>>(qah, kah, vah, mask, chi);

    // x1 = x + ctx @ wo (fp32)
    mma_gemm<<<dim3(D_MODEL / 128, S_LEN / 128), 256, GEMM_SMEM>>>(chi, woh,
        x, x1, S_LEN, D_MODEL, D_MODEL, 0, nullptr, nullptr);

    // h tiles = LN2(x1)
    ln_tile<<<S_LEN, 256>>>(x1, ln2w, ln2b, hhi);

    // g13 = h @ [w1|w3] -> fp16 row-major
    mma_gemm<<<dim3(W13_N / 128, S_LEN / 128), 256, GEMM_SMEM>>>(hhi, w13h,
        nullptr, nullptr, S_LEN, W13_N, D_MODEL, 2, g13h, nullptr);

    // gb tiles = silu(g1) * g3
    silu_conv<<<(S_LEN * HID / 8) / 256, 256>>>(g13h, ghi);

    // out = x1 + gb @ w2
    mma_gemm<<<dim3(D_MODEL / 128, S_LEN / 128), 256, GEMM_SMEM>>>(ghi, w2h,
        x1, out, S_LEN, D_MODEL, HID, 0, nullptr, nullptr);
}

// round 15
// speedup vs baseline: 8.4900x; 1.0136x over previous
#include <cuda_runtime.h>
#include <cuda_fp16.h>
#include <cstdint>
#include <math.h>

#define S_LEN   2048
#define D_MODEL 2048
#define HID     5632
#define NH      32
#define NKV     8
#define HD      64
#define QKV_N   3072        // 2048 q | 512 k | 512 v
#define W13_N   11264       // 5632 g1 | 5632 g3 (interleaved 64/64 per 128-tile)
#define TILE_B  16384

// ---------------- fp32 scratch ------------------------------------------------
__device__ __align__(1024) float g_qkv[S_LEN * QKV_N];   // only V cols written/read
__device__ __align__(1024) float g_x1 [S_LEN * D_MODEL];

// ---------------- fp16 scratch ------------------------------------------------
__device__ __align__(1024) __half t_h_hi  [S_LEN * D_MODEL];
__device__ __align__(1024) __half t_ctx_hi[S_LEN * D_MODEL];
__device__ __align__(1024) __half t_g_hi  [S_LEN * HID];
__device__ __align__(1024) __half t_wqkv_hi[QKV_N * D_MODEL];
__device__ __align__(1024) __half t_wo_hi [D_MODEL * D_MODEL];
__device__ __align__(1024) __half t_w13_hi[W13_N * D_MODEL];
__device__ __align__(1024) __half t_w2_hi [D_MODEL * HID];
__device__ __align__(1024) __half t_qat_hi[NH  * 16 * 8192];
__device__ __align__(1024) __half t_kat_hi[NKV * 16 * 8192];
__device__ __align__(1024) __half t_vat_hi[NKV * 16 * 8192];

// ---------------- PTX helpers (baseline PTX only) -----------------------------
__device__ __forceinline__ uint32_t smem_u32(const void* p) {
    uint32_t a;
    asm("{ .reg .u64 t; cvta.to.shared.u64 t, %1; cvt.u32.u64 %0, t; }" : "=r"(a) : "l"(p));
    return a;
}
#define MBAR_INIT(a, c) asm volatile("mbarrier.init.shared.b64 [%0], %1;" :: "r"(a), "r"(c) : "memory")
#define MBAR_EXPECT(a, b) asm volatile("mbarrier.arrive.expect_tx.shared.b64 _, [%0], %1;" :: "r"(a), "r"(b) : "memory")
__device__ __forceinline__ void mbar_wait(uint32_t mbar, uint32_t parity) {
    asm volatile(
        "{\n\t.reg .pred P1;\n\t"
        "W_%=:\n\t"
        "mbarrier.try_wait.parity.acquire.cta.shared::cta.b64 P1, [%0], %1, 0x989680;\n\t"
        "@P1 bra.uni D_%=;\n\t"
        "bra.uni W_%=;\n\t"
        "D_%=:\n\t}"
        :: "r"(mbar), "r"(parity) : "memory");
}
__device__ __forceinline__ void bulk_g2s(uint32_t dst, const void* src, uint32_t bytes, uint32_t mbar) {
    asm volatile("cp.async.bulk.shared::cta.global.mbarrier::complete_tx::bytes [%0], [%1], %2, [%3];"
        :: "r"(dst), "l"(src), "r"(bytes), "r"(mbar) : "memory");
}
#define LDSM4(r, a) \
    asm volatile("ldmatrix.sync.aligned.m8n8.x4.shared.b16 {%0,%1,%2,%3}, [%4];" \
        : "=r"((r)[0]), "=r"((r)[1]), "=r"((r)[2]), "=r"((r)[3]) : "r"(a))
#define MMA_F16(d, a, b) \
    asm volatile("mma.sync.aligned.m16n8k16.row.col.f32.f16.f16.f32 " \
        "{%0,%1,%2,%3}, {%4,%5,%6,%7}, {%8,%9}, {%0,%1,%2,%3};" \
        : "+f"((d)[0]), "+f"((d)[1]), "+f"((d)[2]), "+f"((d)[3]) \
        : "r"((a)[0]), "r"((a)[1]), "r"((a)[2]), "r"((a)[3]), "r"((b)[0]), "r"((b)[1]))

__device__ __forceinline__ uint32_t pack_h2(float a, float b) {
    __half2 t = __floats2half2_rn(a, b);
    return *(uint32_t*)&t;
}

// ---------------- mma.sync GEMM (4-stage pipeline, single-pass fp16) ---------
// mode 0: C fp32 (+R)
// mode 1: qkv — rope Q (-> PQ), K (-> PK); V cols >= 2560 -> C fp32
// mode 3: fused W13 -> silu(g1)*g3 -> gb A-tiles (PQ)
__global__ void __launch_bounds__(256, 1) mma_gemm(
    const __half* __restrict__ Ahi, const __half* __restrict__ Bhi,
    const float* __restrict__ R, float* __restrict__ C, int M, int N, int K, int mode,
    __half* __restrict__ PQ, __half* __restrict__ PK)
{
    extern __shared__ char smem[];
    uint32_t sb = smem_u32(smem);
    int tid = threadIdx.x, wid = tid >> 5, ln = tid & 31;
    int wm = wid >> 2, wn = wid & 3;
    int mt = blockIdx.y, nt = blockIdx.x;
    int MT = M >> 7, NT = N >> 7, KTt = K >> 6;
    uint32_t mb0 = sb + 4 * 2 * TILE_B;

    if (tid == 0) {
        MBAR_INIT(mb0, 1); MBAR_INIT(mb0 + 8, 1);
        MBAR_INIT(mb0 + 16, 1); MBAR_INIT(mb0 + 24, 1);
    }
    __syncthreads();

    auto issue = [&](int s, int kt) {
        uint32_t mb = mb0 + s * 8;
        uint32_t dst = sb + s * (2 * TILE_B);
        size_t aoff = ((size_t)kt * MT + mt) * (size_t)(128 * 64);
        size_t boff = ((size_t)kt * NT + nt) * (size_t)(128 * 64);
        MBAR_EXPECT(mb, 2 * TILE_B);
        bulk_g2s(dst,          Ahi + aoff, TILE_B, mb);
        bulk_g2s(dst + TILE_B, Bhi + boff, TILE_B, mb);
    };
    if (tid == 0) {
        issue(0, 0);
        if (KTt > 1) issue(1, 1);
        if (KTt > 2) issue(2, 2);
        if (KTt > 3) issue(3, 3);
    }

    float acc[4][4][4];
#pragma unroll
    for (int i = 0; i < 4; i++)
#pragma unroll
        for (int j = 0; j < 4; j++)
#pragma unroll
            for (int r = 0; r < 4; r++) acc[i][j][r] = 0.f;

    int arow0 = wm * 64 + (ln & 7) + ((ln & 8) ? 8 : 0);
    int acgs  = (ln >> 4) & 1;
    int brow0 = wn * 32 + (ln & 7) + ((ln & 16) ? 8 : 0);
    int bcgs  = (ln >> 3) & 1;

    for (int kt = 0; kt < KTt; kt++) {
        int s = kt & 3, ph = (kt >> 2) & 1;
        mbar_wait(mb0 + s * 8, ph);
        uint32_t st = sb + s * (2 * TILE_B);
        uint32_t Ah = st, Bh = st + TILE_B;
#pragma unroll
        for (int ks = 0; ks < 4; ks++) {
            int acg = ks * 2 + acgs;
            int bcg = ks * 2 + bcgs;
            uint32_t ahr[16], bhr[8];
#pragma unroll
            for (int fm = 0; fm < 4; fm++) {
                int row = arow0 + fm * 16;
                uint32_t off = (uint32_t)(row * 128) + (uint32_t)((acg ^ (row & 7)) << 4);
                LDSM4(ahr + fm * 4, Ah + off);
            }
#pragma unroll
            for (int pr = 0; pr < 2; pr++) {
                int row = brow0 + pr * 16;
                uint32_t off = (uint32_t)(row * 128) + (uint32_t)((bcg ^ (row & 7)) << 4);
                LDSM4(bhr + pr * 4, Bh + off);
            }
#pragma unroll
            for (int fm = 0; fm < 4; fm++)
#pragma unroll
                for (int fn = 0; fn < 4; fn++)
                    MMA_F16(acc[fm][fn], ahr + fm * 4, bhr + fn * 2);
        }
        __syncthreads();
        if (tid == 0 && kt + 4 < KTt) issue(s, kt + 4);
    }

    int qr = ln >> 2, qc = ln & 3;

    if (mode == 3) {
        // stage fp32 accs to smem [128][132], then silu-combine -> gb A-tile
        float* sf = (float*)smem;
#pragma unroll
        for (int fm = 0; fm < 4; fm++) {
            int rl = wm * 64 + fm * 16 + qr;
#pragma unroll
            for (int fn = 0; fn < 4; fn++) {
                int col = wn * 32 + fn * 8 + 2 * qc;
                sf[rl * 132 + col]           = acc[fm][fn][0];
                sf[rl * 132 + col + 1]       = acc[fm][fn][1];
                sf[(rl + 8) * 132 + col]     = acc[fm][fn][2];
                sf[(rl + 8) * 132 + col + 1] = acc[fm][fn][3];
            }
        }
        __syncthreads();
        size_t tile = ((size_t)nt * MT + mt) * (size_t)TILE_B;
#pragma unroll
        for (int i = 0; i < 4; i++) {
            int ch = tid + 256 * i;         // 0..1023
            int r = ch >> 3, c8 = ch & 7;
            __half h8[8];
#pragma unroll
            for (int u = 0; u < 8; u++) {
                float a = sf[r * 132 + c8 * 8 + u];
                float c = sf[r * 132 + 64 + c8 * 8 + u];
                float sig = 1.0f / (1.0f + expf(-a));
                h8[u] = __float2half_rn(a * sig * c);
            }
            uint32_t off = (uint32_t)(r * 128) + (uint32_t)((c8 ^ (r & 7)) << 4);
            *(uint4*)((char*)PQ + tile + off) = *(uint4*)h8;
        }
        return;
    }

    float freqs[4];
    if (mode == 1) {
#pragma unroll
        for (int fn = 0; fn < 4; fn++) {
            int col = nt * 128 + wn * 32 + fn * 8 + 2 * qc;
            int i = (col & 63) >> 1;
            freqs[fn] = 1.0f / powf(10000.0f, (2.0f * (float)i) / 64.0f);
        }
    }

#pragma unroll
    for (int fm = 0; fm < 4; fm++) {
        int row0 = mt * 128 + wm * 64 + fm * 16 + qr;
#pragma unroll
        for (int fn = 0; fn < 4; fn++) {
            int col = nt * 128 + wn * 32 + fn * 8 + 2 * qc;
            if (mode == 0) {
                size_t i0 = (size_t)row0 * N + col;
                size_t i1 = (size_t)(row0 + 8) * N + col;
                float2 v0 = make_float2(acc[fm][fn][0], acc[fm][fn][1]);
                float2 v1 = make_float2(acc[fm][fn][2], acc[fm][fn][3]);
                if (R) {
                    float2 r0 = *(const float2*)&R[i0];
                    float2 r1 = *(const float2*)&R[i1];
                    v0.x += r0.x; v0.y += r0.y; v1.x += r1.x; v1.y += r1.y;
                }
                *(float2*)&C[i0] = v0;
                *(float2*)&C[i1] = v1;
            } else {   // mode 1: qkv
                if (col >= 2560) {
                    size_t i0 = (size_t)row0 * N + col;
                    size_t i1 = (size_t)(row0 + 8) * N + col;
                    *(float2*)&C[i0] = make_float2(acc[fm][fn][0], acc[fm][fn][1]);
                    *(float2*)&C[i1] = make_float2(acc[fm][fn][2], acc[fm][fn][3]);
                } else {
                    float freq = freqs[fn];
                    int isq = (col < 2048);
                    int head = isq ? (col >> 6) : ((col - 2048) >> 6);
                    __half* Hp = isq ? PQ : PK;
                    int c8 = (col & 63) >> 3;
                    uint32_t inoff = (uint32_t)((col & 7) * 2);
#pragma unroll
                    for (int rr = 0; rr < 2; rr++) {
                        int row = row0 + rr * 8;
                        float v0 = acc[fm][fn][rr * 2], v1 = acc[fm][fn][rr * 2 + 1];
                        float sn, cs; sincosf((float)row * freq, &sn, &cs);
                        float orr = v0 * cs - v1 * sn;
                        float oii = v0 * sn + v1 * cs;
                        int r = row & 127;
                        size_t tile = ((size_t)head * 16 + (row >> 7)) * (size_t)TILE_B;
                        uint32_t off = (uint32_t)(r * 128) + (uint32_t)((c8 ^ (r & 7)) << 4) + inoff;
                        *(uint32_t*)((char*)Hp + tile + off) = pack_h2(orr, oii);
                    }
                }
            }
        }
    }
}
#define GEMM_SMEM (4 * 2 * TILE_B + 64)

// ---------------- tensorized flash attention (single-pass fp16) --------------
#define ATT_SQ    0u
#define ATT_SMSK  16384u
#define ATT_SST   24576u
#define ATT_MB    (24576u + 131072u)
#define ATT_SMEM  (24576 + 131072 + 64)
__global__ void __launch_bounds__(256, 1) attn_mma(
    const __half* __restrict__ Qhi,
    const __half* __restrict__ Khi, const __half* __restrict__ Vhi,
    const int* __restrict__ mask,
    __half* __restrict__ Chi)
{
    extern __shared__ char smem[];
    uint32_t sb = smem_u32(smem);
    int tid = threadIdx.x, wid = tid >> 5, ln = tid & 31;
    int qb = blockIdx.x, h = blockIdx.y;
    int kvh = h >> 2;
    int q2 = (ln & 3) * 2;

    int* msk = (int*)(smem + ATT_SMSK);
    for (int i = tid; i < S_LEN; i += 256) msk[i] = mask[i];
    {
        const uint4* qs0 = (const uint4*)(Qhi + ((size_t)h * 16 + qb) * 8192);
        uint4* qd0 = (uint4*)(smem + ATT_SQ);
        for (int i = tid; i < 1024; i += 256) qd0[i] = qs0[i];
    }
    uint32_t mb0 = sb + ATT_MB;
    if (tid == 0) {
        MBAR_INIT(mb0, 1); MBAR_INIT(mb0 + 8, 1);
        MBAR_INIT(mb0 + 16, 1); MBAR_INIT(mb0 + 24, 1);
    }
    __syncthreads();

    auto issue = [&](int s, int kb) {
        uint32_t mb = mb0 + s * 8;
        uint32_t dst = sb + ATT_SST + s * 32768;
        size_t ko = ((size_t)kvh * 16 + kb) * 8192;
        MBAR_EXPECT(mb, 32768);
        bulk_g2s(dst,         Khi + ko, 16384, mb);
        bulk_g2s(dst + 16384, Vhi + ko, 16384, mb);
    };
    if (tid == 0) { issue(0, 0); issue(1, 1); issue(2, 2); issue(3, 3); }

    uint32_t qh[4][4];
    {
        int arow0 = wid * 16 + (ln & 7) + ((ln & 8) ? 8 : 0);
        int acgs = (ln >> 4) & 1;
#pragma unroll
        for (int ks = 0; ks < 4; ks++) {
            int cg = ks * 2 + acgs;
            uint32_t off = (uint32_t)(arow0 * 128) + (uint32_t)((cg ^ (arow0 & 7)) << 4);
            LDSM4(qh[ks], sb + ATT_SQ + off);
        }
    }

    float mrow0 = -INFINITY, mrow1 = -INFINITY, lrow0 = 0.f, lrow1 = 0.f;
    float cacc[8][4];
#pragma unroll
    for (int j = 0; j < 8; j++)
#pragma unroll
        for (int r = 0; r < 4; r++) cacc[j][r] = 0.f;

    int brow_b = (ln & 7) + ((ln & 16) ? 8 : 0);
    int bcgs = (ln >> 3) & 1;

    for (int kb = 0; kb < 16; kb++) {
        int s = kb & 3, ph = (kb >> 2) & 1;
        mbar_wait(mb0 + s * 8, ph);
        uint32_t st = sb + ATT_SST + s * 32768;
        uint32_t Kh = st, Vh = st + 16384;

        float sacc[16][4];
#pragma unroll
        for (int j = 0; j < 16; j++)
#pragma unroll
            for (int r = 0; r < 4; r++) sacc[j][r] = 0.f;
#pragma unroll
        for (int nj = 0; nj < 4; nj++) {
#pragma unroll
            for (int ks = 0; ks < 4; ks++) {
                uint32_t bh[8];
                int cg = ks * 2 + bcgs;
#pragma unroll
                for (int pr = 0; pr < 2; pr++) {
                    int row = nj * 32 + pr * 16 + brow_b;
                    uint32_t off = (uint32_t)(row * 128) + (uint32_t)((cg ^ (row & 7)) << 4);
                    LDSM4(bh + pr * 4, Kh + off);
                }
#pragma unroll
                for (int nt = 0; nt < 4; nt++) {
                    float* d = sacc[nj * 4 + nt];
                    uint32_t* rh = bh + (nt >> 1) * 4 + (nt & 1) * 2;
                    MMA_F16(d, qh[ks], rh);
                }
            }
        }
        float tmax0 = -INFINITY, tmax1 = -INFINITY;
#pragma unroll
        for (int j = 0; j < 16; j++) {
            int c = kb * 128 + 8 * j + q2;
            sacc[j][0] = msk[c]     ? sacc[j][0] * 0.125f : -1e30f;
            sacc[j][1] = msk[c + 1] ? sacc[j][1] * 0.125f : -1e30f;
            sacc[j][2] = msk[c]     ? sacc[j][2] * 0.125f : -1e30f;
            sacc[j][3] = msk[c + 1] ? sacc[j][3] * 0.125f : -1e30f;
            tmax0 = fmaxf(tmax0, fmaxf(sacc[j][0], sacc[j][1]));
            tmax1 = fmaxf(tmax1, fmaxf(sacc[j][2], sacc[j][3]));
        }
        tmax0 = fmaxf(tmax0, __shfl_xor_sync(0xffffffffu, tmax0, 1));
        tmax0 = fmaxf(tmax0, __shfl_xor_sync(0xffffffffu, tmax0, 2));
        tmax1 = fmaxf(tmax1, __shfl_xor_sync(0xffffffffu, tmax1, 1));
        tmax1 = fmaxf(tmax1, __shfl_xor_sync(0xffffffffu, tmax1, 2));
        float mnew0 = fmaxf(mrow0, tmax0);
        float mnew1 = fmaxf(mrow1, tmax1);
        float alpha0 = (mrow0 == -INFINITY) ? 0.f : __expf(mrow0 - mnew0);
        float alpha1 = (mrow1 == -INFINITY) ? 0.f : __expf(mrow1 - mnew1);
        float rs0 = 0.f, rs1 = 0.f;
#pragma unroll
        for (int j = 0; j < 16; j++) {
            float p0 = __expf(sacc[j][0] - mnew0);
            float p1 = __expf(sacc[j][1] - mnew0);
            float p2 = __expf(sacc[j][2] - mnew1);
            float p3 = __expf(sacc[j][3] - mnew1);
            rs0 += p0 + p1; rs1 += p2 + p3;
            sacc[j][0] = p0; sacc[j][1] = p1; sacc[j][2] = p2; sacc[j][3] = p3;
        }
        rs0 += __shfl_xor_sync(0xffffffffu, rs0, 1);
        rs0 += __shfl_xor_sync(0xffffffffu, rs0, 2);
        rs1 += __shfl_xor_sync(0xffffffffu, rs1, 1);
        rs1 += __shfl_xor_sync(0xffffffffu, rs1, 2);
        lrow0 = lrow0 * alpha0 + rs0;
        lrow1 = lrow1 * alpha1 + rs1;
        mrow0 = mnew0; mrow1 = mnew1;
#pragma unroll
        for (int j = 0; j < 8; j++) {
            cacc[j][0] *= alpha0; cacc[j][1] *= alpha0;
            cacc[j][2] *= alpha1; cacc[j][3] *= alpha1;
        }
#pragma unroll
        for (int t = 0; t < 8; t++) {
            uint32_t pah[4];
            {
                float* s0 = sacc[2 * t]; float* s1 = sacc[2 * t + 1];
                pah[0] = pack_h2(s0[0], s0[1]);
                pah[1] = pack_h2(s0[2], s0[3]);
                pah[2] = pack_h2(s1[0], s1[1]);
                pah[3] = pack_h2(s1[2], s1[3]);
            }
            uint32_t vbh[16];
            int sub = t >> 2;
            int cgv = (t & 3) * 2 + bcgs;
#pragma unroll
            for (int prd = 0; prd < 4; prd++) {
                int row = prd * 16 + brow_b;
                uint32_t off = (uint32_t)(sub * 8192) + (uint32_t)(row * 128) +
                               (uint32_t)((cgv ^ (row & 7)) << 4);
                LDSM4(vbh + prd * 4, Vh + off);
            }
#pragma unroll
            for (int jd = 0; jd < 8; jd++) {
                uint32_t* rh = vbh + (jd >> 1) * 4 + (jd & 1) * 2;
                MMA_F16(cacc[jd], pah, rh);
            }
        }
        __syncthreads();
        if (tid == 0 && kb + 4 < 16) issue(s, kb + 4);
    }
    float inv0 = (lrow0 > 0.f) ? (1.f / lrow0) : 0.f;
    float inv1 = (lrow1 > 0.f) ? (1.f / lrow1) : 0.f;
    int r0 = wid * 16 + (ln >> 2);
    size_t tile = ((size_t)h * 16 + qb) * (size_t)TILE_B;
#pragma unroll
    for (int jd = 0; jd < 8; jd++) {
        uint32_t inoff = (uint32_t)(q2 * 2);
#pragma unroll
        for (int rr = 0; rr < 2; rr++) {
            int r = r0 + rr * 8;
            float v0 = cacc[jd][rr * 2] * (rr ? inv1 : inv0);
            float v1 = cacc[jd][rr * 2 + 1] * (rr ? inv1 : inv0);
            uint32_t off = (uint32_t)(r * 128) + (uint32_t)((jd ^ (r & 7)) << 4) + inoff;
            *(uint32_t*)((char*)Chi + tile + off) = pack_h2(v0, v1);
        }
    }
}

// ---------------- LayerNorm -> tiled fp16 directly ----------------------------
__global__ void ln_tile(const float* __restrict__ x, const float* __restrict__ w,
                        const float* __restrict__ b, __half* __restrict__ Hi) {
    int row = blockIdx.x;
    int tid = threadIdx.x;
    const float* xr = x + (size_t)row * D_MODEL;
    float4 v0 = *(const float4*)&xr[tid * 8];
    float4 v1 = *(const float4*)&xr[tid * 8 + 4];
    float xin[8] = {v0.x, v0.y, v0.z, v0.w, v1.x, v1.y, v1.z, v1.w};
    float s = 0.f, s2 = 0.f;
#pragma unroll
    for (int u = 0; u < 8; u++) { s += xin[u]; s2 += xin[u] * xin[u]; }
    __shared__ float r0s[256], r1s[256];
    r0s[tid] = s; r1s[tid] = s2;
    __syncthreads();
    for (int o = 128; o > 0; o >>= 1) {
        if (tid < o) { r0s[tid] += r0s[tid + o]; r1s[tid] += r1s[tid + o]; }
        __syncthreads();
    }
    float mean = r0s[0] * (1.0f / D_MODEL);
    float var  = r1s[0] * (1.0f / D_MODEL) - mean * mean;
    float inv  = rsqrtf(var + 1e-5f);
    int kt = tid >> 3, c8 = tid & 7;
    int mt = row >> 7, r = row & 127;
    size_t tile = ((size_t)kt * 16 + mt) * (size_t)TILE_B;
    uint32_t off = (uint32_t)(r * 128) + (uint32_t)((c8 ^ (r & 7)) << 4);
    __half h8[8];
#pragma unroll
    for (int u = 0; u < 8; u++)
        h8[u] = __float2half_rn((xin[u] - mean) * inv * w[tid * 8 + u] + b[tid * 8 + u]);
    *(uint4*)((char*)Hi + tile + off) = *(uint4*)h8;
}

// ---------------- V fp32 -> transposed fp16 tiles [64 d][128 keys] -----------
__global__ void conv_vt(const float* __restrict__ src, __half* __restrict__ Hi) {
    __shared__ float s[128][65];
    int sbk = blockIdx.x, kvh = blockIdx.y;
    int tid = threadIdx.x;
    for (int t = tid; t < 128 * 16; t += 256) {
        int r = t >> 4, c4 = (t & 15) * 4;
        float4 v = *(const float4*)&src[(size_t)(sbk * 128 + r) * QKV_N + 2560 + kvh * 64 + c4];
        s[r][c4] = v.x; s[r][c4 + 1] = v.y; s[r][c4 + 2] = v.z; s[r][c4 + 3] = v.w;
    }
    __syncthreads();
    size_t tile = ((size_t)kvh * 16 + sbk) * (size_t)TILE_B;
    for (int t = tid; t < 1024; t += 256) {
        int d = t >> 4, kc8 = t & 15;
        int sub = kc8 >> 3, c8 = kc8 & 7;
        __half h8[8];
#pragma unroll
        for (int u = 0; u < 8; u++)
            h8[u] = __float2half_rn(s[(kc8 & 7) * 8 + sub * 64 + u][d]);
        uint32_t off = (uint32_t)(sub * 8192) + (uint32_t)(d * 128) +
                       (uint32_t)((c8 ^ (d & 7)) << 4);
        *(uint4*)((char*)Hi + tile + off) = *(uint4*)h8;
    }
}

// ---------------- fp32 weight [K,N] -> tiled transposed fp16 -----------------
__global__ void conv_w(const float* __restrict__ W, __half* __restrict__ Hi,
                       int K, int Nsrc, int nt_off, int NT_total) {
    __shared__ float s[128][65];
    int kt = blockIdx.x, nt = blockIdx.y;
    int tid = threadIdx.x;
    for (int t = tid; t < 64 * 32; t += 256) {
        int i = t >> 5, j4 = (t & 31) * 4;
        float4 v = *(const float4*)&W[((size_t)kt * 64 + i) * Nsrc + (size_t)nt * 128 + j4];
        s[j4 + 0][i] = v.x; s[j4 + 1][i] = v.y; s[j4 + 2][i] = v.z; s[j4 + 3][i] = v.w;
    }
    __syncthreads();
    size_t tile = ((size_t)kt * NT_total + (nt_off + nt)) * TILE_B;
    for (int t = tid; t < 1024; t += 256) {
        int r = t >> 3, c8 = t & 7;
        __half h8[8];
#pragma unroll
        for (int u = 0; u < 8; u++)
            h8[u] = __float2half_rn(s[r][c8 * 8 + u]);
        uint32_t off = (uint32_t)(r * 128) + (uint32_t)((c8 ^ (r & 7)) << 4);
        *(uint4*)((char*)Hi + tile + off) = *(uint4*)h8;
    }
}

// ---------------- w1/w3 -> interleaved tiles (rows 0-63 = w1, 64-127 = w3) ---
__global__ void conv_w13(const float* __restrict__ W, __half* __restrict__ Hi,
                         int rowoff) {
    __shared__ float s[64][65];
    int kt = blockIdx.x, nt = blockIdx.y;      // kt over 32, nt over 88
    int tid = threadIdx.x;
    // load 64 k-rows x 64 n-cols, store transposed s[n][k]
    for (int t = tid; t < 64 * 16; t += 256) {
        int i = t >> 4, j4 = (t & 15) * 4;
        float4 v = *(const float4*)&W[((size_t)kt * 64 + i) * HID + (size_t)nt * 64 + j4];
        s[j4 + 0][i] = v.x; s[j4 + 1][i] = v.y; s[j4 + 2][i] = v.z; s[j4 + 3][i] = v.w;
    }
    __syncthreads();
    size_t tile = ((size_t)kt * 88 + nt) * (size_t)TILE_B;
    for (int t = tid; t < 512; t += 256) {
        int rr = t >> 3, c8 = t & 7;
        int r = rowoff + rr;
        __half h8[8];
#pragma unroll
        for (int u = 0; u < 8; u++)
            h8[u] = __float2half_rn(s[rr][c8 * 8 + u]);
        uint32_t off = (uint32_t)(r * 128) + (uint32_t)((c8 ^ (r & 7)) << 4);
        *(uint4*)((char*)Hi + tile + off) = *(uint4*)h8;
    }
}

// ---------------- launch -----------------------------------------------------
extern "C" void kernel_launch(void* const* d_in, const int* in_sizes, int n_in,
                              void* d_out, int out_size) {
    const float* x    = (const float*)d_in[0];
    const int*   mask = (const int*)  d_in[1];
    const float* wq   = (const float*)d_in[2];
    const float* wk   = (const float*)d_in[3];
    const float* wv   = (const float*)d_in[4];
    const float* wo   = (const float*)d_in[5];
    const float* w1   = (const float*)d_in[6];
    const float* w2   = (const float*)d_in[7];
    const float* w3   = (const float*)d_in[8];
    const float* ln1w = (const float*)d_in[9];
    const float* ln1b = (const float*)d_in[10];
    const float* ln2w = (const float*)d_in[11];
    const float* ln2b = (const float*)d_in[12];
    float* out = (float*)d_out;

    float *qkv, *x1;
    cudaGetSymbolAddress((void**)&qkv, g_qkv);
    cudaGetSymbolAddress((void**)&x1,  g_x1);

    __half *hhi, *chi, *ghi;
    __half *wqkvh, *woh, *w13h, *w2h;
    __half *qah, *kah, *vah;
    cudaGetSymbolAddress((void**)&hhi, t_h_hi);
    cudaGetSymbolAddress((void**)&chi, t_ctx_hi);
    cudaGetSymbolAddress((void**)&ghi, t_g_hi);
    cudaGetSymbolAddress((void**)&wqkvh, t_wqkv_hi);
    cudaGetSymbolAddress((void**)&woh, t_wo_hi);
    cudaGetSymbolAddress((void**)&w13h, t_w13_hi);
    cudaGetSymbolAddress((void**)&w2h, t_w2_hi);
    cudaGetSymbolAddress((void**)&qah, t_qat_hi);
    cudaGetSymbolAddress((void**)&kah, t_kat_hi);
    cudaGetSymbolAddress((void**)&vah, t_vat_hi);

    cudaFuncSetAttribute(mma_gemm, cudaFuncAttributeMaxDynamicSharedMemorySize, GEMM_SMEM);
    cudaFuncSetAttribute(attn_mma, cudaFuncAttributeMaxDynamicSharedMemorySize, ATT_SMEM);

    // weights -> tiled fp16
    conv_w<<<dim3(D_MODEL / 64, 16), 256>>>(wq, wqkvh, D_MODEL, D_MODEL, 0,  24);
    conv_w<<<dim3(D_MODEL / 64, 4),  256>>>(wk, wqkvh, D_MODEL, 512,     16, 24);
    conv_w<<<dim3(D_MODEL / 64, 4),  256>>>(wv, wqkvh, D_MODEL, 512,     20, 24);
    conv_w<<<dim3(D_MODEL / 64, 16), 256>>>(wo, woh,   D_MODEL, D_MODEL, 0,  16);
    conv_w13<<<dim3(D_MODEL / 64, 88), 256>>>(w1, w13h, 0);
    conv_w13<<<dim3(D_MODEL / 64, 88), 256>>>(w3, w13h, 64);
    conv_w<<<dim3(HID / 64,     16), 256>>>(w2, w2h,   HID,     D_MODEL, 0,  16);

    // h tiles = LN1(x)
    ln_tile<<<S_LEN, 256>>>(x, ln1w, ln1b, hhi);

    // qkv GEMM: rope Q/K -> attention tiles; V -> fp32
    mma_gemm<<<dim3(QKV_N / 128, S_LEN / 128), 256, GEMM_SMEM>>>(hhi, wqkvh,
        nullptr, qkv, S_LEN, QKV_N, D_MODEL, 1, qah, kah);

    conv_vt<<<dim3(16, NKV), 256>>>(qkv, vah);

    // attention -> ctx tiles
    attn_mma<<<dim3(S_LEN / 128, NH), 256, ATT_SMEM>>>(qah, kah, vah, mask, chi);

    // x1 = x + ctx @ wo (fp32)
    mma_gemm<<<dim3(D_MODEL / 128, S_LEN / 128), 256, GEMM_SMEM>>>(chi, woh,
        x, x1, S_LEN, D_MODEL, D_MODEL, 0, nullptr, nullptr);

    // h tiles = LN2(x1)
    ln_tile<<<S_LEN, 256>>>(x1, ln2w, ln2b, hhi);

    // fused: gb tiles = silu(h @ w1) * (h @ w3)
    mma_gemm<<<dim3(W13_N / 128, S_LEN / 128), 256, GEMM_SMEM>>>(hhi, w13h,
        nullptr, nullptr, S_LEN, W13_N, D_MODEL, 3, ghi, nullptr);

    // out = x1 + gb @ w2
    mma_gemm<<<dim3(D_MODEL / 128, S_LEN / 128), 256, GEMM_SMEM>>>(ghi, w2h,
        x1, out, S_LEN, D_MODEL, HID, 0, nullptr, nullptr);
}